// round 9
// baseline (speedup 1.0000x reference)
#include <cuda_runtime.h>
#include <cuda_fp16.h>
#include <math.h>
#include <stdint.h>

#define Bb 32
#define Ss 512
#define NNODE 6
#define CIN 12
#define H1C 128
#define HHC 256
#define TCC 1536
#define LLEN 512
#define LROWS 544           /* 16 pad | 512 | 16 pad rows in [l][c] layout */
#define M1R (Bb*Ss*NNODE)   /* 98304 */
#define NBS (Bb*Ss)         /* 16384 */
#define RKK (5*TCC)         /* 7680  */
#define BNEPS 1e-5f

// ---------------- scratch (device globals; no runtime allocation) ----------
__device__ float  g_xc1 [M1R*H1C];
__device__ float  g_res1[M1R*H1C];
__device__ float  g_h1  [M1R*H1C];     // tf32-rounded at write
__device__ float  g_y2  [M1R*HHC];
__device__ float  g_res2[M1R*HHC];
__device__ float  g_xc2 [M1R*HHC];
__device__ __half g_htH [Bb*LROWS*TCC];  // [l][c] fp16, padded rows
__device__ __half g_t1H [Bb*LROWS*TCC];
__device__ __half g_t2H [Bb*LROWS*TCC];
__device__ __half g_wt1H[RKK*TCC];       // fragment-permuted fp16 tiles
__device__ __half g_wt2H[RKK*TCC];
__device__ float  g_wB  [H1C*512];       // packed (w2T | rw2T), tf32 bits
__device__ float  g_biasP[512];
__device__ __half g_owRH[TCC*HHC];       // fragment-permuted ow fp16 tiles
__device__ float  g_stats[4*TCC];

// ---------------- helpers ----------------------------------------------------
__device__ __forceinline__ unsigned f2tf32(float f) {
    unsigned u; asm("cvt.rna.tf32.f32 %0, %1;" : "=r"(u) : "f"(f)); return u;
}
#define MMA_TF32(c, a, b) \
    asm volatile("mma.sync.aligned.m16n8k8.row.col.f32.tf32.tf32.f32 " \
        "{%0,%1,%2,%3}, {%4,%5,%6,%7}, {%8,%9}, {%0,%1,%2,%3};" \
        : "+f"((c)[0]), "+f"((c)[1]), "+f"((c)[2]), "+f"((c)[3]) \
        : "r"((a)[0]), "r"((a)[1]), "r"((a)[2]), "r"((a)[3]), \
          "r"((b)[0]), "r"((b)[1]))
#define MMA_F16(c, a, b) \
    asm volatile("mma.sync.aligned.m16n8k16.row.col.f32.f16.f16.f32 " \
        "{%0,%1,%2,%3}, {%4,%5,%6,%7}, {%8,%9}, {%0,%1,%2,%3};" \
        : "+f"((c)[0]), "+f"((c)[1]), "+f"((c)[2]), "+f"((c)[3]) \
        : "r"((a)[0]), "r"((a)[1]), "r"((a)[2]), "r"((a)[3]), \
          "r"((b)[0]), "r"((b)[1]))

__device__ __forceinline__ void cpasync16(uint32_t dst, const void* src) {
    asm volatile("cp.async.cg.shared.global [%0], [%1], 16;" :: "r"(dst), "l"(src));
}
__device__ __forceinline__ void cpa_commit() {
    asm volatile("cp.async.commit_group;" ::: "memory");
}
template<int N>
__device__ __forceinline__ void cpa_wait() {
    asm volatile("cp.async.wait_group %0;" :: "n"(N) : "memory");
}
__device__ __forceinline__ uint32_t s2u(const void* p) {
    return (uint32_t)__cvta_generic_to_shared(p);
}
__device__ __forceinline__ unsigned packh2(float a, float b) {
    __half2 h = __floats2half2_rn(a, b);
    return *(unsigned*)&h;
}

// ---------------- small utility kernels ------------------------------------
__global__ void zero_stats_k() {
    int i = blockIdx.x * blockDim.x + threadIdx.x;
    if (i < 4*TCC) g_stats[i] = 0.f;
}

// zero pad rows (0..15, 528..543) of ht and t1 fp16 tensors
__global__ void zero_padsH() {
    int idx = blockIdx.x * blockDim.x + threadIdx.x;
    const int per = Bb * 32 * (TCC/8);
    if (idx >= per) return;
    int col8 = idx % (TCC/8);
    int rr   = (idx / (TCC/8)) % 32;
    int b    = idx / (32 * (TCC/8));
    int row  = rr < 16 ? rr : 512 + rr;
    size_t off = ((size_t)b * LROWS + row) * TCC + col8 * 8;
    uint4 z = make_uint4(0,0,0,0);
    *(uint4*)((char*)g_htH + off*2) = z;
    *(uint4*)((char*)g_t1H + off*2) = z;
}

// pack w2/rw2 into wB (tf32 bits) -- gcn2 stays tf32
__global__ void pack_gcn2(const float* __restrict__ w2, const float* __restrict__ rw2,
                          const float* __restrict__ b2, const float* __restrict__ rb2) {
    int idx = blockIdx.x * blockDim.x + threadIdx.x;
    if (idx >= H1C * HHC) return;
    int i = idx >> 8;
    int o = idx & 255;
    unsigned* wB = (unsigned*)g_wB;
    wB[i * 512 + o]       = f2tf32(w2[(size_t)o * H1C + i]);
    wB[i * 512 + 256 + o] = f2tf32(rw2[(size_t)o * H1C + i]);
    if (i == 0) { g_biasP[o] = b2[o]; g_biasP[256 + o] = rb2[o]; }
}

// ---- fp16 fragment permutation for m16n8k16 --------------------------------
// coalesced conv-weight transform: one block stages 128co x 80 floats
// (16 ci x 5 k contiguous range) in smem, emits all 5 k-tiles.
__global__ void wtrans_convH2(const float* __restrict__ cw, __half* __restrict__ wt) {
    __shared__ float sm[128 * 81];
    int blk = blockIdx.x;                 // cib*12 + cb ; cib in [0,96)
    int cib = blk / 12, cb = blk % 12;
    int ci0 = cib * 16;
    int tid = threadIdx.x;
    for (int i = tid; i < 128 * 80; i += 256) {
        int co = i / 80, j = i % 80;
        sm[co * 81 + j] = cw[((size_t)(cb * 128 + co) * TCC + ci0) * 5 + j];
    }
    __syncthreads();
#pragma unroll
    for (int k = 0; k < 5; k++) {
        int tile = (k * 96 + cib) * 12 + cb;
        unsigned* dst = (unsigned*)wt + (size_t)tile * 1024 + tid * 4;
#pragma unroll
        for (int u = 0; u < 4; u++) {
            int pos = tid * 4 + u;
            int r = pos & 3, lane = (pos >> 2) & 31, mi = pos >> 7;
            int kl = 2 * (lane & 3) + ((r >> 1) << 3);
            int ml = mi * 16 + (lane >> 2) + ((r & 1) << 3);
            float f0 = sm[ml * 81 + kl * 5 + k];
            float f1 = sm[ml * 81 + (kl + 1) * 5 + k];
            dst[u] = packh2(f0, f1);
        }
    }
}

__global__ void pack_owH(const float* __restrict__ ow) {
    int tile = blockIdx.x;                    // tk*2 + cb ; tk in [0,96)
    int tk = tile >> 1, cb = tile & 1;
    int tid = threadIdx.x;
    unsigned* dst = (unsigned*)g_owRH + (size_t)tile * 1024 + tid * 4;
#pragma unroll
    for (int u = 0; u < 4; u++) {
        int pos = tid * 4 + u;
        int r = pos & 3, lane = (pos >> 2) & 31, mi = pos >> 7;
        int kl = 2 * (lane & 3) + ((r >> 1) << 3);
        int ml = mi * 16 + (lane >> 2) + ((r & 1) << 3);
        int c = tk * 16 + kl;
        int o = cb * 128 + ml;
        float f0 = ow[(size_t)o * TCC + c];
        float f1 = ow[(size_t)o * TCC + c + 1];
        dst[u] = packh2(f0, f1);
    }
}

// ---------------- GCN stage 1 ------------------------------------------------
__global__ void gcn1_kernel(const float* __restrict__ x, const float* __restrict__ adj,
                            const float* __restrict__ eimp,
                            const float* __restrict__ w1, const float* __restrict__ b1,
                            const float* __restrict__ rw1, const float* __restrict__ rb1) {
    __shared__ float xs[NNODE*CIN];
    __shared__ float Asm[NNODE*NNODE];
    __shared__ float xts[NNODE*H1C];
    int bs = blockIdx.x;
    int tid = threadIdx.x;
    if (tid < NNODE*CIN) xs[tid] = x[(size_t)bs*NNODE*CIN + tid];
    if (tid >= 128 && tid < 128 + NNODE*NNODE) Asm[tid-128] = adj[tid-128] * eimp[tid-128];
    __syncthreads();
    for (int e = tid; e < NNODE*H1C; e += blockDim.x) {
        int n = e / H1C, c = e % H1C;
        float ws = b1[c], rs = rb1[c];
#pragma unroll
        for (int i = 0; i < CIN; i++) {
            float xv = xs[n*CIN + i];
            ws += xv * w1[c*CIN + i];
            rs += xv * rw1[c*CIN + i];
        }
        xts[e] = ws;
        g_res1[(size_t)bs*(NNODE*H1C) + e] = rs;
    }
    __syncthreads();
    for (int e = tid; e < NNODE*H1C; e += blockDim.x) {
        int n = e / H1C, c = e % H1C;
        float acc = 0.f;
#pragma unroll
        for (int m = 0; m < NNODE; m++) acc += Asm[n*NNODE + m] * xts[m*H1C + c];
        g_xc1[(size_t)bs*(NNODE*H1C) + e] = acc;
    }
}

__global__ void stats_rows(const float* __restrict__ a, const float* __restrict__ b,
                           int Mrows, int C) {
    int c = threadIdx.x;
    int rows_per = Mrows / gridDim.x;
    int r0 = blockIdx.x * rows_per;
    int r1 = r0 + rows_per;
    float sa = 0.f, qa = 0.f, sb = 0.f, qb = 0.f;
    for (int r = r0; r < r1; r++) {
        float v = a[(size_t)r*C + c]; sa += v; qa += v*v;
        float u = b[(size_t)r*C + c]; sb += u; qb += u*u;
    }
    atomicAdd(&g_stats[c],       sa);
    atomicAdd(&g_stats[C + c],   qa);
    atomicAdd(&g_stats[2*C + c], sb);
    atomicAdd(&g_stats[3*C + c], qb);
}

__global__ void bn_apply1(const float* __restrict__ g1, const float* __restrict__ beta1,
                          const float* __restrict__ rg1, const float* __restrict__ rbeta1) {
    size_t idx = (size_t)blockIdx.x * blockDim.x + threadIdx.x;
    if (idx >= (size_t)M1R*H1C) return;
    int c = (int)(idx % H1C);
    const float invM = 1.f / (float)M1R;
    float m1 = g_stats[c] * invM;
    float v1 = g_stats[H1C + c] * invM - m1*m1;
    float m2 = g_stats[2*H1C + c] * invM;
    float v2 = g_stats[3*H1C + c] * invM - m2*m2;
    float a = (g_xc1[idx]  - m1) * rsqrtf(v1 + BNEPS) * g1[c]  + beta1[c];
    float r = (g_res1[idx] - m2) * rsqrtf(v2 + BNEPS) * rg1[c] + rbeta1[c];
    float o = a + r;
    o = o > 0.f ? o : 0.f;
    g_h1[idx] = __uint_as_float(f2tf32(o));
}

// ---------------- gcn2 dual GEMM (tf32 mma, unchanged) ----------------------
#define A2STR 20
#define B2STR 136
#define A2SZ (128*A2STR*4)
#define B2SZ (16*B2STR*4)
#define STG2 (A2SZ + B2SZ)

__global__ __launch_bounds__(256, 2) void gcn2_gemm_tf32() {
    extern __shared__ __align__(128) char dsm[];
    const int tid = threadIdx.x;
    const int bm = blockIdx.x * 128;
    const int by = blockIdx.y;
    const int bn = by * 128;
    const int lane = tid & 31, wid = tid >> 5;
    const int wm = (wid & 1) * 64, wn = (wid >> 1) * 32;
    const int g = lane >> 2, tg = lane & 3;
    const uint32_t smem_u = s2u(dsm);
    const float* A = g_h1;

    float acc[4][4][4];
#pragma unroll
    for (int mi = 0; mi < 4; mi++)
#pragma unroll
        for (int ni = 0; ni < 4; ni++)
#pragma unroll
            for (int r = 0; r < 4; r++) acc[mi][ni][r] = 0.f;

    const int NT = H1C / 16;   // 8

    auto load_stage = [&](int slot, int t) {
        const int kk0 = t * 16;
        const uint32_t sa = smem_u + slot * STG2;
        const uint32_t sb = sa + A2SZ;
#pragma unroll
        for (int i = 0; i < 2; i++) {
            int idx = tid + i * 256;
            int m = idx >> 2, kc = (idx & 3) * 4;
            cpasync16(sa + (m * A2STR + kc) * 4,
                      A + (size_t)(bm + m) * H1C + kk0 + kc);
        }
#pragma unroll
        for (int i = 0; i < 2; i++) {
            int idx = tid + i * 256;
            int row = idx >> 5, ch = idx & 31;
            cpasync16(sb + (row * B2STR + ch * 4) * 4,
                      g_wB + (size_t)(kk0 + row) * 512 + bn + ch * 4);
        }
    };
    load_stage(0, 0); cpa_commit();
    load_stage(1, 1); cpa_commit();

    for (int t = 0; t < NT; ++t) {
        cpa_wait<1>();
        __syncthreads();
        if (t + 2 < NT) load_stage((t + 2) % 3, t + 2);
        cpa_commit();
        const int cur = t % 3;
        const float* As = (const float*)(dsm + cur * STG2);
        const float* Bs = (const float*)(dsm + cur * STG2 + A2SZ);
#pragma unroll
        for (int ks = 0; ks < 16; ks += 8) {
            unsigned a[4][4], b[4][2];
#pragma unroll
            for (int mi = 0; mi < 4; mi++) {
                int m = wm + mi * 16 + g;
                a[mi][0] = __float_as_uint(As[(m    ) * A2STR + ks + tg]);
                a[mi][1] = __float_as_uint(As[(m + 8) * A2STR + ks + tg]);
                a[mi][2] = __float_as_uint(As[(m    ) * A2STR + ks + tg + 4]);
                a[mi][3] = __float_as_uint(As[(m + 8) * A2STR + ks + tg + 4]);
            }
#pragma unroll
            for (int ni = 0; ni < 4; ni++) {
                int c = wn + ni * 8 + g;
                b[ni][0] = __float_as_uint(Bs[(ks + tg    ) * B2STR + c]);
                b[ni][1] = __float_as_uint(Bs[(ks + tg + 4) * B2STR + c]);
            }
#pragma unroll
            for (int mi = 0; mi < 4; mi++)
#pragma unroll
                for (int ni = 0; ni < 4; ni++)
                    MMA_TF32(acc[mi][ni], a[mi], b[ni]);
        }
    }

    float* tgt = (by < 2) ? g_y2 : g_res2;
    const int nb = (by & 1) * 128;
#pragma unroll
    for (int mi = 0; mi < 4; mi++) {
        int m0 = bm + wm + mi * 16 + g;
#pragma unroll
        for (int ni = 0; ni < 4; ni++) {
            int n = nb + wn + ni * 8 + 2 * tg;
            int pb = bn + wn + ni * 8 + 2 * tg;
            float b0 = g_biasP[pb], b1 = g_biasP[pb + 1];
            *(float2*)(tgt + (size_t)m0 * HHC + n)
                = make_float2(acc[mi][ni][0] + b0, acc[mi][ni][1] + b1);
            *(float2*)(tgt + (size_t)(m0 + 8) * HHC + n)
                = make_float2(acc[mi][ni][2] + b0, acc[mi][ni][3] + b1);
        }
    }
}

// ---------------- node mix for stage 2 --------------------------------------
__global__ void nodemix2(const float* __restrict__ adj, const float* __restrict__ eimp) {
    __shared__ float ys[NNODE*HHC];
    __shared__ float Asm[NNODE*NNODE];
    int bs = blockIdx.x, tid = threadIdx.x;
    if (tid < NNODE*NNODE) Asm[tid] = adj[tid] * eimp[tid];
    for (int e = tid; e < NNODE*HHC; e += blockDim.x)
        ys[e] = g_y2[(size_t)bs*NNODE*HHC + e];
    __syncthreads();
    for (int e = tid; e < NNODE*HHC; e += blockDim.x) {
        int n = e / HHC, c = e % HHC;
        float acc = 0.f;
#pragma unroll
        for (int m = 0; m < NNODE; m++) acc += Asm[n*NNODE + m] * ys[m*HHC + c];
        g_xc2[(size_t)bs*NNODE*HHC + e] = acc;
    }
}

// ---------------- BN apply stage 2 -> [l][c] fp16 ----------------------------
__global__ void bn_apply2_tohalf(const float* __restrict__ g2, const float* __restrict__ beta2,
                                 const float* __restrict__ rg2, const float* __restrict__ rbeta2) {
    int row = blockIdx.x;        // (b*Ss + s)*6 + n
    int c = threadIdx.x;         // 0..255
    const float invM = 1.f / (float)M1R;
    float m1 = g_stats[c] * invM;
    float v1 = g_stats[HHC + c] * invM - m1*m1;
    float m2 = g_stats[2*HHC + c] * invM;
    float v2 = g_stats[3*HHC + c] * invM - m2*m2;
    float sc1 = rsqrtf(v1 + BNEPS) * g2[c];
    float sh1 = beta2[c] - m1*sc1;
    float sc2 = rsqrtf(v2 + BNEPS) * rg2[c];
    float sh2 = rbeta2[c] - m2*sc2;
    size_t ridx = (size_t)row * HHC + c;
    float o = g_xc2[ridx]*sc1 + sh1 + g_res2[ridx]*sc2 + sh2;
    o = o > 0.f ? o : 0.f;
    int n = row % NNODE;
    int bs = row / NNODE;
    int b = bs / Ss, s = bs % Ss;
    g_htH[((size_t)b * LROWS + 16 + s) * TCC + n * HHC + c] = __float2half(o);
}

// ======================= conv1d fp16 mma GEMM ================================
// 6 tile-slots = 3 pair-slots; 2 k16-tiles consumed per wait+barrier.
#define ASZh 4096
#define BROWB 48            /* B smem row stride bytes (24 fp16) */
#define BSZh (128*BROWB)    /* 6144 */
#define STGh (ASZh + BSZh)  /* 10240 */

__global__ __launch_bounds__(256, 2) void conv_gemm_f16(
        const __half* __restrict__ X, const __half* __restrict__ Wt,
        __half* __restrict__ Y) {
    extern __shared__ __align__(128) char dsm[];
    const int tid = threadIdx.x;
    const int cb = blockIdx.x;
    const int bm = cb * 128;           // co
    const int bn = blockIdx.y * 128;   // l
    const __half* Xb = X + (size_t)blockIdx.z * LROWS * TCC;
    __half* Yb = Y + (size_t)blockIdx.z * LROWS * TCC;
    const int lane = tid & 31, wid = tid >> 5;
    const int wm = (wid & 1) * 64, wn = (wid >> 1) * 32;
    const int g = lane >> 2, tg = lane & 3;
    const int aoff = (wid & 1) * 4;
    const uint32_t smem_u = s2u(dsm);

    float acc[4][4][4];
#pragma unroll
    for (int mi = 0; mi < 4; mi++)
#pragma unroll
        for (int ni = 0; ni < 4; ni++)
#pragma unroll
            for (int r = 0; r < 4; r++) acc[mi][ni][r] = 0.f;

    const int NP = RKK / 32;   // 240 pairs (480 k16-tiles)
    const int brow = tid >> 1, bhalf = tid & 1;

    // load one k16-tile into tile-slot `slot`
    auto load_tile = [&](int slot, int t) {
        const int kseg = t / 96;
        const int ci0  = t * 16 - kseg * TCC;
        const uint32_t sa = smem_u + slot * STGh;
        const uint32_t sb = sa + ASZh;
        cpasync16(sa + tid * 16, Wt + ((size_t)t * 12 + cb) * 2048 + tid * 8);
        const __half* src = Xb + (size_t)(16 + bn + kseg - 2 + brow) * TCC
                              + ci0 + bhalf * 8;
        cpasync16(sb + brow * BROWB + bhalf * 16, src);
    };
    // one group per pair
    auto load_pair = [&](int ps, int p) {
        load_tile(2 * ps,     2 * p);
        load_tile(2 * ps + 1, 2 * p + 1);
    };

    // compute one k16-tile from tile-slot `slot`
    auto compute_tile = [&](int slot) {
        const uint4* Af = (const uint4*)(dsm + slot * STGh);
        const char* Bs = dsm + slot * STGh + ASZh;
        unsigned a[4][4], b[4][2];
#pragma unroll
        for (int mi = 0; mi < 4; mi++) {
            uint4 v = Af[(aoff + mi) * 32 + lane];
            a[mi][0] = v.x; a[mi][1] = v.y; a[mi][2] = v.z; a[mi][3] = v.w;
        }
#pragma unroll
        for (int ni = 0; ni < 4; ni++) {
            int row = wn + ni * 8 + g;
            b[ni][0] = *(const unsigned*)(Bs + row * BROWB + tg * 4);
            b[ni][1] = *(const unsigned*)(Bs + row * BROWB + 16 + tg * 4);
        }
#pragma unroll
        for (int mi = 0; mi < 4; mi++)
#pragma unroll
            for (int ni = 0; ni < 4; ni++)
                MMA_F16(acc[mi][ni], a[mi], b[ni]);
    };

    load_pair(0, 0); cpa_commit();
    load_pair(1, 1); cpa_commit();

    for (int pb = 0; pb < NP; pb += 3) {
#pragma unroll
        for (int s = 0; s < 3; s++) {
            const int p = pb + s;
            cpa_wait<1>();
            __syncthreads();
            if (p + 2 < NP) load_pair((s + 2) % 3, p + 2);
            cpa_commit();
            compute_tile(2 * s);
            compute_tile(2 * s + 1);
        }
    }

    // epilogue: store fp16 [l][c] + fused per-channel stats from fp32 accs
#pragma unroll
    for (int mi = 0; mi < 4; mi++) {
        int m0 = bm + wm + mi * 16 + g;
        float s0 = 0.f, q0 = 0.f, s1 = 0.f, q1 = 0.f;
#pragma unroll
        for (int ni = 0; ni < 4; ni++) {
            float v0 = acc[mi][ni][0], v1 = acc[mi][ni][1];
            float v2 = acc[mi][ni][2], v3 = acc[mi][ni][3];
            s0 += v0 + v1; q0 += v0*v0 + v1*v1;
            s1 += v2 + v3; q1 += v2*v2 + v3*v3;
            int l0 = bn + wn + ni * 8 + 2 * tg;
            size_t r0 = ((size_t)(16 + l0)) * TCC;
            size_t r1 = ((size_t)(17 + l0)) * TCC;
            Yb[r0 + m0]     = __float2half(v0);
            Yb[r1 + m0]     = __float2half(v1);
            Yb[r0 + m0 + 8] = __float2half(v2);
            Yb[r1 + m0 + 8] = __float2half(v3);
        }
        s0 += __shfl_xor_sync(0xffffffffu, s0, 1);
        s0 += __shfl_xor_sync(0xffffffffu, s0, 2);
        q0 += __shfl_xor_sync(0xffffffffu, q0, 1);
        q0 += __shfl_xor_sync(0xffffffffu, q0, 2);
        s1 += __shfl_xor_sync(0xffffffffu, s1, 1);
        s1 += __shfl_xor_sync(0xffffffffu, s1, 2);
        q1 += __shfl_xor_sync(0xffffffffu, q1, 1);
        q1 += __shfl_xor_sync(0xffffffffu, q1, 2);
        if (tg == 0) {
            atomicAdd(&g_stats[m0],         s0);
            atomicAdd(&g_stats[TCC + m0],   q0);
            atomicAdd(&g_stats[m0 + 8],     s1);
            atomicAdd(&g_stats[TCC + m0+8], q1);
        }
    }
}

// ---------------- conv BN apply in-place on fp16 [l][c] ----------------------
__global__ void conv_bnH(__half* __restrict__ T, const float* __restrict__ g,
                         const float* __restrict__ beta, const __half* __restrict__ resid) {
    size_t idx = (size_t)blockIdx.x * blockDim.x + threadIdx.x;
    const size_t total = (size_t)Bb * LLEN * (TCC/2);
    if (idx >= total) return;
    int c2  = (int)(idx % (TCC/2));
    int l   = (int)((idx / (TCC/2)) % LLEN);
    int b   = (int)(idx / ((size_t)(TCC/2) * LLEN));
    int c   = c2 * 2;
    size_t a = ((size_t)b * LROWS + 16 + l) * TCC + c;
    const float invM = 1.f / (float)(Bb * LLEN);
    float m0 = g_stats[c] * invM;
    float va = g_stats[TCC + c] * invM - m0*m0;
    float m1 = g_stats[c+1] * invM;
    float vb = g_stats[TCC + c+1] * invM - m1*m1;
    __half2 hv = *(__half2*)(T + a);
    float2 f = __half22float2(hv);
    float o0 = (f.x - m0) * rsqrtf(va + BNEPS) * g[c]   + beta[c];
    float o1 = (f.y - m1) * rsqrtf(vb + BNEPS) * g[c+1] + beta[c+1];
    o0 = o0 > 0.f ? o0 : 0.f;
    o1 = o1 > 0.f ? o1 : 0.f;
    if (resid) {
        float2 r = __half22float2(*(const __half2*)(resid + a));
        o0 += r.x; o1 += r.y;
    }
    *(__half2*)(T + a) = __floats2half2_rn(o0, o1);
}

// ======================= output GEMM (fp16 mma, permuted A) =================
#define STGOh (ASZh + BSZh)

__global__ __launch_bounds__(256, 2) void out_gemm_f16(
        const __half* __restrict__ T2, const float* __restrict__ OB,
        float* __restrict__ OUT) {
    extern __shared__ __align__(128) char dsm[];
    const int tid = threadIdx.x;
    const int cb = blockIdx.x;
    const int bm = cb * 128;           // o
    const int bn = blockIdx.y * 128;   // s
    const int b  = blockIdx.z;
    const __half* T2b = T2 + (size_t)b * LROWS * TCC;
    const int lane = tid & 31, wid = tid >> 5;
    const int wm = (wid & 1) * 64, wn = (wid >> 1) * 32;
    const int g = lane >> 2, tg = lane & 3;
    const int aoff = (wid & 1) * 4;
    const uint32_t smem_u = s2u(dsm);

    float acc[4][4][4];
#pragma unroll
    for (int mi = 0; mi < 4; mi++)
#pragma unroll
        for (int ni = 0; ni < 4; ni++)
#pragma unroll
            for (int r = 0; r < 4; r++) acc[mi][ni][r] = 0.f;

    const int NT = TCC / 16;   // 96
    const int brow = tid >> 1, bhalf = tid & 1;

    auto load_stage = [&](int slot, int t) {
        const uint32_t sa = smem_u + slot * STGOh;
        const uint32_t sb = sa + ASZh;
        cpasync16(sa + tid * 16, g_owRH + ((size_t)t * 2 + cb) * 2048 + tid * 8);
        const __half* src = T2b + (size_t)(16 + bn + brow) * TCC + t * 16 + bhalf * 8;
        cpasync16(sb + brow * BROWB + bhalf * 16, src);
    };
    load_stage(0, 0); cpa_commit();
    load_stage(1, 1); cpa_commit();

    for (int t = 0; t < NT; ++t) {
        cpa_wait<1>();
        __syncthreads();
        if (t + 2 < NT) load_stage((t + 2) % 3, t + 2);
        cpa_commit();
        const int cur = t % 3;
        const uint4* Af = (const uint4*)(dsm + cur * STGOh);
        const char* Bs = dsm + cur * STGOh + ASZh;

        unsigned a[4][4], b[4][2];
#pragma unroll
        for (int mi = 0; mi < 4; mi++) {
            uint4 v = Af[(aoff + mi) * 32 + lane];
            a[mi][0] = v.x; a[mi][1] = v.y; a[mi][2] = v.z; a[mi][3] = v.w;
        }
#pragma unroll
        for (int ni = 0; ni < 4; ni++) {
            int row = wn + ni * 8 + g;
            b[ni][0] = *(const unsigned*)(Bs + row * BROWB + tg * 4);
            b[ni][1] = *(const unsigned*)(Bs + row * BROWB + 16 + tg * 4);
        }
#pragma unroll
        for (int mi = 0; mi < 4; mi++)
#pragma unroll
            for (int ni = 0; ni < 4; ni++)
                MMA_F16(acc[mi][ni], a[mi], b[ni]);
    }

#pragma unroll
    for (int mi = 0; mi < 4; mi++) {
        int o0 = bm + wm + mi * 16 + g;
        float bo0 = OB[o0], bo1 = OB[o0 + 8];
#pragma unroll
        for (int ni = 0; ni < 4; ni++) {
            int sL = bn + wn + ni * 8 + 2 * tg;
            float v0 = acc[mi][ni][0] + bo0; v0 = v0 > 0.f ? v0 : 0.f;
            float v1 = acc[mi][ni][1] + bo0; v1 = v1 > 0.f ? v1 : 0.f;
            float v2 = acc[mi][ni][2] + bo1; v2 = v2 > 0.f ? v2 : 0.f;
            float v3 = acc[mi][ni][3] + bo1; v3 = v3 > 0.f ? v3 : 0.f;
            OUT[((size_t)b * Ss + sL    ) * HHC + o0    ] = v0;
            OUT[((size_t)b * Ss + sL + 1) * HHC + o0    ] = v1;
            OUT[((size_t)b * Ss + sL    ) * HHC + o0 + 8] = v2;
            OUT[((size_t)b * Ss + sL + 1) * HHC + o0 + 8] = v3;
        }
    }
}

// ---------------- launch ----------------------------------------------------
extern "C" void kernel_launch(void* const* d_in, const int* in_sizes, int n_in,
                              void* d_out, int out_size) {
    const float* x     = (const float*)d_in[0];
    const float* adj   = (const float*)d_in[1];
    const float* eimp  = (const float*)d_in[2];
    const float* w1    = (const float*)d_in[3];
    const float* b1    = (const float*)d_in[4];
    const float* rw1   = (const float*)d_in[5];
    const float* rb1   = (const float*)d_in[6];
    const float* rg1   = (const float*)d_in[7];
    const float* rbeta1= (const float*)d_in[8];
    const float* g1    = (const float*)d_in[9];
    const float* beta1 = (const float*)d_in[10];
    const float* w2    = (const float*)d_in[11];
    const float* b2    = (const float*)d_in[12];
    const float* rw2   = (const float*)d_in[13];
    const float* rb2   = (const float*)d_in[14];
    const float* rg2   = (const float*)d_in[15];
    const float* rbeta2= (const float*)d_in[16];
    const float* g2    = (const float*)d_in[17];
    const float* beta2 = (const float*)d_in[18];
    const float* cw1   = (const float*)d_in[19];
    /* cb1 = d_in[20]: cancels exactly through BN mean-subtraction */
    const float* cg1   = (const float*)d_in[21];
    const float* cbeta1= (const float*)d_in[22];
    const float* cw2   = (const float*)d_in[23];
    /* cb2 = d_in[24]: cancels exactly */
    const float* cg2   = (const float*)d_in[25];
    const float* cbeta2= (const float*)d_in[26];
    const float* ow    = (const float*)d_in[27];
    const float* ob    = (const float*)d_in[28];
    float* out = (float*)d_out;

    float *p_xc1, *p_res1, *p_xc2, *p_res2;
    __half *p_htH, *p_t1H, *p_t2H, *p_wt1H, *p_wt2H;
    cudaGetSymbolAddress((void**)&p_xc1,  g_xc1);
    cudaGetSymbolAddress((void**)&p_res1, g_res1);
    cudaGetSymbolAddress((void**)&p_xc2,  g_xc2);
    cudaGetSymbolAddress((void**)&p_res2, g_res2);
    cudaGetSymbolAddress((void**)&p_htH,  g_htH);
    cudaGetSymbolAddress((void**)&p_t1H,  g_t1H);
    cudaGetSymbolAddress((void**)&p_t2H,  g_t2H);
    cudaGetSymbolAddress((void**)&p_wt1H, g_wt1H);
    cudaGetSymbolAddress((void**)&p_wt2H, g_wt2H);

    cudaFuncSetAttribute(conv_gemm_f16,
                         cudaFuncAttributeMaxDynamicSharedMemorySize, 6 * STGh);
    cudaFuncSetAttribute(gcn2_gemm_tf32,
                         cudaFuncAttributeMaxDynamicSharedMemorySize, 3 * STG2);
    cudaFuncSetAttribute(out_gemm_f16,
                         cudaFuncAttributeMaxDynamicSharedMemorySize, 3 * STGOh);

    // -------- GCN stage 1 --------
    gcn1_kernel<<<NBS, 256>>>(x, adj, eimp, w1, b1, rw1, rb1);
    zero_stats_k<<<(4*TCC + 255)/256, 256>>>();
    zero_padsH<<<(Bb*32*(TCC/8) + 255)/256, 256>>>();
    pack_gcn2<<<(H1C*HHC + 255)/256, 256>>>(w2, rw2, b2, rb2);
    pack_owH<<<(TCC/16)*2, 256>>>(ow);
    stats_rows<<<1024, H1C>>>(p_xc1, p_res1, M1R, H1C);
    bn_apply1<<<(M1R*H1C)/256, 256>>>(g1, beta1, rg1, rbeta1);

    // -------- GCN stage 2 (tf32 dual GEMM) --------
    gcn2_gemm_tf32<<<dim3(M1R/128, 4), 256, 3*STG2>>>();
    nodemix2<<<NBS, 256>>>(adj, eimp);
    zero_stats_k<<<(4*TCC + 255)/256, 256>>>();
    stats_rows<<<1024, HHC>>>(p_xc2, p_res2, M1R, HHC);
    bn_apply2_tohalf<<<M1R, 256>>>(g2, beta2, rg2, rbeta2);

    // -------- TCN conv 1 (fp16 mma, pair-unrolled pipeline) --------
    wtrans_convH2<<<96*12, 256>>>(cw1, p_wt1H);
    zero_stats_k<<<(4*TCC + 255)/256, 256>>>();
    conv_gemm_f16<<<dim3(TCC/128, LLEN/128, Bb), 256, 6*STGh>>>(p_htH, p_wt1H, p_t1H);
    conv_bnH<<<(Bb*LLEN*(TCC/2) + 255)/256, 256>>>(p_t1H, cg1, cbeta1, (const __half*)nullptr);

    // -------- TCN conv 2 + residual --------
    wtrans_convH2<<<96*12, 256>>>(cw2, p_wt2H);
    zero_stats_k<<<(4*TCC + 255)/256, 256>>>();
    conv_gemm_f16<<<dim3(TCC/128, LLEN/128, Bb), 256, 6*STGh>>>(p_t1H, p_wt2H, p_t2H);
    conv_bnH<<<(Bb*LLEN*(TCC/2) + 255)/256, 256>>>(p_t2H, cg2, cbeta2, p_htH);

    // -------- output layer (fp16 mma) --------
    out_gemm_f16<<<dim3(HHC/128, LLEN/128, Bb), 256, 3*STGOh>>>(p_t2H, ob, out);

    (void)in_sizes; (void)n_in; (void)out_size;
}

// round 10
// speedup vs baseline: 1.0034x; 1.0034x over previous
#include <cuda_runtime.h>
#include <cuda_fp16.h>
#include <math.h>
#include <stdint.h>

#define Bb 32
#define Ss 512
#define NNODE 6
#define CIN 12
#define H1C 128
#define HHC 256
#define TCC 1536
#define LLEN 512
#define LROWS 544           /* 16 pad | 512 | 16 pad rows in [l][c] layout */
#define M1R (Bb*Ss*NNODE)   /* 98304 */
#define NBS (Bb*Ss)         /* 16384 */
#define RKK (5*TCC)         /* 7680  */
#define BNEPS 1e-5f

// ---------------- scratch (device globals; no runtime allocation) ----------
__device__ float  g_xc1 [M1R*H1C];
__device__ float  g_res1[M1R*H1C];
__device__ float  g_h1  [M1R*H1C];     // tf32-rounded at write
__device__ float  g_y2  [M1R*HHC];
__device__ float  g_res2[M1R*HHC];
__device__ float  g_xc2 [M1R*HHC];
__device__ __half g_htH [Bb*LROWS*TCC];  // [l][c] fp16, padded rows
__device__ __half g_t1H [Bb*LROWS*TCC];
__device__ __half g_t2H [Bb*LROWS*TCC];
__device__ __half g_wt1H[RKK*TCC];       // fragment-permuted fp16 tiles
__device__ __half g_wt2H[RKK*TCC];
__device__ float  g_wB  [H1C*512];       // packed (w2T | rw2T), tf32 bits
__device__ float  g_biasP[512];
__device__ __half g_owRH[TCC*HHC];       // fragment-permuted ow fp16 tiles
__device__ float  g_stats[4*TCC];

// ---------------- helpers ----------------------------------------------------
__device__ __forceinline__ unsigned f2tf32(float f) {
    unsigned u; asm("cvt.rna.tf32.f32 %0, %1;" : "=r"(u) : "f"(f)); return u;
}
#define MMA_TF32(c, a, b) \
    asm volatile("mma.sync.aligned.m16n8k8.row.col.f32.tf32.tf32.f32 " \
        "{%0,%1,%2,%3}, {%4,%5,%6,%7}, {%8,%9}, {%0,%1,%2,%3};" \
        : "+f"((c)[0]), "+f"((c)[1]), "+f"((c)[2]), "+f"((c)[3]) \
        : "r"((a)[0]), "r"((a)[1]), "r"((a)[2]), "r"((a)[3]), \
          "r"((b)[0]), "r"((b)[1]))
#define MMA_F16(c, a, b) \
    asm volatile("mma.sync.aligned.m16n8k16.row.col.f32.f16.f16.f32 " \
        "{%0,%1,%2,%3}, {%4,%5,%6,%7}, {%8,%9}, {%0,%1,%2,%3};" \
        : "+f"((c)[0]), "+f"((c)[1]), "+f"((c)[2]), "+f"((c)[3]) \
        : "r"((a)[0]), "r"((a)[1]), "r"((a)[2]), "r"((a)[3]), \
          "r"((b)[0]), "r"((b)[1]))

__device__ __forceinline__ void cpasync16(uint32_t dst, const void* src) {
    asm volatile("cp.async.cg.shared.global [%0], [%1], 16;" :: "r"(dst), "l"(src));
}
__device__ __forceinline__ void cpa_commit() {
    asm volatile("cp.async.commit_group;" ::: "memory");
}
template<int N>
__device__ __forceinline__ void cpa_wait() {
    asm volatile("cp.async.wait_group %0;" :: "n"(N) : "memory");
}
__device__ __forceinline__ uint32_t s2u(const void* p) {
    return (uint32_t)__cvta_generic_to_shared(p);
}
__device__ __forceinline__ unsigned packh2(float a, float b) {
    __half2 h = __floats2half2_rn(a, b);
    return *(unsigned*)&h;
}

// ---------------- small utility kernels ------------------------------------
__global__ void zero_stats_k() {
    int i = blockIdx.x * blockDim.x + threadIdx.x;
    if (i < 4*TCC) g_stats[i] = 0.f;
}

// zero pad rows (0..15, 528..543) of ht and t1 fp16 tensors
__global__ void zero_padsH() {
    int idx = blockIdx.x * blockDim.x + threadIdx.x;
    const int per = Bb * 32 * (TCC/8);
    if (idx >= per) return;
    int col8 = idx % (TCC/8);
    int rr   = (idx / (TCC/8)) % 32;
    int b    = idx / (32 * (TCC/8));
    int row  = rr < 16 ? rr : 512 + rr;
    size_t off = ((size_t)b * LROWS + row) * TCC + col8 * 8;
    uint4 z = make_uint4(0,0,0,0);
    *(uint4*)((char*)g_htH + off*2) = z;
    *(uint4*)((char*)g_t1H + off*2) = z;
}

// pack w2/rw2 into wB (tf32 bits) -- gcn2 stays tf32
__global__ void pack_gcn2(const float* __restrict__ w2, const float* __restrict__ rw2,
                          const float* __restrict__ b2, const float* __restrict__ rb2) {
    int idx = blockIdx.x * blockDim.x + threadIdx.x;
    if (idx >= H1C * HHC) return;
    int i = idx >> 8;
    int o = idx & 255;
    unsigned* wB = (unsigned*)g_wB;
    wB[i * 512 + o]       = f2tf32(w2[(size_t)o * H1C + i]);
    wB[i * 512 + 256 + o] = f2tf32(rw2[(size_t)o * H1C + i]);
    if (i == 0) { g_biasP[o] = b2[o]; g_biasP[256 + o] = rb2[o]; }
}

// ---- fp16 fragment permutation for m16n8k16 --------------------------------
// coalesced conv-weight transform: one block stages 128co x 80 floats
// (16 ci x 5 k contiguous range) in smem, emits all 5 k-tiles.
__global__ void wtrans_convH2(const float* __restrict__ cw, __half* __restrict__ wt) {
    __shared__ float sm[128 * 81];
    int blk = blockIdx.x;                 // cib*12 + cb ; cib in [0,96)
    int cib = blk / 12, cb = blk % 12;
    int ci0 = cib * 16;
    int tid = threadIdx.x;
    for (int i = tid; i < 128 * 80; i += 256) {
        int co = i / 80, j = i % 80;
        sm[co * 81 + j] = cw[((size_t)(cb * 128 + co) * TCC + ci0) * 5 + j];
    }
    __syncthreads();
#pragma unroll
    for (int k = 0; k < 5; k++) {
        int tile = (k * 96 + cib) * 12 + cb;
        unsigned* dst = (unsigned*)wt + (size_t)tile * 1024 + tid * 4;
#pragma unroll
        for (int u = 0; u < 4; u++) {
            int pos = tid * 4 + u;
            int r = pos & 3, lane = (pos >> 2) & 31, mi = pos >> 7;
            int kl = 2 * (lane & 3) + ((r >> 1) << 3);
            int ml = mi * 16 + (lane >> 2) + ((r & 1) << 3);
            float f0 = sm[ml * 81 + kl * 5 + k];
            float f1 = sm[ml * 81 + (kl + 1) * 5 + k];
            dst[u] = packh2(f0, f1);
        }
    }
}

__global__ void pack_owH(const float* __restrict__ ow) {
    int tile = blockIdx.x;                    // tk*2 + cb ; tk in [0,96)
    int tk = tile >> 1, cb = tile & 1;
    int tid = threadIdx.x;
    unsigned* dst = (unsigned*)g_owRH + (size_t)tile * 1024 + tid * 4;
#pragma unroll
    for (int u = 0; u < 4; u++) {
        int pos = tid * 4 + u;
        int r = pos & 3, lane = (pos >> 2) & 31, mi = pos >> 7;
        int kl = 2 * (lane & 3) + ((r >> 1) << 3);
        int ml = mi * 16 + (lane >> 2) + ((r & 1) << 3);
        int c = tk * 16 + kl;
        int o = cb * 128 + ml;
        float f0 = ow[(size_t)o * TCC + c];
        float f1 = ow[(size_t)o * TCC + c + 1];
        dst[u] = packh2(f0, f1);
    }
}

// ---------------- GCN stage 1 ------------------------------------------------
__global__ void gcn1_kernel(const float* __restrict__ x, const float* __restrict__ adj,
                            const float* __restrict__ eimp,
                            const float* __restrict__ w1, const float* __restrict__ b1,
                            const float* __restrict__ rw1, const float* __restrict__ rb1) {
    __shared__ float xs[NNODE*CIN];
    __shared__ float Asm[NNODE*NNODE];
    __shared__ float xts[NNODE*H1C];
    int bs = blockIdx.x;
    int tid = threadIdx.x;
    if (tid < NNODE*CIN) xs[tid] = x[(size_t)bs*NNODE*CIN + tid];
    if (tid >= 128 && tid < 128 + NNODE*NNODE) Asm[tid-128] = adj[tid-128] * eimp[tid-128];
    __syncthreads();
    for (int e = tid; e < NNODE*H1C; e += blockDim.x) {
        int n = e / H1C, c = e % H1C;
        float ws = b1[c], rs = rb1[c];
#pragma unroll
        for (int i = 0; i < CIN; i++) {
            float xv = xs[n*CIN + i];
            ws += xv * w1[c*CIN + i];
            rs += xv * rw1[c*CIN + i];
        }
        xts[e] = ws;
        g_res1[(size_t)bs*(NNODE*H1C) + e] = rs;
    }
    __syncthreads();
    for (int e = tid; e < NNODE*H1C; e += blockDim.x) {
        int n = e / H1C, c = e % H1C;
        float acc = 0.f;
#pragma unroll
        for (int m = 0; m < NNODE; m++) acc += Asm[n*NNODE + m] * xts[m*H1C + c];
        g_xc1[(size_t)bs*(NNODE*H1C) + e] = acc;
    }
}

__global__ void stats_rows(const float* __restrict__ a, const float* __restrict__ b,
                           int Mrows, int C) {
    int c = threadIdx.x;
    int rows_per = Mrows / gridDim.x;
    int r0 = blockIdx.x * rows_per;
    int r1 = r0 + rows_per;
    float sa = 0.f, qa = 0.f, sb = 0.f, qb = 0.f;
    for (int r = r0; r < r1; r++) {
        float v = a[(size_t)r*C + c]; sa += v; qa += v*v;
        float u = b[(size_t)r*C + c]; sb += u; qb += u*u;
    }
    atomicAdd(&g_stats[c],       sa);
    atomicAdd(&g_stats[C + c],   qa);
    atomicAdd(&g_stats[2*C + c], sb);
    atomicAdd(&g_stats[3*C + c], qb);
}

__global__ void bn_apply1(const float* __restrict__ g1, const float* __restrict__ beta1,
                          const float* __restrict__ rg1, const float* __restrict__ rbeta1) {
    size_t idx = (size_t)blockIdx.x * blockDim.x + threadIdx.x;
    if (idx >= (size_t)M1R*H1C) return;
    int c = (int)(idx % H1C);
    const float invM = 1.f / (float)M1R;
    float m1 = g_stats[c] * invM;
    float v1 = g_stats[H1C + c] * invM - m1*m1;
    float m2 = g_stats[2*H1C + c] * invM;
    float v2 = g_stats[3*H1C + c] * invM - m2*m2;
    float a = (g_xc1[idx]  - m1) * rsqrtf(v1 + BNEPS) * g1[c]  + beta1[c];
    float r = (g_res1[idx] - m2) * rsqrtf(v2 + BNEPS) * rg1[c] + rbeta1[c];
    float o = a + r;
    o = o > 0.f ? o : 0.f;
    g_h1[idx] = __uint_as_float(f2tf32(o));
}

// ---------------- gcn2 dual GEMM (tf32 mma, unchanged) ----------------------
#define A2STR 20
#define B2STR 136
#define A2SZ (128*A2STR*4)
#define B2SZ (16*B2STR*4)
#define STG2 (A2SZ + B2SZ)

__global__ __launch_bounds__(256, 2) void gcn2_gemm_tf32() {
    extern __shared__ __align__(128) char dsm[];
    const int tid = threadIdx.x;
    const int bm = blockIdx.x * 128;
    const int by = blockIdx.y;
    const int bn = by * 128;
    const int lane = tid & 31, wid = tid >> 5;
    const int wm = (wid & 1) * 64, wn = (wid >> 1) * 32;
    const int g = lane >> 2, tg = lane & 3;
    const uint32_t smem_u = s2u(dsm);
    const float* A = g_h1;

    float acc[4][4][4];
#pragma unroll
    for (int mi = 0; mi < 4; mi++)
#pragma unroll
        for (int ni = 0; ni < 4; ni++)
#pragma unroll
            for (int r = 0; r < 4; r++) acc[mi][ni][r] = 0.f;

    const int NT = H1C / 16;   // 8

    auto load_stage = [&](int slot, int t) {
        const int kk0 = t * 16;
        const uint32_t sa = smem_u + slot * STG2;
        const uint32_t sb = sa + A2SZ;
#pragma unroll
        for (int i = 0; i < 2; i++) {
            int idx = tid + i * 256;
            int m = idx >> 2, kc = (idx & 3) * 4;
            cpasync16(sa + (m * A2STR + kc) * 4,
                      A + (size_t)(bm + m) * H1C + kk0 + kc);
        }
#pragma unroll
        for (int i = 0; i < 2; i++) {
            int idx = tid + i * 256;
            int row = idx >> 5, ch = idx & 31;
            cpasync16(sb + (row * B2STR + ch * 4) * 4,
                      g_wB + (size_t)(kk0 + row) * 512 + bn + ch * 4);
        }
    };
    load_stage(0, 0); cpa_commit();
    load_stage(1, 1); cpa_commit();

    for (int t = 0; t < NT; ++t) {
        cpa_wait<1>();
        __syncthreads();
        if (t + 2 < NT) load_stage((t + 2) % 3, t + 2);
        cpa_commit();
        const int cur = t % 3;
        const float* As = (const float*)(dsm + cur * STG2);
        const float* Bs = (const float*)(dsm + cur * STG2 + A2SZ);
#pragma unroll
        for (int ks = 0; ks < 16; ks += 8) {
            unsigned a[4][4], b[4][2];
#pragma unroll
            for (int mi = 0; mi < 4; mi++) {
                int m = wm + mi * 16 + g;
                a[mi][0] = __float_as_uint(As[(m    ) * A2STR + ks + tg]);
                a[mi][1] = __float_as_uint(As[(m + 8) * A2STR + ks + tg]);
                a[mi][2] = __float_as_uint(As[(m    ) * A2STR + ks + tg + 4]);
                a[mi][3] = __float_as_uint(As[(m + 8) * A2STR + ks + tg + 4]);
            }
#pragma unroll
            for (int ni = 0; ni < 4; ni++) {
                int c = wn + ni * 8 + g;
                b[ni][0] = __float_as_uint(Bs[(ks + tg    ) * B2STR + c]);
                b[ni][1] = __float_as_uint(Bs[(ks + tg + 4) * B2STR + c]);
            }
#pragma unroll
            for (int mi = 0; mi < 4; mi++)
#pragma unroll
                for (int ni = 0; ni < 4; ni++)
                    MMA_TF32(acc[mi][ni], a[mi], b[ni]);
        }
    }

    float* tgt = (by < 2) ? g_y2 : g_res2;
    const int nb = (by & 1) * 128;
#pragma unroll
    for (int mi = 0; mi < 4; mi++) {
        int m0 = bm + wm + mi * 16 + g;
#pragma unroll
        for (int ni = 0; ni < 4; ni++) {
            int n = nb + wn + ni * 8 + 2 * tg;
            int pb = bn + wn + ni * 8 + 2 * tg;
            float b0 = g_biasP[pb], b1 = g_biasP[pb + 1];
            *(float2*)(tgt + (size_t)m0 * HHC + n)
                = make_float2(acc[mi][ni][0] + b0, acc[mi][ni][1] + b1);
            *(float2*)(tgt + (size_t)(m0 + 8) * HHC + n)
                = make_float2(acc[mi][ni][2] + b0, acc[mi][ni][3] + b1);
        }
    }
}

// ---------------- node mix for stage 2 --------------------------------------
__global__ void nodemix2(const float* __restrict__ adj, const float* __restrict__ eimp) {
    __shared__ float ys[NNODE*HHC];
    __shared__ float Asm[NNODE*NNODE];
    int bs = blockIdx.x, tid = threadIdx.x;
    if (tid < NNODE*NNODE) Asm[tid] = adj[tid] * eimp[tid];
    for (int e = tid; e < NNODE*HHC; e += blockDim.x)
        ys[e] = g_y2[(size_t)bs*NNODE*HHC + e];
    __syncthreads();
    for (int e = tid; e < NNODE*HHC; e += blockDim.x) {
        int n = e / HHC, c = e % HHC;
        float acc = 0.f;
#pragma unroll
        for (int m = 0; m < NNODE; m++) acc += Asm[n*NNODE + m] * ys[m*HHC + c];
        g_xc2[(size_t)bs*NNODE*HHC + e] = acc;
    }
}

// ---------------- BN apply stage 2 -> [l][c] fp16 ----------------------------
__global__ void bn_apply2_tohalf(const float* __restrict__ g2, const float* __restrict__ beta2,
                                 const float* __restrict__ rg2, const float* __restrict__ rbeta2) {
    int row = blockIdx.x;        // (b*Ss + s)*6 + n
    int c = threadIdx.x;         // 0..255
    const float invM = 1.f / (float)M1R;
    float m1 = g_stats[c] * invM;
    float v1 = g_stats[HHC + c] * invM - m1*m1;
    float m2 = g_stats[2*HHC + c] * invM;
    float v2 = g_stats[3*HHC + c] * invM - m2*m2;
    float sc1 = rsqrtf(v1 + BNEPS) * g2[c];
    float sh1 = beta2[c] - m1*sc1;
    float sc2 = rsqrtf(v2 + BNEPS) * rg2[c];
    float sh2 = rbeta2[c] - m2*sc2;
    size_t ridx = (size_t)row * HHC + c;
    float o = g_xc2[ridx]*sc1 + sh1 + g_res2[ridx]*sc2 + sh2;
    o = o > 0.f ? o : 0.f;
    int n = row % NNODE;
    int bs = row / NNODE;
    int b = bs / Ss, s = bs % Ss;
    g_htH[((size_t)b * LROWS + 16 + s) * TCC + n * HHC + c] = __float2half(o);
}

// ======================= conv1d fp16 mma GEMM ================================
// 8 tile-slots = 4 pair-slots; 2 k16-tiles consumed per wait+barrier;
// wait<2> keeps 4 tiles of prefetch in flight (same depth as 6-stage/wait<4>).
#define ASZh 4096
#define BROWB 48            /* B smem row stride bytes (24 fp16) */
#define BSZh (128*BROWB)    /* 6144 */
#define STGh (ASZh + BSZh)  /* 10240 */

__global__ __launch_bounds__(256, 2) void conv_gemm_f16(
        const __half* __restrict__ X, const __half* __restrict__ Wt,
        __half* __restrict__ Y) {
    extern __shared__ __align__(128) char dsm[];
    const int tid = threadIdx.x;
    const int cb = blockIdx.x;
    const int bm = cb * 128;           // co
    const int bn = blockIdx.y * 128;   // l
    const __half* Xb = X + (size_t)blockIdx.z * LROWS * TCC;
    __half* Yb = Y + (size_t)blockIdx.z * LROWS * TCC;
    const int lane = tid & 31, wid = tid >> 5;
    const int wm = (wid & 1) * 64, wn = (wid >> 1) * 32;
    const int g = lane >> 2, tg = lane & 3;
    const int aoff = (wid & 1) * 4;
    const uint32_t smem_u = s2u(dsm);

    float acc[4][4][4];
#pragma unroll
    for (int mi = 0; mi < 4; mi++)
#pragma unroll
        for (int ni = 0; ni < 4; ni++)
#pragma unroll
            for (int r = 0; r < 4; r++) acc[mi][ni][r] = 0.f;

    const int NP = RKK / 32;   // 240 pairs (480 k16-tiles), 240 % 4 == 0
    const int brow = tid >> 1, bhalf = tid & 1;

    auto load_tile = [&](int slot, int t) {
        const int kseg = t / 96;
        const int ci0  = t * 16 - kseg * TCC;
        const uint32_t sa = smem_u + slot * STGh;
        const uint32_t sb = sa + ASZh;
        cpasync16(sa + tid * 16, Wt + ((size_t)t * 12 + cb) * 2048 + tid * 8);
        const __half* src = Xb + (size_t)(16 + bn + kseg - 2 + brow) * TCC
                              + ci0 + bhalf * 8;
        cpasync16(sb + brow * BROWB + bhalf * 16, src);
    };
    auto load_pair = [&](int ps, int p) {
        load_tile(2 * ps,     2 * p);
        load_tile(2 * ps + 1, 2 * p + 1);
    };

    auto compute_tile = [&](int slot) {
        const uint4* Af = (const uint4*)(dsm + slot * STGh);
        const char* Bs = dsm + slot * STGh + ASZh;
        unsigned a[4][4], b[4][2];
#pragma unroll
        for (int mi = 0; mi < 4; mi++) {
            uint4 v = Af[(aoff + mi) * 32 + lane];
            a[mi][0] = v.x; a[mi][1] = v.y; a[mi][2] = v.z; a[mi][3] = v.w;
        }
#pragma unroll
        for (int ni = 0; ni < 4; ni++) {
            int row = wn + ni * 8 + g;
            b[ni][0] = *(const unsigned*)(Bs + row * BROWB + tg * 4);
            b[ni][1] = *(const unsigned*)(Bs + row * BROWB + 16 + tg * 4);
        }
#pragma unroll
        for (int mi = 0; mi < 4; mi++)
#pragma unroll
            for (int ni = 0; ni < 4; ni++)
                MMA_F16(acc[mi][ni], a[mi], b[ni]);
    };

    load_pair(0, 0); cpa_commit();
    load_pair(1, 1); cpa_commit();
    load_pair(2, 2); cpa_commit();

    for (int pb = 0; pb < NP; pb += 4) {
#pragma unroll
        for (int s = 0; s < 4; s++) {
            const int p = pb + s;
            cpa_wait<2>();
            __syncthreads();
            if (p + 3 < NP) load_pair((s + 3) & 3, p + 3);
            cpa_commit();
            compute_tile(2 * s);
            compute_tile(2 * s + 1);
        }
    }

    // epilogue: store fp16 [l][c] + fused per-channel stats from fp32 accs
#pragma unroll
    for (int mi = 0; mi < 4; mi++) {
        int m0 = bm + wm + mi * 16 + g;
        float s0 = 0.f, q0 = 0.f, s1 = 0.f, q1 = 0.f;
#pragma unroll
        for (int ni = 0; ni < 4; ni++) {
            float v0 = acc[mi][ni][0], v1 = acc[mi][ni][1];
            float v2 = acc[mi][ni][2], v3 = acc[mi][ni][3];
            s0 += v0 + v1; q0 += v0*v0 + v1*v1;
            s1 += v2 + v3; q1 += v2*v2 + v3*v3;
            int l0 = bn + wn + ni * 8 + 2 * tg;
            size_t r0 = ((size_t)(16 + l0)) * TCC;
            size_t r1 = ((size_t)(17 + l0)) * TCC;
            Yb[r0 + m0]     = __float2half(v0);
            Yb[r1 + m0]     = __float2half(v1);
            Yb[r0 + m0 + 8] = __float2half(v2);
            Yb[r1 + m0 + 8] = __float2half(v3);
        }
        s0 += __shfl_xor_sync(0xffffffffu, s0, 1);
        s0 += __shfl_xor_sync(0xffffffffu, s0, 2);
        q0 += __shfl_xor_sync(0xffffffffu, q0, 1);
        q0 += __shfl_xor_sync(0xffffffffu, q0, 2);
        s1 += __shfl_xor_sync(0xffffffffu, s1, 1);
        s1 += __shfl_xor_sync(0xffffffffu, s1, 2);
        q1 += __shfl_xor_sync(0xffffffffu, q1, 1);
        q1 += __shfl_xor_sync(0xffffffffu, q1, 2);
        if (tg == 0) {
            atomicAdd(&g_stats[m0],         s0);
            atomicAdd(&g_stats[TCC + m0],   q0);
            atomicAdd(&g_stats[m0 + 8],     s1);
            atomicAdd(&g_stats[TCC + m0+8], q1);
        }
    }
}

// ---------------- conv BN apply in-place on fp16 [l][c] ----------------------
__global__ void conv_bnH(__half* __restrict__ T, const float* __restrict__ g,
                         const float* __restrict__ beta, const __half* __restrict__ resid) {
    size_t idx = (size_t)blockIdx.x * blockDim.x + threadIdx.x;
    const size_t total = (size_t)Bb * LLEN * (TCC/2);
    if (idx >= total) return;
    int c2  = (int)(idx % (TCC/2));
    int l   = (int)((idx / (TCC/2)) % LLEN);
    int b   = (int)(idx / ((size_t)(TCC/2) * LLEN));
    int c   = c2 * 2;
    size_t a = ((size_t)b * LROWS + 16 + l) * TCC + c;
    const float invM = 1.f / (float)(Bb * LLEN);
    float m0 = g_stats[c] * invM;
    float va = g_stats[TCC + c] * invM - m0*m0;
    float m1 = g_stats[c+1] * invM;
    float vb = g_stats[TCC + c+1] * invM - m1*m1;
    __half2 hv = *(__half2*)(T + a);
    float2 f = __half22float2(hv);
    float o0 = (f.x - m0) * rsqrtf(va + BNEPS) * g[c]   + beta[c];
    float o1 = (f.y - m1) * rsqrtf(vb + BNEPS) * g[c+1] + beta[c+1];
    o0 = o0 > 0.f ? o0 : 0.f;
    o1 = o1 > 0.f ? o1 : 0.f;
    if (resid) {
        float2 r = __half22float2(*(const __half2*)(resid + a));
        o0 += r.x; o1 += r.y;
    }
    *(__half2*)(T + a) = __floats2half2_rn(o0, o1);
}

// ======================= output GEMM (fp16 mma, permuted A) =================
#define STGOh (ASZh + BSZh)

__global__ __launch_bounds__(256, 2) void out_gemm_f16(
        const __half* __restrict__ T2, const float* __restrict__ OB,
        float* __restrict__ OUT) {
    extern __shared__ __align__(128) char dsm[];
    const int tid = threadIdx.x;
    const int cb = blockIdx.x;
    const int bm = cb * 128;           // o
    const int bn = blockIdx.y * 128;   // s
    const int b  = blockIdx.z;
    const __half* T2b = T2 + (size_t)b * LROWS * TCC;
    const int lane = tid & 31, wid = tid >> 5;
    const int wm = (wid & 1) * 64, wn = (wid >> 1) * 32;
    const int g = lane >> 2, tg = lane & 3;
    const int aoff = (wid & 1) * 4;
    const uint32_t smem_u = s2u(dsm);

    float acc[4][4][4];
#pragma unroll
    for (int mi = 0; mi < 4; mi++)
#pragma unroll
        for (int ni = 0; ni < 4; ni++)
#pragma unroll
            for (int r = 0; r < 4; r++) acc[mi][ni][r] = 0.f;

    const int NT = TCC / 16;   // 96
    const int brow = tid >> 1, bhalf = tid & 1;

    auto load_stage = [&](int slot, int t) {
        const uint32_t sa = smem_u + slot * STGOh;
        const uint32_t sb = sa + ASZh;
        cpasync16(sa + tid * 16, g_owRH + ((size_t)t * 2 + cb) * 2048 + tid * 8);
        const __half* src = T2b + (size_t)(16 + bn + brow) * TCC + t * 16 + bhalf * 8;
        cpasync16(sb + brow * BROWB + bhalf * 16, src);
    };
    load_stage(0, 0); cpa_commit();
    load_stage(1, 1); cpa_commit();

    for (int t = 0; t < NT; ++t) {
        cpa_wait<1>();
        __syncthreads();
        if (t + 2 < NT) load_stage((t + 2) % 3, t + 2);
        cpa_commit();
        const int cur = t % 3;
        const uint4* Af = (const uint4*)(dsm + cur * STGOh);
        const char* Bs = dsm + cur * STGOh + ASZh;

        unsigned a[4][4], b[4][2];
#pragma unroll
        for (int mi = 0; mi < 4; mi++) {
            uint4 v = Af[(aoff + mi) * 32 + lane];
            a[mi][0] = v.x; a[mi][1] = v.y; a[mi][2] = v.z; a[mi][3] = v.w;
        }
#pragma unroll
        for (int ni = 0; ni < 4; ni++) {
            int row = wn + ni * 8 + g;
            b[ni][0] = *(const unsigned*)(Bs + row * BROWB + tg * 4);
            b[ni][1] = *(const unsigned*)(Bs + row * BROWB + 16 + tg * 4);
        }
#pragma unroll
        for (int mi = 0; mi < 4; mi++)
#pragma unroll
            for (int ni = 0; ni < 4; ni++)
                MMA_F16(acc[mi][ni], a[mi], b[ni]);
    }

#pragma unroll
    for (int mi = 0; mi < 4; mi++) {
        int o0 = bm + wm + mi * 16 + g;
        float bo0 = OB[o0], bo1 = OB[o0 + 8];
#pragma unroll
        for (int ni = 0; ni < 4; ni++) {
            int sL = bn + wn + ni * 8 + 2 * tg;
            float v0 = acc[mi][ni][0] + bo0; v0 = v0 > 0.f ? v0 : 0.f;
            float v1 = acc[mi][ni][1] + bo0; v1 = v1 > 0.f ? v1 : 0.f;
            float v2 = acc[mi][ni][2] + bo1; v2 = v2 > 0.f ? v2 : 0.f;
            float v3 = acc[mi][ni][3] + bo1; v3 = v3 > 0.f ? v3 : 0.f;
            OUT[((size_t)b * Ss + sL    ) * HHC + o0    ] = v0;
            OUT[((size_t)b * Ss + sL + 1) * HHC + o0    ] = v1;
            OUT[((size_t)b * Ss + sL    ) * HHC + o0 + 8] = v2;
            OUT[((size_t)b * Ss + sL + 1) * HHC + o0 + 8] = v3;
        }
    }
}

// ---------------- launch ----------------------------------------------------
extern "C" void kernel_launch(void* const* d_in, const int* in_sizes, int n_in,
                              void* d_out, int out_size) {
    const float* x     = (const float*)d_in[0];
    const float* adj   = (const float*)d_in[1];
    const float* eimp  = (const float*)d_in[2];
    const float* w1    = (const float*)d_in[3];
    const float* b1    = (const float*)d_in[4];
    const float* rw1   = (const float*)d_in[5];
    const float* rb1   = (const float*)d_in[6];
    const float* rg1   = (const float*)d_in[7];
    const float* rbeta1= (const float*)d_in[8];
    const float* g1    = (const float*)d_in[9];
    const float* beta1 = (const float*)d_in[10];
    const float* w2    = (const float*)d_in[11];
    const float* b2    = (const float*)d_in[12];
    const float* rw2   = (const float*)d_in[13];
    const float* rb2   = (const float*)d_in[14];
    const float* rg2   = (const float*)d_in[15];
    const float* rbeta2= (const float*)d_in[16];
    const float* g2    = (const float*)d_in[17];
    const float* beta2 = (const float*)d_in[18];
    const float* cw1   = (const float*)d_in[19];
    /* cb1 = d_in[20]: cancels exactly through BN mean-subtraction */
    const float* cg1   = (const float*)d_in[21];
    const float* cbeta1= (const float*)d_in[22];
    const float* cw2   = (const float*)d_in[23];
    /* cb2 = d_in[24]: cancels exactly */
    const float* cg2   = (const float*)d_in[25];
    const float* cbeta2= (const float*)d_in[26];
    const float* ow    = (const float*)d_in[27];
    const float* ob    = (const float*)d_in[28];
    float* out = (float*)d_out;

    float *p_xc1, *p_res1, *p_xc2, *p_res2;
    __half *p_htH, *p_t1H, *p_t2H, *p_wt1H, *p_wt2H;
    cudaGetSymbolAddress((void**)&p_xc1,  g_xc1);
    cudaGetSymbolAddress((void**)&p_res1, g_res1);
    cudaGetSymbolAddress((void**)&p_xc2,  g_xc2);
    cudaGetSymbolAddress((void**)&p_res2, g_res2);
    cudaGetSymbolAddress((void**)&p_htH,  g_htH);
    cudaGetSymbolAddress((void**)&p_t1H,  g_t1H);
    cudaGetSymbolAddress((void**)&p_t2H,  g_t2H);
    cudaGetSymbolAddress((void**)&p_wt1H, g_wt1H);
    cudaGetSymbolAddress((void**)&p_wt2H, g_wt2H);

    cudaFuncSetAttribute(conv_gemm_f16,
                         cudaFuncAttributeMaxDynamicSharedMemorySize, 8 * STGh);
    cudaFuncSetAttribute(gcn2_gemm_tf32,
                         cudaFuncAttributeMaxDynamicSharedMemorySize, 3 * STG2);
    cudaFuncSetAttribute(out_gemm_f16,
                         cudaFuncAttributeMaxDynamicSharedMemorySize, 3 * STGOh);

    // -------- GCN stage 1 --------
    gcn1_kernel<<<NBS, 256>>>(x, adj, eimp, w1, b1, rw1, rb1);
    zero_stats_k<<<(4*TCC + 255)/256, 256>>>();
    zero_padsH<<<(Bb*32*(TCC/8) + 255)/256, 256>>>();
    pack_gcn2<<<(H1C*HHC + 255)/256, 256>>>(w2, rw2, b2, rb2);
    pack_owH<<<(TCC/16)*2, 256>>>(ow);
    stats_rows<<<1024, H1C>>>(p_xc1, p_res1, M1R, H1C);
    bn_apply1<<<(M1R*H1C)/256, 256>>>(g1, beta1, rg1, rbeta1);

    // -------- GCN stage 2 (tf32 dual GEMM) --------
    gcn2_gemm_tf32<<<dim3(M1R/128, 4), 256, 3*STG2>>>();
    nodemix2<<<NBS, 256>>>(adj, eimp);
    zero_stats_k<<<(4*TCC + 255)/256, 256>>>();
    stats_rows<<<1024, HHC>>>(p_xc2, p_res2, M1R, HHC);
    bn_apply2_tohalf<<<M1R, 256>>>(g2, beta2, rg2, rbeta2);

    // -------- TCN conv 1 (fp16 mma, 4-pair pipeline) --------
    wtrans_convH2<<<96*12, 256>>>(cw1, p_wt1H);
    zero_stats_k<<<(4*TCC + 255)/256, 256>>>();
    conv_gemm_f16<<<dim3(TCC/128, LLEN/128, Bb), 256, 8*STGh>>>(p_htH, p_wt1H, p_t1H);
    conv_bnH<<<(Bb*LLEN*(TCC/2) + 255)/256, 256>>>(p_t1H, cg1, cbeta1, (const __half*)nullptr);

    // -------- TCN conv 2 + residual --------
    wtrans_convH2<<<96*12, 256>>>(cw2, p_wt2H);
    zero_stats_k<<<(4*TCC + 255)/256, 256>>>();
    conv_gemm_f16<<<dim3(TCC/128, LLEN/128, Bb), 256, 8*STGh>>>(p_t1H, p_wt2H, p_t2H);
    conv_bnH<<<(Bb*LLEN*(TCC/2) + 255)/256, 256>>>(p_t2H, cg2, cbeta2, p_htH);

    // -------- output layer (fp16 mma) --------
    out_gemm_f16<<<dim3(HHC/128, LLEN/128, Bb), 256, 3*STGOh>>>(p_t2H, ob, out);

    (void)in_sizes; (void)n_in; (void)out_size;
}

// round 11
// speedup vs baseline: 1.1754x; 1.1714x over previous
#include <cuda_runtime.h>
#include <cuda_fp16.h>
#include <math.h>
#include <stdint.h>

#define Bb 32
#define Ss 512
#define NNODE 6
#define CIN 12
#define H1C 128
#define HHC 256
#define TCC 1536
#define LLEN 512
#define LROWS 544           /* 16 pad | 512 | 16 pad rows in [l][c] layout */
#define M1R (Bb*Ss*NNODE)   /* 98304 */
#define NBS (Bb*Ss)         /* 16384 */
#define RKK (5*TCC)         /* 7680  */
#define BNEPS 1e-5f

// ---------------- scratch (device globals; no runtime allocation) ----------
__device__ float  g_xc1 [M1R*H1C];
__device__ float  g_res1[M1R*H1C];
__device__ float  g_h1  [M1R*H1C];     // tf32-rounded at write
__device__ float  g_y2  [M1R*HHC];
__device__ float  g_res2[M1R*HHC];
__device__ float  g_xc2 [M1R*HHC];
__device__ __half g_htH [Bb*LROWS*TCC];  // [l][c] fp16, padded rows
__device__ __half g_t1H [Bb*LROWS*TCC];
__device__ __half g_t2H [Bb*LROWS*TCC];
__device__ __half g_wt1H[RKK*TCC];       // fragment-permuted fp16 tiles
__device__ __half g_wt2H[RKK*TCC];
__device__ float  g_wB  [H1C*512];       // packed (w2T | rw2T), tf32 bits
__device__ float  g_biasP[512];
__device__ __half g_owRH[TCC*HHC];       // fragment-permuted ow fp16 tiles
__device__ float  g_stats[4*TCC];

// ---------------- helpers ----------------------------------------------------
__device__ __forceinline__ unsigned f2tf32(float f) {
    unsigned u; asm("cvt.rna.tf32.f32 %0, %1;" : "=r"(u) : "f"(f)); return u;
}
#define MMA_TF32(c, a, b) \
    asm volatile("mma.sync.aligned.m16n8k8.row.col.f32.tf32.tf32.f32 " \
        "{%0,%1,%2,%3}, {%4,%5,%6,%7}, {%8,%9}, {%0,%1,%2,%3};" \
        : "+f"((c)[0]), "+f"((c)[1]), "+f"((c)[2]), "+f"((c)[3]) \
        : "r"((a)[0]), "r"((a)[1]), "r"((a)[2]), "r"((a)[3]), \
          "r"((b)[0]), "r"((b)[1]))
#define MMA_F16(c, a, b) \
    asm volatile("mma.sync.aligned.m16n8k16.row.col.f32.f16.f16.f32 " \
        "{%0,%1,%2,%3}, {%4,%5,%6,%7}, {%8,%9}, {%0,%1,%2,%3};" \
        : "+f"((c)[0]), "+f"((c)[1]), "+f"((c)[2]), "+f"((c)[3]) \
        : "r"((a)[0]), "r"((a)[1]), "r"((a)[2]), "r"((a)[3]), \
          "r"((b)[0]), "r"((b)[1]))

__device__ __forceinline__ void cpasync16(uint32_t dst, const void* src) {
    asm volatile("cp.async.cg.shared.global [%0], [%1], 16;" :: "r"(dst), "l"(src));
}
__device__ __forceinline__ void cpa_commit() {
    asm volatile("cp.async.commit_group;" ::: "memory");
}
template<int N>
__device__ __forceinline__ void cpa_wait() {
    asm volatile("cp.async.wait_group %0;" :: "n"(N) : "memory");
}
__device__ __forceinline__ uint32_t s2u(const void* p) {
    return (uint32_t)__cvta_generic_to_shared(p);
}
__device__ __forceinline__ unsigned packh2(float a, float b) {
    __half2 h = __floats2half2_rn(a, b);
    return *(unsigned*)&h;
}

// ---------------- small utility kernels ------------------------------------
__global__ void zero_stats_k() {
    int i = blockIdx.x * blockDim.x + threadIdx.x;
    if (i < 4*TCC) g_stats[i] = 0.f;
}

// zero pad rows (0..15, 528..543) of ht and t1 fp16 tensors
__global__ void zero_padsH() {
    int idx = blockIdx.x * blockDim.x + threadIdx.x;
    const int per = Bb * 32 * (TCC/8);
    if (idx >= per) return;
    int col8 = idx % (TCC/8);
    int rr   = (idx / (TCC/8)) % 32;
    int b    = idx / (32 * (TCC/8));
    int row  = rr < 16 ? rr : 512 + rr;
    size_t off = ((size_t)b * LROWS + row) * TCC + col8 * 8;
    uint4 z = make_uint4(0,0,0,0);
    *(uint4*)((char*)g_htH + off*2) = z;
    *(uint4*)((char*)g_t1H + off*2) = z;
}

// pack w2/rw2 into wB (tf32 bits) -- gcn2 stays tf32
__global__ void pack_gcn2(const float* __restrict__ w2, const float* __restrict__ rw2,
                          const float* __restrict__ b2, const float* __restrict__ rb2) {
    int idx = blockIdx.x * blockDim.x + threadIdx.x;
    if (idx >= H1C * HHC) return;
    int i = idx >> 8;
    int o = idx & 255;
    unsigned* wB = (unsigned*)g_wB;
    wB[i * 512 + o]       = f2tf32(w2[(size_t)o * H1C + i]);
    wB[i * 512 + 256 + o] = f2tf32(rw2[(size_t)o * H1C + i]);
    if (i == 0) { g_biasP[o] = b2[o]; g_biasP[256 + o] = rb2[o]; }
}

// ---- fp16 fragment permutation for m16n8k16 --------------------------------
// coalesced conv-weight transform: one block stages 128co x 80 floats
// (16 ci x 5 k contiguous range) in smem, emits all 5 k-tiles.
__global__ void wtrans_convH2(const float* __restrict__ cw, __half* __restrict__ wt) {
    __shared__ float sm[128 * 81];
    int blk = blockIdx.x;                 // cib*12 + cb ; cib in [0,96)
    int cib = blk / 12, cb = blk % 12;
    int ci0 = cib * 16;
    int tid = threadIdx.x;
    for (int i = tid; i < 128 * 80; i += 256) {
        int co = i / 80, j = i % 80;
        sm[co * 81 + j] = cw[((size_t)(cb * 128 + co) * TCC + ci0) * 5 + j];
    }
    __syncthreads();
#pragma unroll
    for (int k = 0; k < 5; k++) {
        int tile = (k * 96 + cib) * 12 + cb;
        unsigned* dst = (unsigned*)wt + (size_t)tile * 1024 + tid * 4;
#pragma unroll
        for (int u = 0; u < 4; u++) {
            int pos = tid * 4 + u;
            int r = pos & 3, lane = (pos >> 2) & 31, mi = pos >> 7;
            int kl = 2 * (lane & 3) + ((r >> 1) << 3);
            int ml = mi * 16 + (lane >> 2) + ((r & 1) << 3);
            float f0 = sm[ml * 81 + kl * 5 + k];
            float f1 = sm[ml * 81 + (kl + 1) * 5 + k];
            dst[u] = packh2(f0, f1);
        }
    }
}

__global__ void pack_owH(const float* __restrict__ ow) {
    int tile = blockIdx.x;                    // tk*2 + cb ; tk in [0,96)
    int tk = tile >> 1, cb = tile & 1;
    int tid = threadIdx.x;
    unsigned* dst = (unsigned*)g_owRH + (size_t)tile * 1024 + tid * 4;
#pragma unroll
    for (int u = 0; u < 4; u++) {
        int pos = tid * 4 + u;
        int r = pos & 3, lane = (pos >> 2) & 31, mi = pos >> 7;
        int kl = 2 * (lane & 3) + ((r >> 1) << 3);
        int ml = mi * 16 + (lane >> 2) + ((r & 1) << 3);
        int c = tk * 16 + kl;
        int o = cb * 128 + ml;
        float f0 = ow[(size_t)o * TCC + c];
        float f1 = ow[(size_t)o * TCC + c + 1];
        dst[u] = packh2(f0, f1);
    }
}

// ---------------- GCN stage 1 ------------------------------------------------
__global__ void gcn1_kernel(const float* __restrict__ x, const float* __restrict__ adj,
                            const float* __restrict__ eimp,
                            const float* __restrict__ w1, const float* __restrict__ b1,
                            const float* __restrict__ rw1, const float* __restrict__ rb1) {
    __shared__ float xs[NNODE*CIN];
    __shared__ float Asm[NNODE*NNODE];
    __shared__ float xts[NNODE*H1C];
    int bs = blockIdx.x;
    int tid = threadIdx.x;
    if (tid < NNODE*CIN) xs[tid] = x[(size_t)bs*NNODE*CIN + tid];
    if (tid >= 128 && tid < 128 + NNODE*NNODE) Asm[tid-128] = adj[tid-128] * eimp[tid-128];
    __syncthreads();
    for (int e = tid; e < NNODE*H1C; e += blockDim.x) {
        int n = e / H1C, c = e % H1C;
        float ws = b1[c], rs = rb1[c];
#pragma unroll
        for (int i = 0; i < CIN; i++) {
            float xv = xs[n*CIN + i];
            ws += xv * w1[c*CIN + i];
            rs += xv * rw1[c*CIN + i];
        }
        xts[e] = ws;
        g_res1[(size_t)bs*(NNODE*H1C) + e] = rs;
    }
    __syncthreads();
    for (int e = tid; e < NNODE*H1C; e += blockDim.x) {
        int n = e / H1C, c = e % H1C;
        float acc = 0.f;
#pragma unroll
        for (int m = 0; m < NNODE; m++) acc += Asm[n*NNODE + m] * xts[m*H1C + c];
        g_xc1[(size_t)bs*(NNODE*H1C) + e] = acc;
    }
}

__global__ void stats_rows(const float* __restrict__ a, const float* __restrict__ b,
                           int Mrows, int C) {
    int c = threadIdx.x;
    int rows_per = Mrows / gridDim.x;
    int r0 = blockIdx.x * rows_per;
    int r1 = r0 + rows_per;
    float sa = 0.f, qa = 0.f, sb = 0.f, qb = 0.f;
    for (int r = r0; r < r1; r++) {
        float v = a[(size_t)r*C + c]; sa += v; qa += v*v;
        float u = b[(size_t)r*C + c]; sb += u; qb += u*u;
    }
    atomicAdd(&g_stats[c],       sa);
    atomicAdd(&g_stats[C + c],   qa);
    atomicAdd(&g_stats[2*C + c], sb);
    atomicAdd(&g_stats[3*C + c], qb);
}

__global__ void bn_apply1(const float* __restrict__ g1, const float* __restrict__ beta1,
                          const float* __restrict__ rg1, const float* __restrict__ rbeta1) {
    size_t idx = (size_t)blockIdx.x * blockDim.x + threadIdx.x;
    if (idx >= (size_t)M1R*H1C) return;
    int c = (int)(idx % H1C);
    const float invM = 1.f / (float)M1R;
    float m1 = g_stats[c] * invM;
    float v1 = g_stats[H1C + c] * invM - m1*m1;
    float m2 = g_stats[2*H1C + c] * invM;
    float v2 = g_stats[3*H1C + c] * invM - m2*m2;
    float a = (g_xc1[idx]  - m1) * rsqrtf(v1 + BNEPS) * g1[c]  + beta1[c];
    float r = (g_res1[idx] - m2) * rsqrtf(v2 + BNEPS) * rg1[c] + rbeta1[c];
    float o = a + r;
    o = o > 0.f ? o : 0.f;
    g_h1[idx] = __uint_as_float(f2tf32(o));
}

// ---------------- gcn2 dual GEMM (tf32 mma, unchanged) ----------------------
#define A2STR 20
#define B2STR 136
#define A2SZ (128*A2STR*4)
#define B2SZ (16*B2STR*4)
#define STG2 (A2SZ + B2SZ)

__global__ __launch_bounds__(256, 2) void gcn2_gemm_tf32() {
    extern __shared__ __align__(128) char dsm[];
    const int tid = threadIdx.x;
    const int bm = blockIdx.x * 128;
    const int by = blockIdx.y;
    const int bn = by * 128;
    const int lane = tid & 31, wid = tid >> 5;
    const int wm = (wid & 1) * 64, wn = (wid >> 1) * 32;
    const int g = lane >> 2, tg = lane & 3;
    const uint32_t smem_u = s2u(dsm);
    const float* A = g_h1;

    float acc[4][4][4];
#pragma unroll
    for (int mi = 0; mi < 4; mi++)
#pragma unroll
        for (int ni = 0; ni < 4; ni++)
#pragma unroll
            for (int r = 0; r < 4; r++) acc[mi][ni][r] = 0.f;

    const int NT = H1C / 16;   // 8

    auto load_stage = [&](int slot, int t) {
        const int kk0 = t * 16;
        const uint32_t sa = smem_u + slot * STG2;
        const uint32_t sb = sa + A2SZ;
#pragma unroll
        for (int i = 0; i < 2; i++) {
            int idx = tid + i * 256;
            int m = idx >> 2, kc = (idx & 3) * 4;
            cpasync16(sa + (m * A2STR + kc) * 4,
                      A + (size_t)(bm + m) * H1C + kk0 + kc);
        }
#pragma unroll
        for (int i = 0; i < 2; i++) {
            int idx = tid + i * 256;
            int row = idx >> 5, ch = idx & 31;
            cpasync16(sb + (row * B2STR + ch * 4) * 4,
                      g_wB + (size_t)(kk0 + row) * 512 + bn + ch * 4);
        }
    };
    load_stage(0, 0); cpa_commit();
    load_stage(1, 1); cpa_commit();

    for (int t = 0; t < NT; ++t) {
        cpa_wait<1>();
        __syncthreads();
        if (t + 2 < NT) load_stage((t + 2) % 3, t + 2);
        cpa_commit();
        const int cur = t % 3;
        const float* As = (const float*)(dsm + cur * STG2);
        const float* Bs = (const float*)(dsm + cur * STG2 + A2SZ);
#pragma unroll
        for (int ks = 0; ks < 16; ks += 8) {
            unsigned a[4][4], b[4][2];
#pragma unroll
            for (int mi = 0; mi < 4; mi++) {
                int m = wm + mi * 16 + g;
                a[mi][0] = __float_as_uint(As[(m    ) * A2STR + ks + tg]);
                a[mi][1] = __float_as_uint(As[(m + 8) * A2STR + ks + tg]);
                a[mi][2] = __float_as_uint(As[(m    ) * A2STR + ks + tg + 4]);
                a[mi][3] = __float_as_uint(As[(m + 8) * A2STR + ks + tg + 4]);
            }
#pragma unroll
            for (int ni = 0; ni < 4; ni++) {
                int c = wn + ni * 8 + g;
                b[ni][0] = __float_as_uint(Bs[(ks + tg    ) * B2STR + c]);
                b[ni][1] = __float_as_uint(Bs[(ks + tg + 4) * B2STR + c]);
            }
#pragma unroll
            for (int mi = 0; mi < 4; mi++)
#pragma unroll
                for (int ni = 0; ni < 4; ni++)
                    MMA_TF32(acc[mi][ni], a[mi], b[ni]);
        }
    }

    float* tgt = (by < 2) ? g_y2 : g_res2;
    const int nb = (by & 1) * 128;
#pragma unroll
    for (int mi = 0; mi < 4; mi++) {
        int m0 = bm + wm + mi * 16 + g;
#pragma unroll
        for (int ni = 0; ni < 4; ni++) {
            int n = nb + wn + ni * 8 + 2 * tg;
            int pb = bn + wn + ni * 8 + 2 * tg;
            float b0 = g_biasP[pb], b1 = g_biasP[pb + 1];
            *(float2*)(tgt + (size_t)m0 * HHC + n)
                = make_float2(acc[mi][ni][0] + b0, acc[mi][ni][1] + b1);
            *(float2*)(tgt + (size_t)(m0 + 8) * HHC + n)
                = make_float2(acc[mi][ni][2] + b0, acc[mi][ni][3] + b1);
        }
    }
}

// ---------------- node mix for stage 2 --------------------------------------
__global__ void nodemix2(const float* __restrict__ adj, const float* __restrict__ eimp) {
    __shared__ float ys[NNODE*HHC];
    __shared__ float Asm[NNODE*NNODE];
    int bs = blockIdx.x, tid = threadIdx.x;
    if (tid < NNODE*NNODE) Asm[tid] = adj[tid] * eimp[tid];
    for (int e = tid; e < NNODE*HHC; e += blockDim.x)
        ys[e] = g_y2[(size_t)bs*NNODE*HHC + e];
    __syncthreads();
    for (int e = tid; e < NNODE*HHC; e += blockDim.x) {
        int n = e / HHC, c = e % HHC;
        float acc = 0.f;
#pragma unroll
        for (int m = 0; m < NNODE; m++) acc += Asm[n*NNODE + m] * ys[m*HHC + c];
        g_xc2[(size_t)bs*NNODE*HHC + e] = acc;
    }
}

// ---------------- BN apply stage 2 -> [l][c] fp16 ----------------------------
__global__ void bn_apply2_tohalf(const float* __restrict__ g2, const float* __restrict__ beta2,
                                 const float* __restrict__ rg2, const float* __restrict__ rbeta2) {
    int row = blockIdx.x;        // (b*Ss + s)*6 + n
    int c = threadIdx.x;         // 0..255
    const float invM = 1.f / (float)M1R;
    float m1 = g_stats[c] * invM;
    float v1 = g_stats[HHC + c] * invM - m1*m1;
    float m2 = g_stats[2*HHC + c] * invM;
    float v2 = g_stats[3*HHC + c] * invM - m2*m2;
    float sc1 = rsqrtf(v1 + BNEPS) * g2[c];
    float sh1 = beta2[c] - m1*sc1;
    float sc2 = rsqrtf(v2 + BNEPS) * rg2[c];
    float sh2 = rbeta2[c] - m2*sc2;
    size_t ridx = (size_t)row * HHC + c;
    float o = g_xc2[ridx]*sc1 + sh1 + g_res2[ridx]*sc2 + sh2;
    o = o > 0.f ? o : 0.f;
    int n = row % NNODE;
    int bs = row / NNODE;
    int b = bs / Ss, s = bs % Ss;
    g_htH[((size_t)b * LROWS + 16 + s) * TCC + n * HHC + c] = __float2half(o);
}

// ======================= conv1d fp16 mma GEMM (round-8 mainloop) ============
// 6 single-tile stages, wait<4>: 4 tiles of prefetch, one tile per barrier.
#define ASZh 4096
#define BROWB 48            /* B smem row stride bytes (24 fp16) */
#define BSZh (128*BROWB)    /* 6144 */
#define STGh (ASZh + BSZh)  /* 10240 */
#define CSTAGES 6

__global__ __launch_bounds__(256, 2) void conv_gemm_f16(
        const __half* __restrict__ X, const __half* __restrict__ Wt,
        __half* __restrict__ Y) {
    extern __shared__ __align__(128) char dsm[];
    const int tid = threadIdx.x;
    const int cb = blockIdx.x;
    const int bm = cb * 128;           // co
    const int bn = blockIdx.y * 128;   // l
    const __half* Xb = X + (size_t)blockIdx.z * LROWS * TCC;
    __half* Yb = Y + (size_t)blockIdx.z * LROWS * TCC;
    const int lane = tid & 31, wid = tid >> 5;
    const int wm = (wid & 1) * 64, wn = (wid >> 1) * 32;
    const int g = lane >> 2, tg = lane & 3;
    const int aoff = (wid & 1) * 4;
    const uint32_t smem_u = s2u(dsm);

    float acc[4][4][4];
#pragma unroll
    for (int mi = 0; mi < 4; mi++)
#pragma unroll
        for (int ni = 0; ni < 4; ni++)
#pragma unroll
            for (int r = 0; r < 4; r++) acc[mi][ni][r] = 0.f;

    const int NT = RKK / 16;   // 480 = 80 * 6
    const int brow = tid >> 1, bhalf = tid & 1;

    auto load_stage = [&](int slot, int t) {
        const int kseg = t / 96;           // (t*16)/TCC
        const int ci0  = t * 16 - kseg * TCC;
        const uint32_t sa = smem_u + slot * STGh;
        const uint32_t sb = sa + ASZh;
        // A: permuted fp16 weight tile, 4KB straight copy
        cpasync16(sa + tid * 16, Wt + ((size_t)t * 12 + cb) * 2048 + tid * 8);
        // B: 128 rows x 32B from [l][c], shift baked into row base
        const __half* src = Xb + (size_t)(16 + bn + kseg - 2 + brow) * TCC
                              + ci0 + bhalf * 8;
        cpasync16(sb + brow * BROWB + bhalf * 16, src);
    };

    load_stage(0, 0); cpa_commit();
    load_stage(1, 1); cpa_commit();
    load_stage(2, 2); cpa_commit();
    load_stage(3, 3); cpa_commit();
    load_stage(4, 4); cpa_commit();

    for (int tb = 0; tb < NT; tb += CSTAGES) {
#pragma unroll
        for (int s = 0; s < CSTAGES; s++) {
            const int t = tb + s;
            cpa_wait<CSTAGES - 2>();
            __syncthreads();
            if (t + 5 < NT) load_stage((s + 5) % CSTAGES, t + 5);
            cpa_commit();

            const uint4* Af = (const uint4*)(dsm + s * STGh);
            const char* Bs = dsm + s * STGh + ASZh;

            unsigned a[4][4], b[4][2];
#pragma unroll
            for (int mi = 0; mi < 4; mi++) {
                uint4 v = Af[(aoff + mi) * 32 + lane];
                a[mi][0] = v.x; a[mi][1] = v.y; a[mi][2] = v.z; a[mi][3] = v.w;
            }
#pragma unroll
            for (int ni = 0; ni < 4; ni++) {
                int row = wn + ni * 8 + g;
                b[ni][0] = *(const unsigned*)(Bs + row * BROWB + tg * 4);
                b[ni][1] = *(const unsigned*)(Bs + row * BROWB + 16 + tg * 4);
            }
#pragma unroll
            for (int mi = 0; mi < 4; mi++)
#pragma unroll
                for (int ni = 0; ni < 4; ni++)
                    MMA_F16(acc[mi][ni], a[mi], b[ni]);
        }
    }

    // epilogue: store fp16 [l][c] + fused per-channel stats from fp32 accs
#pragma unroll
    for (int mi = 0; mi < 4; mi++) {
        int m0 = bm + wm + mi * 16 + g;
        float s0 = 0.f, q0 = 0.f, s1 = 0.f, q1 = 0.f;
#pragma unroll
        for (int ni = 0; ni < 4; ni++) {
            float v0 = acc[mi][ni][0], v1 = acc[mi][ni][1];
            float v2 = acc[mi][ni][2], v3 = acc[mi][ni][3];
            s0 += v0 + v1; q0 += v0*v0 + v1*v1;
            s1 += v2 + v3; q1 += v2*v2 + v3*v3;
            int l0 = bn + wn + ni * 8 + 2 * tg;
            size_t r0 = ((size_t)(16 + l0)) * TCC;
            size_t r1 = ((size_t)(17 + l0)) * TCC;
            Yb[r0 + m0]     = __float2half(v0);
            Yb[r1 + m0]     = __float2half(v1);
            Yb[r0 + m0 + 8] = __float2half(v2);
            Yb[r1 + m0 + 8] = __float2half(v3);
        }
        s0 += __shfl_xor_sync(0xffffffffu, s0, 1);
        s0 += __shfl_xor_sync(0xffffffffu, s0, 2);
        q0 += __shfl_xor_sync(0xffffffffu, q0, 1);
        q0 += __shfl_xor_sync(0xffffffffu, q0, 2);
        s1 += __shfl_xor_sync(0xffffffffu, s1, 1);
        s1 += __shfl_xor_sync(0xffffffffu, s1, 2);
        q1 += __shfl_xor_sync(0xffffffffu, q1, 1);
        q1 += __shfl_xor_sync(0xffffffffu, q1, 2);
        if (tg == 0) {
            atomicAdd(&g_stats[m0],         s0);
            atomicAdd(&g_stats[TCC + m0],   q0);
            atomicAdd(&g_stats[m0 + 8],     s1);
            atomicAdd(&g_stats[TCC + m0+8], q1);
        }
    }
}

// ---------------- conv BN apply in-place on fp16 [l][c] ----------------------
__global__ void conv_bnH(__half* __restrict__ T, const float* __restrict__ g,
                         const float* __restrict__ beta, const __half* __restrict__ resid) {
    size_t idx = (size_t)blockIdx.x * blockDim.x + threadIdx.x;
    const size_t total = (size_t)Bb * LLEN * (TCC/2);
    if (idx >= total) return;
    int c2  = (int)(idx % (TCC/2));
    int l   = (int)((idx / (TCC/2)) % LLEN);
    int b   = (int)(idx / ((size_t)(TCC/2) * LLEN));
    int c   = c2 * 2;
    size_t a = ((size_t)b * LROWS + 16 + l) * TCC + c;
    const float invM = 1.f / (float)(Bb * LLEN);
    float m0 = g_stats[c] * invM;
    float va = g_stats[TCC + c] * invM - m0*m0;
    float m1 = g_stats[c+1] * invM;
    float vb = g_stats[TCC + c+1] * invM - m1*m1;
    __half2 hv = *(__half2*)(T + a);
    float2 f = __half22float2(hv);
    float o0 = (f.x - m0) * rsqrtf(va + BNEPS) * g[c]   + beta[c];
    float o1 = (f.y - m1) * rsqrtf(vb + BNEPS) * g[c+1] + beta[c+1];
    o0 = o0 > 0.f ? o0 : 0.f;
    o1 = o1 > 0.f ? o1 : 0.f;
    if (resid) {
        float2 r = __half22float2(*(const __half2*)(resid + a));
        o0 += r.x; o1 += r.y;
    }
    *(__half2*)(T + a) = __floats2half2_rn(o0, o1);
}

// ======================= output GEMM (fp16 mma, permuted A) =================
#define STGOh (ASZh + BSZh)

__global__ __launch_bounds__(256, 2) void out_gemm_f16(
        const __half* __restrict__ T2, const float* __restrict__ OB,
        float* __restrict__ OUT) {
    extern __shared__ __align__(128) char dsm[];
    const int tid = threadIdx.x;
    const int cb = blockIdx.x;
    const int bm = cb * 128;           // o
    const int bn = blockIdx.y * 128;   // s
    const int b  = blockIdx.z;
    const __half* T2b = T2 + (size_t)b * LROWS * TCC;
    const int lane = tid & 31, wid = tid >> 5;
    const int wm = (wid & 1) * 64, wn = (wid >> 1) * 32;
    const int g = lane >> 2, tg = lane & 3;
    const int aoff = (wid & 1) * 4;
    const uint32_t smem_u = s2u(dsm);

    float acc[4][4][4];
#pragma unroll
    for (int mi = 0; mi < 4; mi++)
#pragma unroll
        for (int ni = 0; ni < 4; ni++)
#pragma unroll
            for (int r = 0; r < 4; r++) acc[mi][ni][r] = 0.f;

    const int NT = TCC / 16;   // 96
    const int brow = tid >> 1, bhalf = tid & 1;

    auto load_stage = [&](int slot, int t) {
        const uint32_t sa = smem_u + slot * STGOh;
        const uint32_t sb = sa + ASZh;
        cpasync16(sa + tid * 16, g_owRH + ((size_t)t * 2 + cb) * 2048 + tid * 8);
        const __half* src = T2b + (size_t)(16 + bn + brow) * TCC + t * 16 + bhalf * 8;
        cpasync16(sb + brow * BROWB + bhalf * 16, src);
    };
    load_stage(0, 0); cpa_commit();
    load_stage(1, 1); cpa_commit();

    for (int t = 0; t < NT; ++t) {
        cpa_wait<1>();
        __syncthreads();
        if (t + 2 < NT) load_stage((t + 2) % 3, t + 2);
        cpa_commit();
        const int cur = t % 3;
        const uint4* Af = (const uint4*)(dsm + cur * STGOh);
        const char* Bs = dsm + cur * STGOh + ASZh;

        unsigned a[4][4], b[4][2];
#pragma unroll
        for (int mi = 0; mi < 4; mi++) {
            uint4 v = Af[(aoff + mi) * 32 + lane];
            a[mi][0] = v.x; a[mi][1] = v.y; a[mi][2] = v.z; a[mi][3] = v.w;
        }
#pragma unroll
        for (int ni = 0; ni < 4; ni++) {
            int row = wn + ni * 8 + g;
            b[ni][0] = *(const unsigned*)(Bs + row * BROWB + tg * 4);
            b[ni][1] = *(const unsigned*)(Bs + row * BROWB + 16 + tg * 4);
        }
#pragma unroll
        for (int mi = 0; mi < 4; mi++)
#pragma unroll
            for (int ni = 0; ni < 4; ni++)
                MMA_F16(acc[mi][ni], a[mi], b[ni]);
    }

#pragma unroll
    for (int mi = 0; mi < 4; mi++) {
        int o0 = bm + wm + mi * 16 + g;
        float bo0 = OB[o0], bo1 = OB[o0 + 8];
#pragma unroll
        for (int ni = 0; ni < 4; ni++) {
            int sL = bn + wn + ni * 8 + 2 * tg;
            float v0 = acc[mi][ni][0] + bo0; v0 = v0 > 0.f ? v0 : 0.f;
            float v1 = acc[mi][ni][1] + bo0; v1 = v1 > 0.f ? v1 : 0.f;
            float v2 = acc[mi][ni][2] + bo1; v2 = v2 > 0.f ? v2 : 0.f;
            float v3 = acc[mi][ni][3] + bo1; v3 = v3 > 0.f ? v3 : 0.f;
            OUT[((size_t)b * Ss + sL    ) * HHC + o0    ] = v0;
            OUT[((size_t)b * Ss + sL + 1) * HHC + o0    ] = v1;
            OUT[((size_t)b * Ss + sL    ) * HHC + o0 + 8] = v2;
            OUT[((size_t)b * Ss + sL + 1) * HHC + o0 + 8] = v3;
        }
    }
}

// ---------------- launch ----------------------------------------------------
extern "C" void kernel_launch(void* const* d_in, const int* in_sizes, int n_in,
                              void* d_out, int out_size) {
    const float* x     = (const float*)d_in[0];
    const float* adj   = (const float*)d_in[1];
    const float* eimp  = (const float*)d_in[2];
    const float* w1    = (const float*)d_in[3];
    const float* b1    = (const float*)d_in[4];
    const float* rw1   = (const float*)d_in[5];
    const float* rb1   = (const float*)d_in[6];
    const float* rg1   = (const float*)d_in[7];
    const float* rbeta1= (const float*)d_in[8];
    const float* g1    = (const float*)d_in[9];
    const float* beta1 = (const float*)d_in[10];
    const float* w2    = (const float*)d_in[11];
    const float* b2    = (const float*)d_in[12];
    const float* rw2   = (const float*)d_in[13];
    const float* rb2   = (const float*)d_in[14];
    const float* rg2   = (const float*)d_in[15];
    const float* rbeta2= (const float*)d_in[16];
    const float* g2    = (const float*)d_in[17];
    const float* beta2 = (const float*)d_in[18];
    const float* cw1   = (const float*)d_in[19];
    /* cb1 = d_in[20]: cancels exactly through BN mean-subtraction */
    const float* cg1   = (const float*)d_in[21];
    const float* cbeta1= (const float*)d_in[22];
    const float* cw2   = (const float*)d_in[23];
    /* cb2 = d_in[24]: cancels exactly */
    const float* cg2   = (const float*)d_in[25];
    const float* cbeta2= (const float*)d_in[26];
    const float* ow    = (const float*)d_in[27];
    const float* ob    = (const float*)d_in[28];
    float* out = (float*)d_out;

    float *p_xc1, *p_res1, *p_xc2, *p_res2;
    __half *p_htH, *p_t1H, *p_t2H, *p_wt1H, *p_wt2H;
    cudaGetSymbolAddress((void**)&p_xc1,  g_xc1);
    cudaGetSymbolAddress((void**)&p_res1, g_res1);
    cudaGetSymbolAddress((void**)&p_xc2,  g_xc2);
    cudaGetSymbolAddress((void**)&p_res2, g_res2);
    cudaGetSymbolAddress((void**)&p_htH,  g_htH);
    cudaGetSymbolAddress((void**)&p_t1H,  g_t1H);
    cudaGetSymbolAddress((void**)&p_t2H,  g_t2H);
    cudaGetSymbolAddress((void**)&p_wt1H, g_wt1H);
    cudaGetSymbolAddress((void**)&p_wt2H, g_wt2H);

    cudaFuncSetAttribute(conv_gemm_f16,
                         cudaFuncAttributeMaxDynamicSharedMemorySize, CSTAGES * STGh);
    cudaFuncSetAttribute(gcn2_gemm_tf32,
                         cudaFuncAttributeMaxDynamicSharedMemorySize, 3 * STG2);
    cudaFuncSetAttribute(out_gemm_f16,
                         cudaFuncAttributeMaxDynamicSharedMemorySize, 3 * STGOh);

    // -------- GCN stage 1 --------
    gcn1_kernel<<<NBS, 256>>>(x, adj, eimp, w1, b1, rw1, rb1);
    zero_stats_k<<<(4*TCC + 255)/256, 256>>>();
    zero_padsH<<<(Bb*32*(TCC/8) + 255)/256, 256>>>();
    pack_gcn2<<<(H1C*HHC + 255)/256, 256>>>(w2, rw2, b2, rb2);
    pack_owH<<<(TCC/16)*2, 256>>>(ow);
    stats_rows<<<1024, H1C>>>(p_xc1, p_res1, M1R, H1C);
    bn_apply1<<<(M1R*H1C)/256, 256>>>(g1, beta1, rg1, rbeta1);

    // -------- GCN stage 2 (tf32 dual GEMM) --------
    gcn2_gemm_tf32<<<dim3(M1R/128, 4), 256, 3*STG2>>>();
    nodemix2<<<NBS, 256>>>(adj, eimp);
    zero_stats_k<<<(4*TCC + 255)/256, 256>>>();
    stats_rows<<<1024, HHC>>>(p_xc2, p_res2, M1R, HHC);
    bn_apply2_tohalf<<<M1R, 256>>>(g2, beta2, rg2, rbeta2);

    // -------- TCN conv 1 (fp16 mma, round-8 6-stage pipeline) --------
    wtrans_convH2<<<96*12, 256>>>(cw1, p_wt1H);
    zero_stats_k<<<(4*TCC + 255)/256, 256>>>();
    conv_gemm_f16<<<dim3(TCC/128, LLEN/128, Bb), 256, CSTAGES*STGh>>>(p_htH, p_wt1H, p_t1H);
    conv_bnH<<<(Bb*LLEN*(TCC/2) + 255)/256, 256>>>(p_t1H, cg1, cbeta1, (const __half*)nullptr);

    // -------- TCN conv 2 + residual --------
    wtrans_convH2<<<96*12, 256>>>(cw2, p_wt2H);
    zero_stats_k<<<(4*TCC + 255)/256, 256>>>();
    conv_gemm_f16<<<dim3(TCC/128, LLEN/128, Bb), 256, CSTAGES*STGh>>>(p_t1H, p_wt2H, p_t2H);
    conv_bnH<<<(Bb*LLEN*(TCC/2) + 255)/256, 256>>>(p_t2H, cg2, cbeta2, p_htH);

    // -------- output layer (fp16 mma) --------
    out_gemm_f16<<<dim3(HHC/128, LLEN/128, Bb), 256, 3*STGOh>>>(p_t2H, ob, out);

    (void)in_sizes; (void)n_in; (void)out_size;
}

// round 12
// speedup vs baseline: 1.1998x; 1.0208x over previous
#include <cuda_runtime.h>
#include <cuda_fp16.h>
#include <math.h>
#include <stdint.h>

#define Bb 32
#define Ss 512
#define NNODE 6
#define CIN 12
#define H1C 128
#define HHC 256
#define TCC 1536
#define LLEN 512
#define LROWS 544           /* 16 pad | 512 | 16 pad rows in [l][c] layout */
#define M1R (Bb*Ss*NNODE)   /* 98304 */
#define NBS (Bb*Ss)         /* 16384 */
#define RKK (5*TCC)         /* 7680  */
#define BNEPS 1e-5f

// stat regions (disjoint, zeroed once): s1 gcn1 (4*128), s2 gcn2 (4*256),
// c1 conv1 (2*TCC), c2 conv2 (2*TCC)
#define ST1 0
#define ST2 512
#define STC1 1536
#define STC2 4608
#define STTOT 7680

// ---------------- scratch (device globals; no runtime allocation) ----------
__device__ float  g_xc1 [M1R*H1C];
__device__ float  g_res1[M1R*H1C];
__device__ float  g_h1  [M1R*H1C];     // tf32-rounded at write
__device__ float  g_y2  [M1R*HHC];
__device__ float  g_res2[M1R*HHC];
__device__ float  g_xc2 [M1R*HHC];
__device__ __half g_htH [Bb*LROWS*TCC];  // [l][c] fp16, padded rows
__device__ __half g_t1H [Bb*LROWS*TCC];
__device__ __half g_t2H [Bb*LROWS*TCC];
__device__ __half g_wt1H[RKK*TCC];       // fragment-permuted fp16 tiles
__device__ __half g_wt2H[RKK*TCC];
__device__ float  g_wB  [H1C*512];       // packed (w2T | rw2T), tf32 bits
__device__ float  g_biasP[512];
__device__ __half g_owRH[TCC*HHC];       // fragment-permuted ow fp16 tiles
__device__ float  g_stats[STTOT];

// ---------------- helpers ----------------------------------------------------
__device__ __forceinline__ unsigned f2tf32(float f) {
    unsigned u; asm("cvt.rna.tf32.f32 %0, %1;" : "=r"(u) : "f"(f)); return u;
}
#define MMA_TF32(c, a, b) \
    asm volatile("mma.sync.aligned.m16n8k8.row.col.f32.tf32.tf32.f32 " \
        "{%0,%1,%2,%3}, {%4,%5,%6,%7}, {%8,%9}, {%0,%1,%2,%3};" \
        : "+f"((c)[0]), "+f"((c)[1]), "+f"((c)[2]), "+f"((c)[3]) \
        : "r"((a)[0]), "r"((a)[1]), "r"((a)[2]), "r"((a)[3]), \
          "r"((b)[0]), "r"((b)[1]))
#define MMA_F16(c, a, b) \
    asm volatile("mma.sync.aligned.m16n8k16.row.col.f32.f16.f16.f32 " \
        "{%0,%1,%2,%3}, {%4,%5,%6,%7}, {%8,%9}, {%0,%1,%2,%3};" \
        : "+f"((c)[0]), "+f"((c)[1]), "+f"((c)[2]), "+f"((c)[3]) \
        : "r"((a)[0]), "r"((a)[1]), "r"((a)[2]), "r"((a)[3]), \
          "r"((b)[0]), "r"((b)[1]))

__device__ __forceinline__ void cpasync16(uint32_t dst, const void* src) {
    asm volatile("cp.async.cg.shared.global [%0], [%1], 16;" :: "r"(dst), "l"(src));
}
__device__ __forceinline__ void cpa_commit() {
    asm volatile("cp.async.commit_group;" ::: "memory");
}
template<int N>
__device__ __forceinline__ void cpa_wait() {
    asm volatile("cp.async.wait_group %0;" :: "n"(N) : "memory");
}
__device__ __forceinline__ uint32_t s2u(const void* p) {
    return (uint32_t)__cvta_generic_to_shared(p);
}
__device__ __forceinline__ unsigned packh2(float a, float b) {
    __half2 h = __floats2half2_rn(a, b);
    return *(unsigned*)&h;
}

// ---------------- small utility kernels ------------------------------------
__global__ void zero_stats_all() {
    int i = blockIdx.x * blockDim.x + threadIdx.x;
    if (i < STTOT) g_stats[i] = 0.f;
}

// zero pad rows (0..15, 528..543) of ht and t1 fp16 tensors
__global__ void zero_padsH() {
    int idx = blockIdx.x * blockDim.x + threadIdx.x;
    const int per = Bb * 32 * (TCC/8);
    if (idx >= per) return;
    int col8 = idx % (TCC/8);
    int rr   = (idx / (TCC/8)) % 32;
    int b    = idx / (32 * (TCC/8));
    int row  = rr < 16 ? rr : 512 + rr;
    size_t off = ((size_t)b * LROWS + row) * TCC + col8 * 8;
    uint4 z = make_uint4(0,0,0,0);
    *(uint4*)((char*)g_htH + off*2) = z;
    *(uint4*)((char*)g_t1H + off*2) = z;
}

// pack w2/rw2 into wB (tf32 bits) -- gcn2 stays tf32
__global__ void pack_gcn2(const float* __restrict__ w2, const float* __restrict__ rw2,
                          const float* __restrict__ b2, const float* __restrict__ rb2) {
    int idx = blockIdx.x * blockDim.x + threadIdx.x;
    if (idx >= H1C * HHC) return;
    int i = idx >> 8;
    int o = idx & 255;
    unsigned* wB = (unsigned*)g_wB;
    wB[i * 512 + o]       = f2tf32(w2[(size_t)o * H1C + i]);
    wB[i * 512 + 256 + o] = f2tf32(rw2[(size_t)o * H1C + i]);
    if (i == 0) { g_biasP[o] = b2[o]; g_biasP[256 + o] = rb2[o]; }
}

// ---- fp16 fragment permutation for m16n8k16 --------------------------------
// coalesced conv-weight transform: one block stages 128co x 80 floats
// (16 ci x 5 k contiguous range) in smem, emits all 5 k-tiles.
__global__ void wtrans_convH2(const float* __restrict__ cw, __half* __restrict__ wt) {
    __shared__ float sm[128 * 81];
    int blk = blockIdx.x;                 // cib*12 + cb ; cib in [0,96)
    int cib = blk / 12, cb = blk % 12;
    int ci0 = cib * 16;
    int tid = threadIdx.x;
    for (int i = tid; i < 128 * 80; i += 256) {
        int co = i / 80, j = i % 80;
        sm[co * 81 + j] = cw[((size_t)(cb * 128 + co) * TCC + ci0) * 5 + j];
    }
    __syncthreads();
#pragma unroll
    for (int k = 0; k < 5; k++) {
        int tile = (k * 96 + cib) * 12 + cb;
        unsigned* dst = (unsigned*)wt + (size_t)tile * 1024 + tid * 4;
#pragma unroll
        for (int u = 0; u < 4; u++) {
            int pos = tid * 4 + u;
            int r = pos & 3, lane = (pos >> 2) & 31, mi = pos >> 7;
            int kl = 2 * (lane & 3) + ((r >> 1) << 3);
            int ml = mi * 16 + (lane >> 2) + ((r & 1) << 3);
            float f0 = sm[ml * 81 + kl * 5 + k];
            float f1 = sm[ml * 81 + (kl + 1) * 5 + k];
            dst[u] = packh2(f0, f1);
        }
    }
}

__global__ void pack_owH(const float* __restrict__ ow) {
    int tile = blockIdx.x;                    // tk*2 + cb ; tk in [0,96)
    int tk = tile >> 1, cb = tile & 1;
    int tid = threadIdx.x;
    unsigned* dst = (unsigned*)g_owRH + (size_t)tile * 1024 + tid * 4;
#pragma unroll
    for (int u = 0; u < 4; u++) {
        int pos = tid * 4 + u;
        int r = pos & 3, lane = (pos >> 2) & 31, mi = pos >> 7;
        int kl = 2 * (lane & 3) + ((r >> 1) << 3);
        int ml = mi * 16 + (lane >> 2) + ((r & 1) << 3);
        int c = tk * 16 + kl;
        int o = cb * 128 + ml;
        float f0 = ow[(size_t)o * TCC + c];
        float f1 = ow[(size_t)o * TCC + c + 1];
        dst[u] = packh2(f0, f1);
    }
}

// ---------------- GCN stage 1 ------------------------------------------------
__global__ void gcn1_kernel(const float* __restrict__ x, const float* __restrict__ adj,
                            const float* __restrict__ eimp,
                            const float* __restrict__ w1, const float* __restrict__ b1,
                            const float* __restrict__ rw1, const float* __restrict__ rb1) {
    __shared__ float xs[NNODE*CIN];
    __shared__ float Asm[NNODE*NNODE];
    __shared__ float xts[NNODE*H1C];
    int bs = blockIdx.x;
    int tid = threadIdx.x;
    if (tid < NNODE*CIN) xs[tid] = x[(size_t)bs*NNODE*CIN + tid];
    if (tid >= 128 && tid < 128 + NNODE*NNODE) Asm[tid-128] = adj[tid-128] * eimp[tid-128];
    __syncthreads();
    for (int e = tid; e < NNODE*H1C; e += blockDim.x) {
        int n = e / H1C, c = e % H1C;
        float ws = b1[c], rs = rb1[c];
#pragma unroll
        for (int i = 0; i < CIN; i++) {
            float xv = xs[n*CIN + i];
            ws += xv * w1[c*CIN + i];
            rs += xv * rw1[c*CIN + i];
        }
        xts[e] = ws;
        g_res1[(size_t)bs*(NNODE*H1C) + e] = rs;
    }
    __syncthreads();
    for (int e = tid; e < NNODE*H1C; e += blockDim.x) {
        int n = e / H1C, c = e % H1C;
        float acc = 0.f;
#pragma unroll
        for (int m = 0; m < NNODE; m++) acc += Asm[n*NNODE + m] * xts[m*H1C + c];
        g_xc1[(size_t)bs*(NNODE*H1C) + e] = acc;
    }
}

__global__ void stats_rows(const float* __restrict__ a, const float* __restrict__ b,
                           int Mrows, int C, float* __restrict__ base) {
    int c = threadIdx.x;
    int rows_per = Mrows / gridDim.x;
    int r0 = blockIdx.x * rows_per;
    int r1 = r0 + rows_per;
    float sa = 0.f, qa = 0.f, sb = 0.f, qb = 0.f;
    for (int r = r0; r < r1; r++) {
        float v = a[(size_t)r*C + c]; sa += v; qa += v*v;
        float u = b[(size_t)r*C + c]; sb += u; qb += u*u;
    }
    atomicAdd(&base[c],       sa);
    atomicAdd(&base[C + c],   qa);
    atomicAdd(&base[2*C + c], sb);
    atomicAdd(&base[3*C + c], qb);
}

__global__ void bn_apply1(const float* __restrict__ g1, const float* __restrict__ beta1,
                          const float* __restrict__ rg1, const float* __restrict__ rbeta1) {
    size_t idx = (size_t)blockIdx.x * blockDim.x + threadIdx.x;
    if (idx >= (size_t)M1R*H1C) return;
    int c = (int)(idx % H1C);
    const float* st = g_stats + ST1;
    const float invM = 1.f / (float)M1R;
    float m1 = st[c] * invM;
    float v1 = st[H1C + c] * invM - m1*m1;
    float m2 = st[2*H1C + c] * invM;
    float v2 = st[3*H1C + c] * invM - m2*m2;
    float a = (g_xc1[idx]  - m1) * rsqrtf(v1 + BNEPS) * g1[c]  + beta1[c];
    float r = (g_res1[idx] - m2) * rsqrtf(v2 + BNEPS) * rg1[c] + rbeta1[c];
    float o = a + r;
    o = o > 0.f ? o : 0.f;
    g_h1[idx] = __uint_as_float(f2tf32(o));
}

// ---------------- gcn2 dual GEMM (tf32 mma, unchanged) ----------------------
#define A2STR 20
#define B2STR 136
#define A2SZ (128*A2STR*4)
#define B2SZ (16*B2STR*4)
#define STG2 (A2SZ + B2SZ)

__global__ __launch_bounds__(256, 2) void gcn2_gemm_tf32() {
    extern __shared__ __align__(128) char dsm[];
    const int tid = threadIdx.x;
    const int bm = blockIdx.x * 128;
    const int by = blockIdx.y;
    const int bn = by * 128;
    const int lane = tid & 31, wid = tid >> 5;
    const int wm = (wid & 1) * 64, wn = (wid >> 1) * 32;
    const int g = lane >> 2, tg = lane & 3;
    const uint32_t smem_u = s2u(dsm);
    const float* A = g_h1;

    float acc[4][4][4];
#pragma unroll
    for (int mi = 0; mi < 4; mi++)
#pragma unroll
        for (int ni = 0; ni < 4; ni++)
#pragma unroll
            for (int r = 0; r < 4; r++) acc[mi][ni][r] = 0.f;

    const int NT = H1C / 16;   // 8

    auto load_stage = [&](int slot, int t) {
        const int kk0 = t * 16;
        const uint32_t sa = smem_u + slot * STG2;
        const uint32_t sb = sa + A2SZ;
#pragma unroll
        for (int i = 0; i < 2; i++) {
            int idx = tid + i * 256;
            int m = idx >> 2, kc = (idx & 3) * 4;
            cpasync16(sa + (m * A2STR + kc) * 4,
                      A + (size_t)(bm + m) * H1C + kk0 + kc);
        }
#pragma unroll
        for (int i = 0; i < 2; i++) {
            int idx = tid + i * 256;
            int row = idx >> 5, ch = idx & 31;
            cpasync16(sb + (row * B2STR + ch * 4) * 4,
                      g_wB + (size_t)(kk0 + row) * 512 + bn + ch * 4);
        }
    };
    load_stage(0, 0); cpa_commit();
    load_stage(1, 1); cpa_commit();

    for (int t = 0; t < NT; ++t) {
        cpa_wait<1>();
        __syncthreads();
        if (t + 2 < NT) load_stage((t + 2) % 3, t + 2);
        cpa_commit();
        const int cur = t % 3;
        const float* As = (const float*)(dsm + cur * STG2);
        const float* Bs = (const float*)(dsm + cur * STG2 + A2SZ);
#pragma unroll
        for (int ks = 0; ks < 16; ks += 8) {
            unsigned a[4][4], b[4][2];
#pragma unroll
            for (int mi = 0; mi < 4; mi++) {
                int m = wm + mi * 16 + g;
                a[mi][0] = __float_as_uint(As[(m    ) * A2STR + ks + tg]);
                a[mi][1] = __float_as_uint(As[(m + 8) * A2STR + ks + tg]);
                a[mi][2] = __float_as_uint(As[(m    ) * A2STR + ks + tg + 4]);
                a[mi][3] = __float_as_uint(As[(m + 8) * A2STR + ks + tg + 4]);
            }
#pragma unroll
            for (int ni = 0; ni < 4; ni++) {
                int c = wn + ni * 8 + g;
                b[ni][0] = __float_as_uint(Bs[(ks + tg    ) * B2STR + c]);
                b[ni][1] = __float_as_uint(Bs[(ks + tg + 4) * B2STR + c]);
            }
#pragma unroll
            for (int mi = 0; mi < 4; mi++)
#pragma unroll
                for (int ni = 0; ni < 4; ni++)
                    MMA_TF32(acc[mi][ni], a[mi], b[ni]);
        }
    }

    float* tgt = (by < 2) ? g_y2 : g_res2;
    const int nb = (by & 1) * 128;
#pragma unroll
    for (int mi = 0; mi < 4; mi++) {
        int m0 = bm + wm + mi * 16 + g;
#pragma unroll
        for (int ni = 0; ni < 4; ni++) {
            int n = nb + wn + ni * 8 + 2 * tg;
            int pb = bn + wn + ni * 8 + 2 * tg;
            float b0 = g_biasP[pb], b1 = g_biasP[pb + 1];
            *(float2*)(tgt + (size_t)m0 * HHC + n)
                = make_float2(acc[mi][ni][0] + b0, acc[mi][ni][1] + b1);
            *(float2*)(tgt + (size_t)(m0 + 8) * HHC + n)
                = make_float2(acc[mi][ni][2] + b0, acc[mi][ni][3] + b1);
        }
    }
}

// ---------------- node mix for stage 2 --------------------------------------
__global__ void nodemix2(const float* __restrict__ adj, const float* __restrict__ eimp) {
    __shared__ float ys[NNODE*HHC];
    __shared__ float Asm[NNODE*NNODE];
    int bs = blockIdx.x, tid = threadIdx.x;
    if (tid < NNODE*NNODE) Asm[tid] = adj[tid] * eimp[tid];
    for (int e = tid; e < NNODE*HHC; e += blockDim.x)
        ys[e] = g_y2[(size_t)bs*NNODE*HHC + e];
    __syncthreads();
    for (int e = tid; e < NNODE*HHC; e += blockDim.x) {
        int n = e / HHC, c = e % HHC;
        float acc = 0.f;
#pragma unroll
        for (int m = 0; m < NNODE; m++) acc += Asm[n*NNODE + m] * ys[m*HHC + c];
        g_xc2[(size_t)bs*NNODE*HHC + e] = acc;
    }
}

// ---------------- BN apply stage 2 -> [l][c] fp16 ----------------------------
__global__ void bn_apply2_tohalf(const float* __restrict__ g2, const float* __restrict__ beta2,
                                 const float* __restrict__ rg2, const float* __restrict__ rbeta2) {
    int row = blockIdx.x;        // (b*Ss + s)*6 + n
    int c = threadIdx.x;         // 0..255
    const float* st = g_stats + ST2;
    const float invM = 1.f / (float)M1R;
    float m1 = st[c] * invM;
    float v1 = st[HHC + c] * invM - m1*m1;
    float m2 = st[2*HHC + c] * invM;
    float v2 = st[3*HHC + c] * invM - m2*m2;
    float sc1 = rsqrtf(v1 + BNEPS) * g2[c];
    float sh1 = beta2[c] - m1*sc1;
    float sc2 = rsqrtf(v2 + BNEPS) * rg2[c];
    float sh2 = rbeta2[c] - m2*sc2;
    size_t ridx = (size_t)row * HHC + c;
    float o = g_xc2[ridx]*sc1 + sh1 + g_res2[ridx]*sc2 + sh2;
    o = o > 0.f ? o : 0.f;
    int n = row % NNODE;
    int bs = row / NNODE;
    int b = bs / Ss, s = bs % Ss;
    g_htH[((size_t)b * LROWS + 16 + s) * TCC + n * HHC + c] = __float2half(o);
}

// ======================= conv1d fp16 mma GEMM ================================
// 8 single-tile stages, wait<6>: 6 tiles of prefetch, one tile per barrier.
#define ASZh 4096
#define BROWB 48            /* B smem row stride bytes (24 fp16) */
#define BSZh (128*BROWB)    /* 6144 */
#define STGh (ASZh + BSZh)  /* 10240 */
#define CSTAGES 8

__global__ __launch_bounds__(256, 2) void conv_gemm_f16(
        const __half* __restrict__ X, const __half* __restrict__ Wt,
        __half* __restrict__ Y, float* __restrict__ statsB) {
    extern __shared__ __align__(128) char dsm[];
    const int tid = threadIdx.x;
    const int cb = blockIdx.x;
    const int bm = cb * 128;           // co
    const int bn = blockIdx.y * 128;   // l
    const __half* Xb = X + (size_t)blockIdx.z * LROWS * TCC;
    __half* Yb = Y + (size_t)blockIdx.z * LROWS * TCC;
    const int lane = tid & 31, wid = tid >> 5;
    const int wm = (wid & 1) * 64, wn = (wid >> 1) * 32;
    const int g = lane >> 2, tg = lane & 3;
    const int aoff = (wid & 1) * 4;
    const uint32_t smem_u = s2u(dsm);

    float acc[4][4][4];
#pragma unroll
    for (int mi = 0; mi < 4; mi++)
#pragma unroll
        for (int ni = 0; ni < 4; ni++)
#pragma unroll
            for (int r = 0; r < 4; r++) acc[mi][ni][r] = 0.f;

    const int NT = RKK / 16;   // 480 = 60 * 8
    const int brow = tid >> 1, bhalf = tid & 1;

    auto load_stage = [&](int slot, int t) {
        const int kseg = t / 96;           // (t*16)/TCC
        const int ci0  = t * 16 - kseg * TCC;
        const uint32_t sa = smem_u + slot * STGh;
        const uint32_t sb = sa + ASZh;
        // A: permuted fp16 weight tile, 4KB straight copy
        cpasync16(sa + tid * 16, Wt + ((size_t)t * 12 + cb) * 2048 + tid * 8);
        // B: 128 rows x 32B from [l][c], shift baked into row base
        const __half* src = Xb + (size_t)(16 + bn + kseg - 2 + brow) * TCC
                              + ci0 + bhalf * 8;
        cpasync16(sb + brow * BROWB + bhalf * 16, src);
    };

    load_stage(0, 0); cpa_commit();
    load_stage(1, 1); cpa_commit();
    load_stage(2, 2); cpa_commit();
    load_stage(3, 3); cpa_commit();
    load_stage(4, 4); cpa_commit();
    load_stage(5, 5); cpa_commit();
    load_stage(6, 6); cpa_commit();

    for (int tb = 0; tb < NT; tb += CSTAGES) {
#pragma unroll
        for (int s = 0; s < CSTAGES; s++) {
            const int t = tb + s;
            cpa_wait<CSTAGES - 2>();
            __syncthreads();
            if (t + 7 < NT) load_stage((s + 7) & 7, t + 7);
            cpa_commit();

            const uint4* Af = (const uint4*)(dsm + s * STGh);
            const char* Bs = dsm + s * STGh + ASZh;

            unsigned a[4][4], b[4][2];
#pragma unroll
            for (int mi = 0; mi < 4; mi++) {
                uint4 v = Af[(aoff + mi) * 32 + lane];
                a[mi][0] = v.x; a[mi][1] = v.y; a[mi][2] = v.z; a[mi][3] = v.w;
            }
#pragma unroll
            for (int ni = 0; ni < 4; ni++) {
                int row = wn + ni * 8 + g;
                b[ni][0] = *(const unsigned*)(Bs + row * BROWB + tg * 4);
                b[ni][1] = *(const unsigned*)(Bs + row * BROWB + 16 + tg * 4);
            }
#pragma unroll
            for (int mi = 0; mi < 4; mi++)
#pragma unroll
                for (int ni = 0; ni < 4; ni++)
                    MMA_F16(acc[mi][ni], a[mi], b[ni]);
        }
    }

    // epilogue: store fp16 [l][c] + fused per-channel stats from fp32 accs
#pragma unroll
    for (int mi = 0; mi < 4; mi++) {
        int m0 = bm + wm + mi * 16 + g;
        float s0 = 0.f, q0 = 0.f, s1 = 0.f, q1 = 0.f;
#pragma unroll
        for (int ni = 0; ni < 4; ni++) {
            float v0 = acc[mi][ni][0], v1 = acc[mi][ni][1];
            float v2 = acc[mi][ni][2], v3 = acc[mi][ni][3];
            s0 += v0 + v1; q0 += v0*v0 + v1*v1;
            s1 += v2 + v3; q1 += v2*v2 + v3*v3;
            int l0 = bn + wn + ni * 8 + 2 * tg;
            size_t r0 = ((size_t)(16 + l0)) * TCC;
            size_t r1 = ((size_t)(17 + l0)) * TCC;
            Yb[r0 + m0]     = __float2half(v0);
            Yb[r1 + m0]     = __float2half(v1);
            Yb[r0 + m0 + 8] = __float2half(v2);
            Yb[r1 + m0 + 8] = __float2half(v3);
        }
        s0 += __shfl_xor_sync(0xffffffffu, s0, 1);
        s0 += __shfl_xor_sync(0xffffffffu, s0, 2);
        q0 += __shfl_xor_sync(0xffffffffu, q0, 1);
        q0 += __shfl_xor_sync(0xffffffffu, q0, 2);
        s1 += __shfl_xor_sync(0xffffffffu, s1, 1);
        s1 += __shfl_xor_sync(0xffffffffu, s1, 2);
        q1 += __shfl_xor_sync(0xffffffffu, q1, 1);
        q1 += __shfl_xor_sync(0xffffffffu, q1, 2);
        if (tg == 0) {
            atomicAdd(&statsB[m0],         s0);
            atomicAdd(&statsB[TCC + m0],   q0);
            atomicAdd(&statsB[m0 + 8],     s1);
            atomicAdd(&statsB[TCC + m0+8], q1);
        }
    }
}

// ---------------- conv BN apply in-place on fp16 [l][c] ----------------------
__global__ void conv_bnH(__half* __restrict__ T, const float* __restrict__ g,
                         const float* __restrict__ beta, const __half* __restrict__ resid,
                         const float* __restrict__ statsB) {
    size_t idx = (size_t)blockIdx.x * blockDim.x + threadIdx.x;
    const size_t total = (size_t)Bb * LLEN * (TCC/2);
    if (idx >= total) return;
    int c2  = (int)(idx % (TCC/2));
    int l   = (int)((idx / (TCC/2)) % LLEN);
    int b   = (int)(idx / ((size_t)(TCC/2) * LLEN));
    int c   = c2 * 2;
    size_t a = ((size_t)b * LROWS + 16 + l) * TCC + c;
    const float invM = 1.f / (float)(Bb * LLEN);
    float m0 = statsB[c] * invM;
    float va = statsB[TCC + c] * invM - m0*m0;
    float m1 = statsB[c+1] * invM;
    float vb = statsB[TCC + c+1] * invM - m1*m1;
    __half2 hv = *(__half2*)(T + a);
    float2 f = __half22float2(hv);
    float o0 = (f.x - m0) * rsqrtf(va + BNEPS) * g[c]   + beta[c];
    float o1 = (f.y - m1) * rsqrtf(vb + BNEPS) * g[c+1] + beta[c+1];
    o0 = o0 > 0.f ? o0 : 0.f;
    o1 = o1 > 0.f ? o1 : 0.f;
    if (resid) {
        float2 r = __half22float2(*(const __half2*)(resid + a));
        o0 += r.x; o1 += r.y;
    }
    *(__half2*)(T + a) = __floats2half2_rn(o0, o1);
}

// ======================= output GEMM (fp16 mma, permuted A) =================
#define STGOh (ASZh + BSZh)

__global__ __launch_bounds__(256, 2) void out_gemm_f16(
        const __half* __restrict__ T2, const float* __restrict__ OB,
        float* __restrict__ OUT) {
    extern __shared__ __align__(128) char dsm[];
    const int tid = threadIdx.x;
    const int cb = blockIdx.x;
    const int bm = cb * 128;           // o
    const int bn = blockIdx.y * 128;   // s
    const int b  = blockIdx.z;
    const __half* T2b = T2 + (size_t)b * LROWS * TCC;
    const int lane = tid & 31, wid = tid >> 5;
    const int wm = (wid & 1) * 64, wn = (wid >> 1) * 32;
    const int g = lane >> 2, tg = lane & 3;
    const int aoff = (wid & 1) * 4;
    const uint32_t smem_u = s2u(dsm);

    float acc[4][4][4];
#pragma unroll
    for (int mi = 0; mi < 4; mi++)
#pragma unroll
        for (int ni = 0; ni < 4; ni++)
#pragma unroll
            for (int r = 0; r < 4; r++) acc[mi][ni][r] = 0.f;

    const int NT = TCC / 16;   // 96
    const int brow = tid >> 1, bhalf = tid & 1;

    auto load_stage = [&](int slot, int t) {
        const uint32_t sa = smem_u + slot * STGOh;
        const uint32_t sb = sa + ASZh;
        cpasync16(sa + tid * 16, g_owRH + ((size_t)t * 2 + cb) * 2048 + tid * 8);
        const __half* src = T2b + (size_t)(16 + bn + brow) * TCC + t * 16 + bhalf * 8;
        cpasync16(sb + brow * BROWB + bhalf * 16, src);
    };
    load_stage(0, 0); cpa_commit();
    load_stage(1, 1); cpa_commit();

    for (int t = 0; t < NT; ++t) {
        cpa_wait<1>();
        __syncthreads();
        if (t + 2 < NT) load_stage((t + 2) % 3, t + 2);
        cpa_commit();
        const int cur = t % 3;
        const uint4* Af = (const uint4*)(dsm + cur * STGOh);
        const char* Bs = dsm + cur * STGOh + ASZh;

        unsigned a[4][4], b[4][2];
#pragma unroll
        for (int mi = 0; mi < 4; mi++) {
            uint4 v = Af[(aoff + mi) * 32 + lane];
            a[mi][0] = v.x; a[mi][1] = v.y; a[mi][2] = v.z; a[mi][3] = v.w;
        }
#pragma unroll
        for (int ni = 0; ni < 4; ni++) {
            int row = wn + ni * 8 + g;
            b[ni][0] = *(const unsigned*)(Bs + row * BROWB + tg * 4);
            b[ni][1] = *(const unsigned*)(Bs + row * BROWB + 16 + tg * 4);
        }
#pragma unroll
        for (int mi = 0; mi < 4; mi++)
#pragma unroll
            for (int ni = 0; ni < 4; ni++)
                MMA_F16(acc[mi][ni], a[mi], b[ni]);
    }

#pragma unroll
    for (int mi = 0; mi < 4; mi++) {
        int o0 = bm + wm + mi * 16 + g;
        float bo0 = OB[o0], bo1 = OB[o0 + 8];
#pragma unroll
        for (int ni = 0; ni < 4; ni++) {
            int sL = bn + wn + ni * 8 + 2 * tg;
            float v0 = acc[mi][ni][0] + bo0; v0 = v0 > 0.f ? v0 : 0.f;
            float v1 = acc[mi][ni][1] + bo0; v1 = v1 > 0.f ? v1 : 0.f;
            float v2 = acc[mi][ni][2] + bo1; v2 = v2 > 0.f ? v2 : 0.f;
            float v3 = acc[mi][ni][3] + bo1; v3 = v3 > 0.f ? v3 : 0.f;
            OUT[((size_t)b * Ss + sL    ) * HHC + o0    ] = v0;
            OUT[((size_t)b * Ss + sL + 1) * HHC + o0    ] = v1;
            OUT[((size_t)b * Ss + sL    ) * HHC + o0 + 8] = v2;
            OUT[((size_t)b * Ss + sL + 1) * HHC + o0 + 8] = v3;
        }
    }
}

// ---------------- launch ----------------------------------------------------
extern "C" void kernel_launch(void* const* d_in, const int* in_sizes, int n_in,
                              void* d_out, int out_size) {
    const float* x     = (const float*)d_in[0];
    const float* adj   = (const float*)d_in[1];
    const float* eimp  = (const float*)d_in[2];
    const float* w1    = (const float*)d_in[3];
    const float* b1    = (const float*)d_in[4];
    const float* rw1   = (const float*)d_in[5];
    const float* rb1   = (const float*)d_in[6];
    const float* rg1   = (const float*)d_in[7];
    const float* rbeta1= (const float*)d_in[8];
    const float* g1    = (const float*)d_in[9];
    const float* beta1 = (const float*)d_in[10];
    const float* w2    = (const float*)d_in[11];
    const float* b2    = (const float*)d_in[12];
    const float* rw2   = (const float*)d_in[13];
    const float* rb2   = (const float*)d_in[14];
    const float* rg2   = (const float*)d_in[15];
    const float* rbeta2= (const float*)d_in[16];
    const float* g2    = (const float*)d_in[17];
    const float* beta2 = (const float*)d_in[18];
    const float* cw1   = (const float*)d_in[19];
    /* cb1 = d_in[20]: cancels exactly through BN mean-subtraction */
    const float* cg1   = (const float*)d_in[21];
    const float* cbeta1= (const float*)d_in[22];
    const float* cw2   = (const float*)d_in[23];
    /* cb2 = d_in[24]: cancels exactly */
    const float* cg2   = (const float*)d_in[25];
    const float* cbeta2= (const float*)d_in[26];
    const float* ow    = (const float*)d_in[27];
    const float* ob    = (const float*)d_in[28];
    float* out = (float*)d_out;

    float *p_xc1, *p_res1, *p_xc2, *p_res2, *p_stats;
    __half *p_htH, *p_t1H, *p_t2H, *p_wt1H, *p_wt2H;
    cudaGetSymbolAddress((void**)&p_xc1,  g_xc1);
    cudaGetSymbolAddress((void**)&p_res1, g_res1);
    cudaGetSymbolAddress((void**)&p_xc2,  g_xc2);
    cudaGetSymbolAddress((void**)&p_res2, g_res2);
    cudaGetSymbolAddress((void**)&p_stats, g_stats);
    cudaGetSymbolAddress((void**)&p_htH,  g_htH);
    cudaGetSymbolAddress((void**)&p_t1H,  g_t1H);
    cudaGetSymbolAddress((void**)&p_t2H,  g_t2H);
    cudaGetSymbolAddress((void**)&p_wt1H, g_wt1H);
    cudaGetSymbolAddress((void**)&p_wt2H, g_wt2H);

    cudaFuncSetAttribute(conv_gemm_f16,
                         cudaFuncAttributeMaxDynamicSharedMemorySize, CSTAGES * STGh);
    cudaFuncSetAttribute(gcn2_gemm_tf32,
                         cudaFuncAttributeMaxDynamicSharedMemorySize, 3 * STG2);
    cudaFuncSetAttribute(out_gemm_f16,
                         cudaFuncAttributeMaxDynamicSharedMemorySize, 3 * STGOh);

    // -------- prep: zero all 4 stat regions once + pads + weight packs ------
    zero_stats_all<<<(STTOT + 255)/256, 256>>>();
    zero_padsH<<<(Bb*32*(TCC/8) + 255)/256, 256>>>();
    pack_gcn2<<<(H1C*HHC + 255)/256, 256>>>(w2, rw2, b2, rb2);
    pack_owH<<<(TCC/16)*2, 256>>>(ow);
    wtrans_convH2<<<96*12, 256>>>(cw1, p_wt1H);
    wtrans_convH2<<<96*12, 256>>>(cw2, p_wt2H);

    // -------- GCN stage 1 --------
    gcn1_kernel<<<NBS, 256>>>(x, adj, eimp, w1, b1, rw1, rb1);
    stats_rows<<<1024, H1C>>>(p_xc1, p_res1, M1R, H1C, p_stats + ST1);
    bn_apply1<<<(M1R*H1C)/256, 256>>>(g1, beta1, rg1, rbeta1);

    // -------- GCN stage 2 (tf32 dual GEMM) --------
    gcn2_gemm_tf32<<<dim3(M1R/128, 4), 256, 3*STG2>>>();
    nodemix2<<<NBS, 256>>>(adj, eimp);
    stats_rows<<<1024, HHC>>>(p_xc2, p_res2, M1R, HHC, p_stats + ST2);
    bn_apply2_tohalf<<<M1R, 256>>>(g2, beta2, rg2, rbeta2);

    // -------- TCN conv 1 (fp16 mma, 8-stage pipeline) --------
    conv_gemm_f16<<<dim3(TCC/128, LLEN/128, Bb), 256, CSTAGES*STGh>>>(
        p_htH, p_wt1H, p_t1H, p_stats + STC1);
    conv_bnH<<<(Bb*LLEN*(TCC/2) + 255)/256, 256>>>(
        p_t1H, cg1, cbeta1, (const __half*)nullptr, p_stats + STC1);

    // -------- TCN conv 2 + residual --------
    conv_gemm_f16<<<dim3(TCC/128, LLEN/128, Bb), 256, CSTAGES*STGh>>>(
        p_t1H, p_wt2H, p_t2H, p_stats + STC2);
    conv_bnH<<<(Bb*LLEN*(TCC/2) + 255)/256, 256>>>(
        p_t2H, cg2, cbeta2, p_htH, p_stats + STC2);

    // -------- output layer (fp16 mma) --------
    out_gemm_f16<<<dim3(HHC/128, LLEN/128, Bb), 256, 3*STGOh>>>(p_t2H, ob, out);

    (void)in_sizes; (void)n_in; (void)out_size;
}

// round 13
// speedup vs baseline: 1.2592x; 1.0495x over previous
#include <cuda_runtime.h>
#include <cuda_fp16.h>
#include <math.h>
#include <stdint.h>

#define Bb 32
#define Ss 512
#define NNODE 6
#define CIN 12
#define H1C 128
#define HHC 256
#define TCC 1536
#define LLEN 512
#define LROWS 544           /* 16 pad | 512 | 16 pad rows in [l][c] layout */
#define M1R (Bb*Ss*NNODE)   /* 98304 */
#define NBS (Bb*Ss)         /* 16384 */
#define RKK (5*TCC)         /* 7680  */
#define BNEPS 1e-5f

// stat regions (disjoint, zeroed once)
#define ST1 0
#define ST2 512
#define STC1 1536
#define STC2 4608
#define STTOT 7680

// ---------------- scratch (device globals; no runtime allocation) ----------
__device__ float  g_xc1 [M1R*H1C];
__device__ float  g_res1[M1R*H1C];
__device__ float  g_h1  [M1R*H1C];     // tf32-rounded at write
__device__ float  g_y2  [M1R*HHC];
__device__ float  g_res2[M1R*HHC];
__device__ float  g_xc2 [M1R*HHC];
__device__ __half g_htH [Bb*LROWS*TCC];  // [l][c] fp16, padded rows
__device__ __half g_t1H [Bb*LROWS*TCC];
__device__ __half g_t2H [Bb*LROWS*TCC];
__device__ __half g_wt1H[RKK*TCC];       // fragment-permuted fp16 tiles
__device__ __half g_wt2H[RKK*TCC];
__device__ float  g_wB  [H1C*512];       // packed (w2T | rw2T), tf32 bits
__device__ float  g_biasP[512];
__device__ __half g_owRH[TCC*HHC];       // fragment-permuted ow fp16 tiles
__device__ float  g_stats[STTOT];

// ---------------- helpers ----------------------------------------------------
__device__ __forceinline__ unsigned f2tf32(float f) {
    unsigned u; asm("cvt.rna.tf32.f32 %0, %1;" : "=r"(u) : "f"(f)); return u;
}
#define MMA_TF32(c, a, b) \
    asm volatile("mma.sync.aligned.m16n8k8.row.col.f32.tf32.tf32.f32 " \
        "{%0,%1,%2,%3}, {%4,%5,%6,%7}, {%8,%9}, {%0,%1,%2,%3};" \
        : "+f"((c)[0]), "+f"((c)[1]), "+f"((c)[2]), "+f"((c)[3]) \
        : "r"((a)[0]), "r"((a)[1]), "r"((a)[2]), "r"((a)[3]), \
          "r"((b)[0]), "r"((b)[1]))
#define MMA_F16(c, a, b) \
    asm volatile("mma.sync.aligned.m16n8k16.row.col.f32.f16.f16.f32 " \
        "{%0,%1,%2,%3}, {%4,%5,%6,%7}, {%8,%9}, {%0,%1,%2,%3};" \
        : "+f"((c)[0]), "+f"((c)[1]), "+f"((c)[2]), "+f"((c)[3]) \
        : "r"((a)[0]), "r"((a)[1]), "r"((a)[2]), "r"((a)[3]), \
          "r"((b)[0]), "r"((b)[1]))

__device__ __forceinline__ void cpasync16(uint32_t dst, const void* src) {
    asm volatile("cp.async.cg.shared.global [%0], [%1], 16;" :: "r"(dst), "l"(src));
}
__device__ __forceinline__ void cpa_commit() {
    asm volatile("cp.async.commit_group;" ::: "memory");
}
template<int N>
__device__ __forceinline__ void cpa_wait() {
    asm volatile("cp.async.wait_group %0;" :: "n"(N) : "memory");
}
__device__ __forceinline__ uint32_t s2u(const void* p) {
    return (uint32_t)__cvta_generic_to_shared(p);
}
__device__ __forceinline__ unsigned packh2(float a, float b) {
    __half2 h = __floats2half2_rn(a, b);
    return *(unsigned*)&h;
}

// ---------------- small utility kernels ------------------------------------
__global__ void zero_stats_all() {
    int i = blockIdx.x * blockDim.x + threadIdx.x;
    if (i < STTOT) g_stats[i] = 0.f;
}

__global__ void zero_padsH() {
    int idx = blockIdx.x * blockDim.x + threadIdx.x;
    const int per = Bb * 32 * (TCC/8);
    if (idx >= per) return;
    int col8 = idx % (TCC/8);
    int rr   = (idx / (TCC/8)) % 32;
    int b    = idx / (32 * (TCC/8));
    int row  = rr < 16 ? rr : 512 + rr;
    size_t off = ((size_t)b * LROWS + row) * TCC + col8 * 8;
    uint4 z = make_uint4(0,0,0,0);
    *(uint4*)((char*)g_htH + off*2) = z;
    *(uint4*)((char*)g_t1H + off*2) = z;
}

__global__ void pack_gcn2(const float* __restrict__ w2, const float* __restrict__ rw2,
                          const float* __restrict__ b2, const float* __restrict__ rb2) {
    int idx = blockIdx.x * blockDim.x + threadIdx.x;
    if (idx >= H1C * HHC) return;
    int i = idx >> 8;
    int o = idx & 255;
    unsigned* wB = (unsigned*)g_wB;
    wB[i * 512 + o]       = f2tf32(w2[(size_t)o * H1C + i]);
    wB[i * 512 + 256 + o] = f2tf32(rw2[(size_t)o * H1C + i]);
    if (i == 0) { g_biasP[o] = b2[o]; g_biasP[256 + o] = rb2[o]; }
}

// coalesced conv-weight transform -> fragment-permuted fp16 tiles
__global__ void wtrans_convH2(const float* __restrict__ cw, __half* __restrict__ wt) {
    __shared__ float sm[128 * 81];
    int blk = blockIdx.x;                 // cib*12 + cb ; cib in [0,96)
    int cib = blk / 12, cb = blk % 12;
    int ci0 = cib * 16;
    int tid = threadIdx.x;
    for (int i = tid; i < 128 * 80; i += 256) {
        int co = i / 80, j = i % 80;
        sm[co * 81 + j] = cw[((size_t)(cb * 128 + co) * TCC + ci0) * 5 + j];
    }
    __syncthreads();
#pragma unroll
    for (int k = 0; k < 5; k++) {
        int tile = (k * 96 + cib) * 12 + cb;
        unsigned* dst = (unsigned*)wt + (size_t)tile * 1024 + tid * 4;
#pragma unroll
        for (int u = 0; u < 4; u++) {
            int pos = tid * 4 + u;
            int r = pos & 3, lane = (pos >> 2) & 31, mi = pos >> 7;
            int kl = 2 * (lane & 3) + ((r >> 1) << 3);
            int ml = mi * 16 + (lane >> 2) + ((r & 1) << 3);
            float f0 = sm[ml * 81 + kl * 5 + k];
            float f1 = sm[ml * 81 + (kl + 1) * 5 + k];
            dst[u] = packh2(f0, f1);
        }
    }
}

__global__ void pack_owH(const float* __restrict__ ow) {
    int tile = blockIdx.x;                    // tk*2 + cb ; tk in [0,96)
    int tk = tile >> 1, cb = tile & 1;
    int tid = threadIdx.x;
    unsigned* dst = (unsigned*)g_owRH + (size_t)tile * 1024 + tid * 4;
#pragma unroll
    for (int u = 0; u < 4; u++) {
        int pos = tid * 4 + u;
        int r = pos & 3, lane = (pos >> 2) & 31, mi = pos >> 7;
        int kl = 2 * (lane & 3) + ((r >> 1) << 3);
        int ml = mi * 16 + (lane >> 2) + ((r & 1) << 3);
        int c = tk * 16 + kl;
        int o = cb * 128 + ml;
        float f0 = ow[(size_t)o * TCC + c];
        float f1 = ow[(size_t)o * TCC + c + 1];
        dst[u] = packh2(f0, f1);
    }
}

// ---------------- GCN stage 1 ------------------------------------------------
__global__ void gcn1_kernel(const float* __restrict__ x, const float* __restrict__ adj,
                            const float* __restrict__ eimp,
                            const float* __restrict__ w1, const float* __restrict__ b1,
                            const float* __restrict__ rw1, const float* __restrict__ rb1) {
    __shared__ float xs[NNODE*CIN];
    __shared__ float Asm[NNODE*NNODE];
    __shared__ float xts[NNODE*H1C];
    int bs = blockIdx.x;
    int tid = threadIdx.x;
    if (tid < NNODE*CIN) xs[tid] = x[(size_t)bs*NNODE*CIN + tid];
    if (tid >= 128 && tid < 128 + NNODE*NNODE) Asm[tid-128] = adj[tid-128] * eimp[tid-128];
    __syncthreads();
    for (int e = tid; e < NNODE*H1C; e += blockDim.x) {
        int n = e / H1C, c = e % H1C;
        float ws = b1[c], rs = rb1[c];
#pragma unroll
        for (int i = 0; i < CIN; i++) {
            float xv = xs[n*CIN + i];
            ws += xv * w1[c*CIN + i];
            rs += xv * rw1[c*CIN + i];
        }
        xts[e] = ws;
        g_res1[(size_t)bs*(NNODE*H1C) + e] = rs;
    }
    __syncthreads();
    for (int e = tid; e < NNODE*H1C; e += blockDim.x) {
        int n = e / H1C, c = e % H1C;
        float acc = 0.f;
#pragma unroll
        for (int m = 0; m < NNODE; m++) acc += Asm[n*NNODE + m] * xts[m*H1C + c];
        g_xc1[(size_t)bs*(NNODE*H1C) + e] = acc;
    }
}

__global__ void stats_rows(const float* __restrict__ a, const float* __restrict__ b,
                           int Mrows, int C, float* __restrict__ base) {
    int c = threadIdx.x;
    int rows_per = Mrows / gridDim.x;
    int r0 = blockIdx.x * rows_per;
    int r1 = r0 + rows_per;
    float sa = 0.f, qa = 0.f, sb = 0.f, qb = 0.f;
    for (int r = r0; r < r1; r++) {
        float v = a[(size_t)r*C + c]; sa += v; qa += v*v;
        float u = b[(size_t)r*C + c]; sb += u; qb += u*u;
    }
    atomicAdd(&base[c],       sa);
    atomicAdd(&base[C + c],   qa);
    atomicAdd(&base[2*C + c], sb);
    atomicAdd(&base[3*C + c], qb);
}

__global__ void bn_apply1(const float* __restrict__ g1, const float* __restrict__ beta1,
                          const float* __restrict__ rg1, const float* __restrict__ rbeta1) {
    size_t idx = (size_t)blockIdx.x * blockDim.x + threadIdx.x;
    if (idx >= (size_t)M1R*H1C) return;
    int c = (int)(idx % H1C);
    const float* st = g_stats + ST1;
    const float invM = 1.f / (float)M1R;
    float m1 = st[c] * invM;
    float v1 = st[H1C + c] * invM - m1*m1;
    float m2 = st[2*H1C + c] * invM;
    float v2 = st[3*H1C + c] * invM - m2*m2;
    float a = (g_xc1[idx]  - m1) * rsqrtf(v1 + BNEPS) * g1[c]  + beta1[c];
    float r = (g_res1[idx] - m2) * rsqrtf(v2 + BNEPS) * rg1[c] + rbeta1[c];
    float o = a + r;
    o = o > 0.f ? o : 0.f;
    g_h1[idx] = __uint_as_float(f2tf32(o));
}

// ---------------- gcn2 dual GEMM (tf32 mma, unchanged) ----------------------
#define A2STR 20
#define B2STR 136
#define A2SZ (128*A2STR*4)
#define B2SZ (16*B2STR*4)
#define STG2 (A2SZ + B2SZ)

__global__ __launch_bounds__(256, 2) void gcn2_gemm_tf32() {
    extern __shared__ __align__(128) char dsm[];
    const int tid = threadIdx.x;
    const int bm = blockIdx.x * 128;
    const int by = blockIdx.y;
    const int bn = by * 128;
    const int lane = tid & 31, wid = tid >> 5;
    const int wm = (wid & 1) * 64, wn = (wid >> 1) * 32;
    const int g = lane >> 2, tg = lane & 3;
    const uint32_t smem_u = s2u(dsm);
    const float* A = g_h1;

    float acc[4][4][4];
#pragma unroll
    for (int mi = 0; mi < 4; mi++)
#pragma unroll
        for (int ni = 0; ni < 4; ni++)
#pragma unroll
            for (int r = 0; r < 4; r++) acc[mi][ni][r] = 0.f;

    const int NT = H1C / 16;   // 8

    auto load_stage = [&](int slot, int t) {
        const int kk0 = t * 16;
        const uint32_t sa = smem_u + slot * STG2;
        const uint32_t sb = sa + A2SZ;
#pragma unroll
        for (int i = 0; i < 2; i++) {
            int idx = tid + i * 256;
            int m = idx >> 2, kc = (idx & 3) * 4;
            cpasync16(sa + (m * A2STR + kc) * 4,
                      A + (size_t)(bm + m) * H1C + kk0 + kc);
        }
#pragma unroll
        for (int i = 0; i < 2; i++) {
            int idx = tid + i * 256;
            int row = idx >> 5, ch = idx & 31;
            cpasync16(sb + (row * B2STR + ch * 4) * 4,
                      g_wB + (size_t)(kk0 + row) * 512 + bn + ch * 4);
        }
    };
    load_stage(0, 0); cpa_commit();
    load_stage(1, 1); cpa_commit();

    for (int t = 0; t < NT; ++t) {
        cpa_wait<1>();
        __syncthreads();
        if (t + 2 < NT) load_stage((t + 2) % 3, t + 2);
        cpa_commit();
        const int cur = t % 3;
        const float* As = (const float*)(dsm + cur * STG2);
        const float* Bs = (const float*)(dsm + cur * STG2 + A2SZ);
#pragma unroll
        for (int ks = 0; ks < 16; ks += 8) {
            unsigned a[4][4], b[4][2];
#pragma unroll
            for (int mi = 0; mi < 4; mi++) {
                int m = wm + mi * 16 + g;
                a[mi][0] = __float_as_uint(As[(m    ) * A2STR + ks + tg]);
                a[mi][1] = __float_as_uint(As[(m + 8) * A2STR + ks + tg]);
                a[mi][2] = __float_as_uint(As[(m    ) * A2STR + ks + tg + 4]);
                a[mi][3] = __float_as_uint(As[(m + 8) * A2STR + ks + tg + 4]);
            }
#pragma unroll
            for (int ni = 0; ni < 4; ni++) {
                int c = wn + ni * 8 + g;
                b[ni][0] = __float_as_uint(Bs[(ks + tg    ) * B2STR + c]);
                b[ni][1] = __float_as_uint(Bs[(ks + tg + 4) * B2STR + c]);
            }
#pragma unroll
            for (int mi = 0; mi < 4; mi++)
#pragma unroll
                for (int ni = 0; ni < 4; ni++)
                    MMA_TF32(acc[mi][ni], a[mi], b[ni]);
        }
    }

    float* tgt = (by < 2) ? g_y2 : g_res2;
    const int nb = (by & 1) * 128;
#pragma unroll
    for (int mi = 0; mi < 4; mi++) {
        int m0 = bm + wm + mi * 16 + g;
#pragma unroll
        for (int ni = 0; ni < 4; ni++) {
            int n = nb + wn + ni * 8 + 2 * tg;
            int pb = bn + wn + ni * 8 + 2 * tg;
            float b0 = g_biasP[pb], b1 = g_biasP[pb + 1];
            *(float2*)(tgt + (size_t)m0 * HHC + n)
                = make_float2(acc[mi][ni][0] + b0, acc[mi][ni][1] + b1);
            *(float2*)(tgt + (size_t)(m0 + 8) * HHC + n)
                = make_float2(acc[mi][ni][2] + b0, acc[mi][ni][3] + b1);
        }
    }
}

// ---------------- node mix for stage 2 --------------------------------------
__global__ void nodemix2(const float* __restrict__ adj, const float* __restrict__ eimp) {
    __shared__ float ys[NNODE*HHC];
    __shared__ float Asm[NNODE*NNODE];
    int bs = blockIdx.x, tid = threadIdx.x;
    if (tid < NNODE*NNODE) Asm[tid] = adj[tid] * eimp[tid];
    for (int e = tid; e < NNODE*HHC; e += blockDim.x)
        ys[e] = g_y2[(size_t)bs*NNODE*HHC + e];
    __syncthreads();
    for (int e = tid; e < NNODE*HHC; e += blockDim.x) {
        int n = e / HHC, c = e % HHC;
        float acc = 0.f;
#pragma unroll
        for (int m = 0; m < NNODE; m++) acc += Asm[n*NNODE + m] * ys[m*HHC + c];
        g_xc2[(size_t)bs*NNODE*HHC + e] = acc;
    }
}

// ---------------- BN apply stage 2 -> [l][c] fp16 ----------------------------
__global__ void bn_apply2_tohalf(const float* __restrict__ g2, const float* __restrict__ beta2,
                                 const float* __restrict__ rg2, const float* __restrict__ rbeta2) {
    int row = blockIdx.x;        // (b*Ss + s)*6 + n
    int c = threadIdx.x;         // 0..255
    const float* st = g_stats + ST2;
    const float invM = 1.f / (float)M1R;
    float m1 = st[c] * invM;
    float v1 = st[HHC + c] * invM - m1*m1;
    float m2 = st[2*HHC + c] * invM;
    float v2 = st[3*HHC + c] * invM - m2*m2;
    float sc1 = rsqrtf(v1 + BNEPS) * g2[c];
    float sh1 = beta2[c] - m1*sc1;
    float sc2 = rsqrtf(v2 + BNEPS) * rg2[c];
    float sh2 = rbeta2[c] - m2*sc2;
    size_t ridx = (size_t)row * HHC + c;
    float o = g_xc2[ridx]*sc1 + sh1 + g_res2[ridx]*sc2 + sh2;
    o = o > 0.f ? o : 0.f;
    int n = row % NNODE;
    int bs = row / NNODE;
    int b = bs / Ss, s = bs % Ss;
    g_htH[((size_t)b * LROWS + 16 + s) * TCC + n * HHC + c] = __float2half(o);
}

// ======================= conv1d fp16 mma GEMM, ci-tiled ======================
// Per stage: one 16-ci X block (132 rows, loaded ONCE) + all 5 weight tap
// tiles; 5 taps' MMAs run from the same smem B with row offsets 0..4.
// B L2 traffic /5, barriers /5 vs kk-tiled version.
#define A5SZ 20480          /* 5 x 4096 weight tap tiles */
#define BROWB2 48           /* B smem row stride bytes */
#define BROWS2 132          /* 128 + 4 halo rows */
#define STG3 26880          /* A5SZ + 132*48 = 26816, padded to 128 */
#define CST3 3

__global__ __launch_bounds__(256, 2) void conv_gemm_f16(
        const __half* __restrict__ X, const __half* __restrict__ Wt,
        __half* __restrict__ Y, float* __restrict__ statsB) {
    extern __shared__ __align__(128) char dsm[];
    const int tid = threadIdx.x;
    const int cb = blockIdx.x;
    const int bm = cb * 128;           // co
    const int bn = blockIdx.y * 128;   // l
    const __half* Xb = X + (size_t)blockIdx.z * LROWS * TCC;
    __half* Yb = Y + (size_t)blockIdx.z * LROWS * TCC;
    const int lane = tid & 31, wid = tid >> 5;
    const int wm = (wid & 1) * 64, wn = (wid >> 1) * 32;
    const int g = lane >> 2, tg = lane & 3;
    const int aoff = (wid & 1) * 4;
    const uint32_t smem_u = s2u(dsm);

    float acc[4][4][4];
#pragma unroll
    for (int mi = 0; mi < 4; mi++)
#pragma unroll
        for (int ni = 0; ni < 4; ni++)
#pragma unroll
            for (int r = 0; r < 4; r++) acc[mi][ni][r] = 0.f;

    const int NTC = TCC / 16;   // 96 ci-tiles

    auto load_stage = [&](int slot, int it) {
        const int ci0 = it * 16;
        const uint32_t sa = smem_u + slot * STG3;
        const uint32_t sb = sa + A5SZ;
        // A: 5 fragment-permuted weight tap tiles (4KB each)
#pragma unroll
        for (int k = 0; k < 5; k++)
            cpasync16(sa + k * 4096 + tid * 16,
                      Wt + ((size_t)(k * 96 + it) * 12 + cb) * 2048 + tid * 8);
        // B: 132 rows x 32B, padded rows [14+bn, 145+bn]
        for (int i = tid; i < 264; i += 256) {
            int r = i >> 1, h = i & 1;
            cpasync16(sb + r * BROWB2 + h * 16,
                      Xb + (size_t)(14 + bn + r) * TCC + ci0 + h * 8);
        }
    };

    load_stage(0, 0); cpa_commit();
    load_stage(1, 1); cpa_commit();

    for (int t = 0; t < NTC; ++t) {
        cpa_wait<1>();
        __syncthreads();
        if (t + 2 < NTC) load_stage((t + 2) % CST3, t + 2);
        cpa_commit();

        const char* base = dsm + (t % CST3) * STG3;
        const char* Bs = base + A5SZ;
#pragma unroll
        for (int k = 0; k < 5; k++) {
            const uint4* Af = (const uint4*)(base + k * 4096);
            unsigned a[4][4], b[4][2];
#pragma unroll
            for (int mi = 0; mi < 4; mi++) {
                uint4 v = Af[(aoff + mi) * 32 + lane];
                a[mi][0] = v.x; a[mi][1] = v.y; a[mi][2] = v.z; a[mi][3] = v.w;
            }
#pragma unroll
            for (int ni = 0; ni < 4; ni++) {
                int row = wn + ni * 8 + g + k;
                b[ni][0] = *(const unsigned*)(Bs + row * BROWB2 + tg * 4);
                b[ni][1] = *(const unsigned*)(Bs + row * BROWB2 + 16 + tg * 4);
            }
#pragma unroll
            for (int mi = 0; mi < 4; mi++)
#pragma unroll
                for (int ni = 0; ni < 4; ni++)
                    MMA_F16(acc[mi][ni], a[mi], b[ni]);
        }
    }

    // epilogue: store fp16 [l][c] + fused per-channel stats from fp32 accs
#pragma unroll
    for (int mi = 0; mi < 4; mi++) {
        int m0 = bm + wm + mi * 16 + g;
        float s0 = 0.f, q0 = 0.f, s1 = 0.f, q1 = 0.f;
#pragma unroll
        for (int ni = 0; ni < 4; ni++) {
            float v0 = acc[mi][ni][0], v1 = acc[mi][ni][1];
            float v2 = acc[mi][ni][2], v3 = acc[mi][ni][3];
            s0 += v0 + v1; q0 += v0*v0 + v1*v1;
            s1 += v2 + v3; q1 += v2*v2 + v3*v3;
            int l0 = bn + wn + ni * 8 + 2 * tg;
            size_t r0 = ((size_t)(16 + l0)) * TCC;
            size_t r1 = ((size_t)(17 + l0)) * TCC;
            Yb[r0 + m0]     = __float2half(v0);
            Yb[r1 + m0]     = __float2half(v1);
            Yb[r0 + m0 + 8] = __float2half(v2);
            Yb[r1 + m0 + 8] = __float2half(v3);
        }
        s0 += __shfl_xor_sync(0xffffffffu, s0, 1);
        s0 += __shfl_xor_sync(0xffffffffu, s0, 2);
        q0 += __shfl_xor_sync(0xffffffffu, q0, 1);
        q0 += __shfl_xor_sync(0xffffffffu, q0, 2);
        s1 += __shfl_xor_sync(0xffffffffu, s1, 1);
        s1 += __shfl_xor_sync(0xffffffffu, s1, 2);
        q1 += __shfl_xor_sync(0xffffffffu, q1, 1);
        q1 += __shfl_xor_sync(0xffffffffu, q1, 2);
        if (tg == 0) {
            atomicAdd(&statsB[m0],         s0);
            atomicAdd(&statsB[TCC + m0],   q0);
            atomicAdd(&statsB[m0 + 8],     s1);
            atomicAdd(&statsB[TCC + m0+8], q1);
        }
    }
}

// ---------------- conv BN apply in-place on fp16 [l][c] ----------------------
__global__ void conv_bnH(__half* __restrict__ T, const float* __restrict__ g,
                         const float* __restrict__ beta, const __half* __restrict__ resid,
                         const float* __restrict__ statsB) {
    size_t idx = (size_t)blockIdx.x * blockDim.x + threadIdx.x;
    const size_t total = (size_t)Bb * LLEN * (TCC/2);
    if (idx >= total) return;
    int c2  = (int)(idx % (TCC/2));
    int l   = (int)((idx / (TCC/2)) % LLEN);
    int b   = (int)(idx / ((size_t)(TCC/2) * LLEN));
    int c   = c2 * 2;
    size_t a = ((size_t)b * LROWS + 16 + l) * TCC + c;
    const float invM = 1.f / (float)(Bb * LLEN);
    float m0 = statsB[c] * invM;
    float va = statsB[TCC + c] * invM - m0*m0;
    float m1 = statsB[c+1] * invM;
    float vb = statsB[TCC + c+1] * invM - m1*m1;
    __half2 hv = *(__half2*)(T + a);
    float2 f = __half22float2(hv);
    float o0 = (f.x - m0) * rsqrtf(va + BNEPS) * g[c]   + beta[c];
    float o1 = (f.y - m1) * rsqrtf(vb + BNEPS) * g[c+1] + beta[c+1];
    o0 = o0 > 0.f ? o0 : 0.f;
    o1 = o1 > 0.f ? o1 : 0.f;
    if (resid) {
        float2 r = __half22float2(*(const __half2*)(resid + a));
        o0 += r.x; o1 += r.y;
    }
    *(__half2*)(T + a) = __floats2half2_rn(o0, o1);
}

// ======================= output GEMM (fp16 mma, permuted A) =================
#define ASZh 4096
#define BROWB 48
#define BSZh (128*BROWB)
#define STGOh (ASZh + BSZh)

__global__ __launch_bounds__(256, 2) void out_gemm_f16(
        const __half* __restrict__ T2, const float* __restrict__ OB,
        float* __restrict__ OUT) {
    extern __shared__ __align__(128) char dsm[];
    const int tid = threadIdx.x;
    const int cb = blockIdx.x;
    const int bm = cb * 128;           // o
    const int bn = blockIdx.y * 128;   // s
    const int b  = blockIdx.z;
    const __half* T2b = T2 + (size_t)b * LROWS * TCC;
    const int lane = tid & 31, wid = tid >> 5;
    const int wm = (wid & 1) * 64, wn = (wid >> 1) * 32;
    const int g = lane >> 2, tg = lane & 3;
    const int aoff = (wid & 1) * 4;
    const uint32_t smem_u = s2u(dsm);

    float acc[4][4][4];
#pragma unroll
    for (int mi = 0; mi < 4; mi++)
#pragma unroll
        for (int ni = 0; ni < 4; ni++)
#pragma unroll
            for (int r = 0; r < 4; r++) acc[mi][ni][r] = 0.f;

    const int NT = TCC / 16;   // 96
    const int brow = tid >> 1, bhalf = tid & 1;

    auto load_stage = [&](int slot, int t) {
        const uint32_t sa = smem_u + slot * STGOh;
        const uint32_t sb = sa + ASZh;
        cpasync16(sa + tid * 16, g_owRH + ((size_t)t * 2 + cb) * 2048 + tid * 8);
        const __half* src = T2b + (size_t)(16 + bn + brow) * TCC + t * 16 + bhalf * 8;
        cpasync16(sb + brow * BROWB + bhalf * 16, src);
    };
    load_stage(0, 0); cpa_commit();
    load_stage(1, 1); cpa_commit();

    for (int t = 0; t < NT; ++t) {
        cpa_wait<1>();
        __syncthreads();
        if (t + 2 < NT) load_stage((t + 2) % 3, t + 2);
        cpa_commit();
        const int cur = t % 3;
        const uint4* Af = (const uint4*)(dsm + cur * STGOh);
        const char* Bs = dsm + cur * STGOh + ASZh;

        unsigned a[4][4], b[4][2];
#pragma unroll
        for (int mi = 0; mi < 4; mi++) {
            uint4 v = Af[(aoff + mi) * 32 + lane];
            a[mi][0] = v.x; a[mi][1] = v.y; a[mi][2] = v.z; a[mi][3] = v.w;
        }
#pragma unroll
        for (int ni = 0; ni < 4; ni++) {
            int row = wn + ni * 8 + g;
            b[ni][0] = *(const unsigned*)(Bs + row * BROWB + tg * 4);
            b[ni][1] = *(const unsigned*)(Bs + row * BROWB + 16 + tg * 4);
        }
#pragma unroll
        for (int mi = 0; mi < 4; mi++)
#pragma unroll
            for (int ni = 0; ni < 4; ni++)
                MMA_F16(acc[mi][ni], a[mi], b[ni]);
    }

#pragma unroll
    for (int mi = 0; mi < 4; mi++) {
        int o0 = bm + wm + mi * 16 + g;
        float bo0 = OB[o0], bo1 = OB[o0 + 8];
#pragma unroll
        for (int ni = 0; ni < 4; ni++) {
            int sL = bn + wn + ni * 8 + 2 * tg;
            float v0 = acc[mi][ni][0] + bo0; v0 = v0 > 0.f ? v0 : 0.f;
            float v1 = acc[mi][ni][1] + bo0; v1 = v1 > 0.f ? v1 : 0.f;
            float v2 = acc[mi][ni][2] + bo1; v2 = v2 > 0.f ? v2 : 0.f;
            float v3 = acc[mi][ni][3] + bo1; v3 = v3 > 0.f ? v3 : 0.f;
            OUT[((size_t)b * Ss + sL    ) * HHC + o0    ] = v0;
            OUT[((size_t)b * Ss + sL + 1) * HHC + o0    ] = v1;
            OUT[((size_t)b * Ss + sL    ) * HHC + o0 + 8] = v2;
            OUT[((size_t)b * Ss + sL + 1) * HHC + o0 + 8] = v3;
        }
    }
}

// ---------------- launch ----------------------------------------------------
extern "C" void kernel_launch(void* const* d_in, const int* in_sizes, int n_in,
                              void* d_out, int out_size) {
    const float* x     = (const float*)d_in[0];
    const float* adj   = (const float*)d_in[1];
    const float* eimp  = (const float*)d_in[2];
    const float* w1    = (const float*)d_in[3];
    const float* b1    = (const float*)d_in[4];
    const float* rw1   = (const float*)d_in[5];
    const float* rb1   = (const float*)d_in[6];
    const float* rg1   = (const float*)d_in[7];
    const float* rbeta1= (const float*)d_in[8];
    const float* g1    = (const float*)d_in[9];
    const float* beta1 = (const float*)d_in[10];
    const float* w2    = (const float*)d_in[11];
    const float* b2    = (const float*)d_in[12];
    const float* rw2   = (const float*)d_in[13];
    const float* rb2   = (const float*)d_in[14];
    const float* rg2   = (const float*)d_in[15];
    const float* rbeta2= (const float*)d_in[16];
    const float* g2    = (const float*)d_in[17];
    const float* beta2 = (const float*)d_in[18];
    const float* cw1   = (const float*)d_in[19];
    /* cb1 = d_in[20]: cancels exactly through BN mean-subtraction */
    const float* cg1   = (const float*)d_in[21];
    const float* cbeta1= (const float*)d_in[22];
    const float* cw2   = (const float*)d_in[23];
    /* cb2 = d_in[24]: cancels exactly */
    const float* cg2   = (const float*)d_in[25];
    const float* cbeta2= (const float*)d_in[26];
    const float* ow    = (const float*)d_in[27];
    const float* ob    = (const float*)d_in[28];
    float* out = (float*)d_out;

    float *p_xc1, *p_res1, *p_xc2, *p_res2, *p_stats;
    __half *p_htH, *p_t1H, *p_t2H, *p_wt1H, *p_wt2H;
    cudaGetSymbolAddress((void**)&p_xc1,  g_xc1);
    cudaGetSymbolAddress((void**)&p_res1, g_res1);
    cudaGetSymbolAddress((void**)&p_xc2,  g_xc2);
    cudaGetSymbolAddress((void**)&p_res2, g_res2);
    cudaGetSymbolAddress((void**)&p_stats, g_stats);
    cudaGetSymbolAddress((void**)&p_htH,  g_htH);
    cudaGetSymbolAddress((void**)&p_t1H,  g_t1H);
    cudaGetSymbolAddress((void**)&p_t2H,  g_t2H);
    cudaGetSymbolAddress((void**)&p_wt1H, g_wt1H);
    cudaGetSymbolAddress((void**)&p_wt2H, g_wt2H);

    cudaFuncSetAttribute(conv_gemm_f16,
                         cudaFuncAttributeMaxDynamicSharedMemorySize, CST3 * STG3);
    cudaFuncSetAttribute(gcn2_gemm_tf32,
                         cudaFuncAttributeMaxDynamicSharedMemorySize, 3 * STG2);
    cudaFuncSetAttribute(out_gemm_f16,
                         cudaFuncAttributeMaxDynamicSharedMemorySize, 3 * STGOh);

    // -------- prep: zero all 4 stat regions once + pads + weight packs ------
    zero_stats_all<<<(STTOT + 255)/256, 256>>>();
    zero_padsH<<<(Bb*32*(TCC/8) + 255)/256, 256>>>();
    pack_gcn2<<<(H1C*HHC + 255)/256, 256>>>(w2, rw2, b2, rb2);
    pack_owH<<<(TCC/16)*2, 256>>>(ow);
    wtrans_convH2<<<96*12, 256>>>(cw1, p_wt1H);
    wtrans_convH2<<<96*12, 256>>>(cw2, p_wt2H);

    // -------- GCN stage 1 --------
    gcn1_kernel<<<NBS, 256>>>(x, adj, eimp, w1, b1, rw1, rb1);
    stats_rows<<<1024, H1C>>>(p_xc1, p_res1, M1R, H1C, p_stats + ST1);
    bn_apply1<<<(M1R*H1C)/256, 256>>>(g1, beta1, rg1, rbeta1);

    // -------- GCN stage 2 (tf32 dual GEMM) --------
    gcn2_gemm_tf32<<<dim3(M1R/128, 4), 256, 3*STG2>>>();
    nodemix2<<<NBS, 256>>>(adj, eimp);
    stats_rows<<<1024, HHC>>>(p_xc2, p_res2, M1R, HHC, p_stats + ST2);
    bn_apply2_tohalf<<<M1R, 256>>>(g2, beta2, rg2, rbeta2);

    // -------- TCN conv 1 (fp16 mma, ci-tiled: X loaded once per 5 taps) ----
    conv_gemm_f16<<<dim3(TCC/128, LLEN/128, Bb), 256, CST3*STG3>>>(
        p_htH, p_wt1H, p_t1H, p_stats + STC1);
    conv_bnH<<<(Bb*LLEN*(TCC/2) + 255)/256, 256>>>(
        p_t1H, cg1, cbeta1, (const __half*)nullptr, p_stats + STC1);

    // -------- TCN conv 2 + residual --------
    conv_gemm_f16<<<dim3(TCC/128, LLEN/128, Bb), 256, CST3*STG3>>>(
        p_t1H, p_wt2H, p_t2H, p_stats + STC2);
    conv_bnH<<<(Bb*LLEN*(TCC/2) + 255)/256, 256>>>(
        p_t2H, cg2, cbeta2, p_htH, p_stats + STC2);

    // -------- output layer (fp16 mma) --------
    out_gemm_f16<<<dim3(HHC/128, LLEN/128, Bb), 256, 3*STGOh>>>(p_t2H, ob, out);

    (void)in_sizes; (void)n_in; (void)out_size;
}

// round 14
// speedup vs baseline: 1.2619x; 1.0021x over previous
#include <cuda_runtime.h>
#include <cuda_fp16.h>
#include <math.h>
#include <stdint.h>

#define Bb 32
#define Ss 512
#define NNODE 6
#define CIN 12
#define H1C 128
#define HHC 256
#define TCC 1536
#define LLEN 512
#define LROWS 544           /* 16 pad | 512 | 16 pad rows in [l][c] layout */
#define M1R (Bb*Ss*NNODE)   /* 98304 */
#define NBS (Bb*Ss)         /* 16384 */
#define RKK (5*TCC)         /* 7680  */
#define BNEPS 1e-5f

// stat regions (disjoint, zeroed once)
#define ST1 0
#define ST2 512
#define STC1 1536
#define STC2 4608
#define STTOT 7680

// ---------------- scratch (device globals; no runtime allocation) ----------
__device__ float  g_xc1 [M1R*H1C];
__device__ float  g_res1[M1R*H1C];
__device__ float  g_h1  [M1R*H1C];     // tf32-rounded at write
__device__ float  g_y2  [M1R*HHC];
__device__ float  g_res2[M1R*HHC];
__device__ float  g_xc2 [M1R*HHC];
__device__ __half g_htH [Bb*LROWS*TCC];  // [l][c] fp16, padded rows
__device__ __half g_t1H [Bb*LROWS*TCC];
__device__ __half g_t2H [Bb*LROWS*TCC];
__device__ __half g_wt1H[RKK*TCC];       // fragment-permuted fp16 tiles
__device__ __half g_wt2H[RKK*TCC];
__device__ float  g_wB  [H1C*512];       // packed (w2T | rw2T), tf32 bits
__device__ float  g_biasP[512];
__device__ __half g_owRH[TCC*HHC];       // fragment-permuted ow fp16 tiles
__device__ float  g_stats[STTOT];

// ---------------- helpers ----------------------------------------------------
__device__ __forceinline__ unsigned f2tf32(float f) {
    unsigned u; asm("cvt.rna.tf32.f32 %0, %1;" : "=r"(u) : "f"(f)); return u;
}
#define MMA_TF32(c, a, b) \
    asm volatile("mma.sync.aligned.m16n8k8.row.col.f32.tf32.tf32.f32 " \
        "{%0,%1,%2,%3}, {%4,%5,%6,%7}, {%8,%9}, {%0,%1,%2,%3};" \
        : "+f"((c)[0]), "+f"((c)[1]), "+f"((c)[2]), "+f"((c)[3]) \
        : "r"((a)[0]), "r"((a)[1]), "r"((a)[2]), "r"((a)[3]), \
          "r"((b)[0]), "r"((b)[1]))
#define MMA_F16(c, a, b) \
    asm volatile("mma.sync.aligned.m16n8k16.row.col.f32.f16.f16.f32 " \
        "{%0,%1,%2,%3}, {%4,%5,%6,%7}, {%8,%9}, {%0,%1,%2,%3};" \
        : "+f"((c)[0]), "+f"((c)[1]), "+f"((c)[2]), "+f"((c)[3]) \
        : "r"((a)[0]), "r"((a)[1]), "r"((a)[2]), "r"((a)[3]), \
          "r"((b)[0]), "r"((b)[1]))

__device__ __forceinline__ void cpasync16(uint32_t dst, const void* src) {
    asm volatile("cp.async.cg.shared.global [%0], [%1], 16;" :: "r"(dst), "l"(src));
}
__device__ __forceinline__ void cpa_commit() {
    asm volatile("cp.async.commit_group;" ::: "memory");
}
template<int N>
__device__ __forceinline__ void cpa_wait() {
    asm volatile("cp.async.wait_group %0;" :: "n"(N) : "memory");
}
__device__ __forceinline__ uint32_t s2u(const void* p) {
    return (uint32_t)__cvta_generic_to_shared(p);
}
__device__ __forceinline__ unsigned packh2(float a, float b) {
    __half2 h = __floats2half2_rn(a, b);
    return *(unsigned*)&h;
}

// ---------------- merged prep kernel ----------------------------------------
// block ranges: [0,30) zero stats | [30,798) zero pads | [798,926) pack_gcn2
//               | [926,1118) pack_owH
__global__ void prep_all(const float* __restrict__ w2, const float* __restrict__ rw2,
                         const float* __restrict__ b2, const float* __restrict__ rb2,
                         const float* __restrict__ ow) {
    int blk = blockIdx.x;
    int tid = threadIdx.x;
    if (blk < 30) {
        int i = blk * 256 + tid;
        if (i < STTOT) g_stats[i] = 0.f;
        return;
    }
    if (blk < 798) {
        int idx = (blk - 30) * 256 + tid;
        const int per = Bb * 32 * (TCC/8);
        if (idx >= per) return;
        int col8 = idx % (TCC/8);
        int rr   = (idx / (TCC/8)) % 32;
        int b    = idx / (32 * (TCC/8));
        int row  = rr < 16 ? rr : 512 + rr;
        size_t off = ((size_t)b * LROWS + row) * TCC + col8 * 8;
        uint4 z = make_uint4(0,0,0,0);
        *(uint4*)((char*)g_htH + off*2) = z;
        *(uint4*)((char*)g_t1H + off*2) = z;
        return;
    }
    if (blk < 926) {
        int idx = (blk - 798) * 256 + tid;
        if (idx >= H1C * HHC) return;
        int i = idx >> 8;
        int o = idx & 255;
        unsigned* wB = (unsigned*)g_wB;
        wB[i * 512 + o]       = f2tf32(w2[(size_t)o * H1C + i]);
        wB[i * 512 + 256 + o] = f2tf32(rw2[(size_t)o * H1C + i]);
        if (i == 0) { g_biasP[o] = b2[o]; g_biasP[256 + o] = rb2[o]; }
        return;
    }
    {
        int tile = blk - 926;                 // 0..191 : tk*2 + cb
        int tk = tile >> 1, cb = tile & 1;
        unsigned* dst = (unsigned*)g_owRH + (size_t)tile * 1024 + tid * 4;
#pragma unroll
        for (int u = 0; u < 4; u++) {
            int pos = tid * 4 + u;
            int r = pos & 3, lane = (pos >> 2) & 31, mi = pos >> 7;
            int kl = 2 * (lane & 3) + ((r >> 1) << 3);
            int ml = mi * 16 + (lane >> 2) + ((r & 1) << 3);
            int c = tk * 16 + kl;
            int o = cb * 128 + ml;
            float f0 = ow[(size_t)o * TCC + c];
            float f1 = ow[(size_t)o * TCC + c + 1];
            dst[u] = packh2(f0, f1);
        }
    }
}

// coalesced conv-weight transform -> fragment-permuted fp16 tiles
__global__ void wtrans_convH2(const float* __restrict__ cw, __half* __restrict__ wt) {
    __shared__ float sm[128 * 81];
    int blk = blockIdx.x;                 // cib*12 + cb ; cib in [0,96)
    int cib = blk / 12, cb = blk % 12;
    int ci0 = cib * 16;
    int tid = threadIdx.x;
    for (int i = tid; i < 128 * 80; i += 256) {
        int co = i / 80, j = i % 80;
        sm[co * 81 + j] = cw[((size_t)(cb * 128 + co) * TCC + ci0) * 5 + j];
    }
    __syncthreads();
#pragma unroll
    for (int k = 0; k < 5; k++) {
        int tile = (k * 96 + cib) * 12 + cb;
        unsigned* dst = (unsigned*)wt + (size_t)tile * 1024 + tid * 4;
#pragma unroll
        for (int u = 0; u < 4; u++) {
            int pos = tid * 4 + u;
            int r = pos & 3, lane = (pos >> 2) & 31, mi = pos >> 7;
            int kl = 2 * (lane & 3) + ((r >> 1) << 3);
            int ml = mi * 16 + (lane >> 2) + ((r & 1) << 3);
            float f0 = sm[ml * 81 + kl * 5 + k];
            float f1 = sm[ml * 81 + (kl + 1) * 5 + k];
            dst[u] = packh2(f0, f1);
        }
    }
}

// ---------------- GCN stage 1 ------------------------------------------------
__global__ void gcn1_kernel(const float* __restrict__ x, const float* __restrict__ adj,
                            const float* __restrict__ eimp,
                            const float* __restrict__ w1, const float* __restrict__ b1,
                            const float* __restrict__ rw1, const float* __restrict__ rb1) {
    __shared__ float xs[NNODE*CIN];
    __shared__ float Asm[NNODE*NNODE];
    __shared__ float xts[NNODE*H1C];
    int bs = blockIdx.x;
    int tid = threadIdx.x;
    if (tid < NNODE*CIN) xs[tid] = x[(size_t)bs*NNODE*CIN + tid];
    if (tid >= 128 && tid < 128 + NNODE*NNODE) Asm[tid-128] = adj[tid-128] * eimp[tid-128];
    __syncthreads();
    for (int e = tid; e < NNODE*H1C; e += blockDim.x) {
        int n = e / H1C, c = e % H1C;
        float ws = b1[c], rs = rb1[c];
#pragma unroll
        for (int i = 0; i < CIN; i++) {
            float xv = xs[n*CIN + i];
            ws += xv * w1[c*CIN + i];
            rs += xv * rw1[c*CIN + i];
        }
        xts[e] = ws;
        g_res1[(size_t)bs*(NNODE*H1C) + e] = rs;
    }
    __syncthreads();
    for (int e = tid; e < NNODE*H1C; e += blockDim.x) {
        int n = e / H1C, c = e % H1C;
        float acc = 0.f;
#pragma unroll
        for (int m = 0; m < NNODE; m++) acc += Asm[n*NNODE + m] * xts[m*H1C + c];
        g_xc1[(size_t)bs*(NNODE*H1C) + e] = acc;
    }
}

__global__ void stats_rows(const float* __restrict__ a, const float* __restrict__ b,
                           int Mrows, int C, float* __restrict__ base) {
    int c = threadIdx.x;
    int rows_per = Mrows / gridDim.x;
    int r0 = blockIdx.x * rows_per;
    int r1 = r0 + rows_per;
    float sa = 0.f, qa = 0.f, sb = 0.f, qb = 0.f;
    for (int r = r0; r < r1; r++) {
        float v = a[(size_t)r*C + c]; sa += v; qa += v*v;
        float u = b[(size_t)r*C + c]; sb += u; qb += u*u;
    }
    atomicAdd(&base[c],       sa);
    atomicAdd(&base[C + c],   qa);
    atomicAdd(&base[2*C + c], sb);
    atomicAdd(&base[3*C + c], qb);
}

__global__ void bn_apply1(const float* __restrict__ g1, const float* __restrict__ beta1,
                          const float* __restrict__ rg1, const float* __restrict__ rbeta1) {
    size_t idx = (size_t)blockIdx.x * blockDim.x + threadIdx.x;
    if (idx >= (size_t)M1R*H1C) return;
    int c = (int)(idx % H1C);
    const float* st = g_stats + ST1;
    const float invM = 1.f / (float)M1R;
    float m1 = st[c] * invM;
    float v1 = st[H1C + c] * invM - m1*m1;
    float m2 = st[2*H1C + c] * invM;
    float v2 = st[3*H1C + c] * invM - m2*m2;
    float a = (g_xc1[idx]  - m1) * rsqrtf(v1 + BNEPS) * g1[c]  + beta1[c];
    float r = (g_res1[idx] - m2) * rsqrtf(v2 + BNEPS) * rg1[c] + rbeta1[c];
    float o = a + r;
    o = o > 0.f ? o : 0.f;
    g_h1[idx] = __uint_as_float(f2tf32(o));
}

// ---------------- gcn2 dual GEMM (tf32 mma, unchanged) ----------------------
#define A2STR 20
#define B2STR 136
#define A2SZ (128*A2STR*4)
#define B2SZ (16*B2STR*4)
#define STG2 (A2SZ + B2SZ)

__global__ __launch_bounds__(256, 2) void gcn2_gemm_tf32() {
    extern __shared__ __align__(128) char dsm[];
    const int tid = threadIdx.x;
    const int bm = blockIdx.x * 128;
    const int by = blockIdx.y;
    const int bn = by * 128;
    const int lane = tid & 31, wid = tid >> 5;
    const int wm = (wid & 1) * 64, wn = (wid >> 1) * 32;
    const int g = lane >> 2, tg = lane & 3;
    const uint32_t smem_u = s2u(dsm);
    const float* A = g_h1;

    float acc[4][4][4];
#pragma unroll
    for (int mi = 0; mi < 4; mi++)
#pragma unroll
        for (int ni = 0; ni < 4; ni++)
#pragma unroll
            for (int r = 0; r < 4; r++) acc[mi][ni][r] = 0.f;

    const int NT = H1C / 16;   // 8

    auto load_stage = [&](int slot, int t) {
        const int kk0 = t * 16;
        const uint32_t sa = smem_u + slot * STG2;
        const uint32_t sb = sa + A2SZ;
#pragma unroll
        for (int i = 0; i < 2; i++) {
            int idx = tid + i * 256;
            int m = idx >> 2, kc = (idx & 3) * 4;
            cpasync16(sa + (m * A2STR + kc) * 4,
                      A + (size_t)(bm + m) * H1C + kk0 + kc);
        }
#pragma unroll
        for (int i = 0; i < 2; i++) {
            int idx = tid + i * 256;
            int row = idx >> 5, ch = idx & 31;
            cpasync16(sb + (row * B2STR + ch * 4) * 4,
                      g_wB + (size_t)(kk0 + row) * 512 + bn + ch * 4);
        }
    };
    load_stage(0, 0); cpa_commit();
    load_stage(1, 1); cpa_commit();

    for (int t = 0; t < NT; ++t) {
        cpa_wait<1>();
        __syncthreads();
        if (t + 2 < NT) load_stage((t + 2) % 3, t + 2);
        cpa_commit();
        const int cur = t % 3;
        const float* As = (const float*)(dsm + cur * STG2);
        const float* Bs = (const float*)(dsm + cur * STG2 + A2SZ);
#pragma unroll
        for (int ks = 0; ks < 16; ks += 8) {
            unsigned a[4][4], b[4][2];
#pragma unroll
            for (int mi = 0; mi < 4; mi++) {
                int m = wm + mi * 16 + g;
                a[mi][0] = __float_as_uint(As[(m    ) * A2STR + ks + tg]);
                a[mi][1] = __float_as_uint(As[(m + 8) * A2STR + ks + tg]);
                a[mi][2] = __float_as_uint(As[(m    ) * A2STR + ks + tg + 4]);
                a[mi][3] = __float_as_uint(As[(m + 8) * A2STR + ks + tg + 4]);
            }
#pragma unroll
            for (int ni = 0; ni < 4; ni++) {
                int c = wn + ni * 8 + g;
                b[ni][0] = __float_as_uint(Bs[(ks + tg    ) * B2STR + c]);
                b[ni][1] = __float_as_uint(Bs[(ks + tg + 4) * B2STR + c]);
            }
#pragma unroll
            for (int mi = 0; mi < 4; mi++)
#pragma unroll
                for (int ni = 0; ni < 4; ni++)
                    MMA_TF32(acc[mi][ni], a[mi], b[ni]);
        }
    }

    float* tgt = (by < 2) ? g_y2 : g_res2;
    const int nb = (by & 1) * 128;
#pragma unroll
    for (int mi = 0; mi < 4; mi++) {
        int m0 = bm + wm + mi * 16 + g;
#pragma unroll
        for (int ni = 0; ni < 4; ni++) {
            int n = nb + wn + ni * 8 + 2 * tg;
            int pb = bn + wn + ni * 8 + 2 * tg;
            float b0 = g_biasP[pb], b1 = g_biasP[pb + 1];
            *(float2*)(tgt + (size_t)m0 * HHC + n)
                = make_float2(acc[mi][ni][0] + b0, acc[mi][ni][1] + b1);
            *(float2*)(tgt + (size_t)(m0 + 8) * HHC + n)
                = make_float2(acc[mi][ni][2] + b0, acc[mi][ni][3] + b1);
        }
    }
}

// ---------------- node mix for stage 2 --------------------------------------
__global__ void nodemix2(const float* __restrict__ adj, const float* __restrict__ eimp) {
    __shared__ float ys[NNODE*HHC];
    __shared__ float Asm[NNODE*NNODE];
    int bs = blockIdx.x, tid = threadIdx.x;
    if (tid < NNODE*NNODE) Asm[tid] = adj[tid] * eimp[tid];
    for (int e = tid; e < NNODE*HHC; e += blockDim.x)
        ys[e] = g_y2[(size_t)bs*NNODE*HHC + e];
    __syncthreads();
    for (int e = tid; e < NNODE*HHC; e += blockDim.x) {
        int n = e / HHC, c = e % HHC;
        float acc = 0.f;
#pragma unroll
        for (int m = 0; m < NNODE; m++) acc += Asm[n*NNODE + m] * ys[m*HHC + c];
        g_xc2[(size_t)bs*NNODE*HHC + e] = acc;
    }
}

// ---------------- BN apply stage 2 -> [l][c] fp16 ----------------------------
__global__ void bn_apply2_tohalf(const float* __restrict__ g2, const float* __restrict__ beta2,
                                 const float* __restrict__ rg2, const float* __restrict__ rbeta2) {
    int row = blockIdx.x;        // (b*Ss + s)*6 + n
    int c = threadIdx.x;         // 0..255
    const float* st = g_stats + ST2;
    const float invM = 1.f / (float)M1R;
    float m1 = st[c] * invM;
    float v1 = st[HHC + c] * invM - m1*m1;
    float m2 = st[2*HHC + c] * invM;
    float v2 = st[3*HHC + c] * invM - m2*m2;
    float sc1 = rsqrtf(v1 + BNEPS) * g2[c];
    float sh1 = beta2[c] - m1*sc1;
    float sc2 = rsqrtf(v2 + BNEPS) * rg2[c];
    float sh2 = rbeta2[c] - m2*sc2;
    size_t ridx = (size_t)row * HHC + c;
    float o = g_xc2[ridx]*sc1 + sh1 + g_res2[ridx]*sc2 + sh2;
    o = o > 0.f ? o : 0.f;
    int n = row % NNODE;
    int bs = row / NNODE;
    int b = bs / Ss, s = bs % Ss;
    g_htH[((size_t)b * LROWS + 16 + s) * TCC + n * HHC + c] = __float2half(o);
}

// ======================= conv1d fp16 mma GEMM, ci-tiled, 4-stage =============
// Per stage: one 16-ci X block (132 rows, loaded ONCE) + all 5 weight tap
// tiles; 5 taps' MMAs run from the same smem B with row offsets 0..4.
#define A5SZ 20480          /* 5 x 4096 weight tap tiles */
#define BROWB2 48           /* B smem row stride bytes */
#define STG3 26880          /* A5SZ + 132*48 = 26816, padded to 128 */
#define CST3 4

__global__ __launch_bounds__(256, 2) void conv_gemm_f16(
        const __half* __restrict__ X, const __half* __restrict__ Wt,
        __half* __restrict__ Y, float* __restrict__ statsB) {
    extern __shared__ __align__(128) char dsm[];
    const int tid = threadIdx.x;
    const int cb = blockIdx.x;
    const int bm = cb * 128;           // co
    const int bn = blockIdx.y * 128;   // l
    const __half* Xb = X + (size_t)blockIdx.z * LROWS * TCC;
    __half* Yb = Y + (size_t)blockIdx.z * LROWS * TCC;
    const int lane = tid & 31, wid = tid >> 5;
    const int wm = (wid & 1) * 64, wn = (wid >> 1) * 32;
    const int g = lane >> 2, tg = lane & 3;
    const int aoff = (wid & 1) * 4;
    const uint32_t smem_u = s2u(dsm);

    float acc[4][4][4];
#pragma unroll
    for (int mi = 0; mi < 4; mi++)
#pragma unroll
        for (int ni = 0; ni < 4; ni++)
#pragma unroll
            for (int r = 0; r < 4; r++) acc[mi][ni][r] = 0.f;

    const int NTC = TCC / 16;   // 96 ci-tiles

    auto load_stage = [&](int slot, int it) {
        const int ci0 = it * 16;
        const uint32_t sa = smem_u + slot * STG3;
        const uint32_t sb = sa + A5SZ;
#pragma unroll
        for (int k = 0; k < 5; k++)
            cpasync16(sa + k * 4096 + tid * 16,
                      Wt + ((size_t)(k * 96 + it) * 12 + cb) * 2048 + tid * 8);
        for (int i = tid; i < 264; i += 256) {
            int r = i >> 1, h = i & 1;
            cpasync16(sb + r * BROWB2 + h * 16,
                      Xb + (size_t)(14 + bn + r) * TCC + ci0 + h * 8);
        }
    };

    load_stage(0, 0); cpa_commit();
    load_stage(1, 1); cpa_commit();
    load_stage(2, 2); cpa_commit();

    for (int t = 0; t < NTC; ++t) {
        cpa_wait<2>();
        __syncthreads();
        if (t + 3 < NTC) load_stage((t + 3) % CST3, t + 3);
        cpa_commit();

        const char* base = dsm + (t % CST3) * STG3;
        const char* Bs = base + A5SZ;
#pragma unroll
        for (int k = 0; k < 5; k++) {
            const uint4* Af = (const uint4*)(base + k * 4096);
            unsigned a[4][4], b[4][2];
#pragma unroll
            for (int mi = 0; mi < 4; mi++) {
                uint4 v = Af[(aoff + mi) * 32 + lane];
                a[mi][0] = v.x; a[mi][1] = v.y; a[mi][2] = v.z; a[mi][3] = v.w;
            }
#pragma unroll
            for (int ni = 0; ni < 4; ni++) {
                int row = wn + ni * 8 + g + k;
                b[ni][0] = *(const unsigned*)(Bs + row * BROWB2 + tg * 4);
                b[ni][1] = *(const unsigned*)(Bs + row * BROWB2 + 16 + tg * 4);
            }
#pragma unroll
            for (int mi = 0; mi < 4; mi++)
#pragma unroll
                for (int ni = 0; ni < 4; ni++)
                    MMA_F16(acc[mi][ni], a[mi], b[ni]);
        }
    }

    // epilogue: store fp16 [l][c] + fused per-channel stats from fp32 accs
#pragma unroll
    for (int mi = 0; mi < 4; mi++) {
        int m0 = bm + wm + mi * 16 + g;
        float s0 = 0.f, q0 = 0.f, s1 = 0.f, q1 = 0.f;
#pragma unroll
        for (int ni = 0; ni < 4; ni++) {
            float v0 = acc[mi][ni][0], v1 = acc[mi][ni][1];
            float v2 = acc[mi][ni][2], v3 = acc[mi][ni][3];
            s0 += v0 + v1; q0 += v0*v0 + v1*v1;
            s1 += v2 + v3; q1 += v2*v2 + v3*v3;
            int l0 = bn + wn + ni * 8 + 2 * tg;
            size_t r0 = ((size_t)(16 + l0)) * TCC;
            size_t r1 = ((size_t)(17 + l0)) * TCC;
            Yb[r0 + m0]     = __float2half(v0);
            Yb[r1 + m0]     = __float2half(v1);
            Yb[r0 + m0 + 8] = __float2half(v2);
            Yb[r1 + m0 + 8] = __float2half(v3);
        }
        s0 += __shfl_xor_sync(0xffffffffu, s0, 1);
        s0 += __shfl_xor_sync(0xffffffffu, s0, 2);
        q0 += __shfl_xor_sync(0xffffffffu, q0, 1);
        q0 += __shfl_xor_sync(0xffffffffu, q0, 2);
        s1 += __shfl_xor_sync(0xffffffffu, s1, 1);
        s1 += __shfl_xor_sync(0xffffffffu, s1, 2);
        q1 += __shfl_xor_sync(0xffffffffu, q1, 1);
        q1 += __shfl_xor_sync(0xffffffffu, q1, 2);
        if (tg == 0) {
            atomicAdd(&statsB[m0],         s0);
            atomicAdd(&statsB[TCC + m0],   q0);
            atomicAdd(&statsB[m0 + 8],     s1);
            atomicAdd(&statsB[TCC + m0+8], q1);
        }
    }
}

// ---------------- conv BN apply in-place on fp16 [l][c] ----------------------
__global__ void conv_bnH(__half* __restrict__ T, const float* __restrict__ g,
                         const float* __restrict__ beta, const __half* __restrict__ resid,
                         const float* __restrict__ statsB) {
    size_t idx = (size_t)blockIdx.x * blockDim.x + threadIdx.x;
    const size_t total = (size_t)Bb * LLEN * (TCC/2);
    if (idx >= total) return;
    int c2  = (int)(idx % (TCC/2));
    int l   = (int)((idx / (TCC/2)) % LLEN);
    int b   = (int)(idx / ((size_t)(TCC/2) * LLEN));
    int c   = c2 * 2;
    size_t a = ((size_t)b * LROWS + 16 + l) * TCC + c;
    const float invM = 1.f / (float)(Bb * LLEN);
    float m0 = statsB[c] * invM;
    float va = statsB[TCC + c] * invM - m0*m0;
    float m1 = statsB[c+1] * invM;
    float vb = statsB[TCC + c+1] * invM - m1*m1;
    __half2 hv = *(__half2*)(T + a);
    float2 f = __half22float2(hv);
    float o0 = (f.x - m0) * rsqrtf(va + BNEPS) * g[c]   + beta[c];
    float o1 = (f.y - m1) * rsqrtf(vb + BNEPS) * g[c+1] + beta[c+1];
    o0 = o0 > 0.f ? o0 : 0.f;
    o1 = o1 > 0.f ? o1 : 0.f;
    if (resid) {
        float2 r = __half22float2(*(const __half2*)(resid + a));
        o0 += r.x; o1 += r.y;
    }
    *(__half2*)(T + a) = __floats2half2_rn(o0, o1);
}

// ======================= output GEMM (fp16 mma, permuted A) =================
#define ASZh 4096
#define BROWB 48
#define BSZh (128*BROWB)
#define STGOh (ASZh + BSZh)

__global__ __launch_bounds__(256, 2) void out_gemm_f16(
        const __half* __restrict__ T2, const float* __restrict__ OB,
        float* __restrict__ OUT) {
    extern __shared__ __align__(128) char dsm[];
    const int tid = threadIdx.x;
    const int cb = blockIdx.x;
    const int bm = cb * 128;           // o
    const int bn = blockIdx.y * 128;   // s
    const int b  = blockIdx.z;
    const __half* T2b = T2 + (size_t)b * LROWS * TCC;
    const int lane = tid & 31, wid = tid >> 5;
    const int wm = (wid & 1) * 64, wn = (wid >> 1) * 32;
    const int g = lane >> 2, tg = lane & 3;
    const int aoff = (wid & 1) * 4;
    const uint32_t smem_u = s2u(dsm);

    float acc[4][4][4];
#pragma unroll
    for (int mi = 0; mi < 4; mi++)
#pragma unroll
        for (int ni = 0; ni < 4; ni++)
#pragma unroll
            for (int r = 0; r < 4; r++) acc[mi][ni][r] = 0.f;

    const int NT = TCC / 16;   // 96
    const int brow = tid >> 1, bhalf = tid & 1;

    auto load_stage = [&](int slot, int t) {
        const uint32_t sa = smem_u + slot * STGOh;
        const uint32_t sb = sa + ASZh;
        cpasync16(sa + tid * 16, g_owRH + ((size_t)t * 2 + cb) * 2048 + tid * 8);
        const __half* src = T2b + (size_t)(16 + bn + brow) * TCC + t * 16 + bhalf * 8;
        cpasync16(sb + brow * BROWB + bhalf * 16, src);
    };
    load_stage(0, 0); cpa_commit();
    load_stage(1, 1); cpa_commit();

    for (int t = 0; t < NT; ++t) {
        cpa_wait<1>();
        __syncthreads();
        if (t + 2 < NT) load_stage((t + 2) % 3, t + 2);
        cpa_commit();
        const int cur = t % 3;
        const uint4* Af = (const uint4*)(dsm + cur * STGOh);
        const char* Bs = dsm + cur * STGOh + ASZh;

        unsigned a[4][4], b[4][2];
#pragma unroll
        for (int mi = 0; mi < 4; mi++) {
            uint4 v = Af[(aoff + mi) * 32 + lane];
            a[mi][0] = v.x; a[mi][1] = v.y; a[mi][2] = v.z; a[mi][3] = v.w;
        }
#pragma unroll
        for (int ni = 0; ni < 4; ni++) {
            int row = wn + ni * 8 + g;
            b[ni][0] = *(const unsigned*)(Bs + row * BROWB + tg * 4);
            b[ni][1] = *(const unsigned*)(Bs + row * BROWB + 16 + tg * 4);
        }
#pragma unroll
        for (int mi = 0; mi < 4; mi++)
#pragma unroll
            for (int ni = 0; ni < 4; ni++)
                MMA_F16(acc[mi][ni], a[mi], b[ni]);
    }

#pragma unroll
    for (int mi = 0; mi < 4; mi++) {
        int o0 = bm + wm + mi * 16 + g;
        float bo0 = OB[o0], bo1 = OB[o0 + 8];
#pragma unroll
        for (int ni = 0; ni < 4; ni++) {
            int sL = bn + wn + ni * 8 + 2 * tg;
            float v0 = acc[mi][ni][0] + bo0; v0 = v0 > 0.f ? v0 : 0.f;
            float v1 = acc[mi][ni][1] + bo0; v1 = v1 > 0.f ? v1 : 0.f;
            float v2 = acc[mi][ni][2] + bo1; v2 = v2 > 0.f ? v2 : 0.f;
            float v3 = acc[mi][ni][3] + bo1; v3 = v3 > 0.f ? v3 : 0.f;
            OUT[((size_t)b * Ss + sL    ) * HHC + o0    ] = v0;
            OUT[((size_t)b * Ss + sL + 1) * HHC + o0    ] = v1;
            OUT[((size_t)b * Ss + sL    ) * HHC + o0 + 8] = v2;
            OUT[((size_t)b * Ss + sL + 1) * HHC + o0 + 8] = v3;
        }
    }
}

// ---------------- launch ----------------------------------------------------
extern "C" void kernel_launch(void* const* d_in, const int* in_sizes, int n_in,
                              void* d_out, int out_size) {
    const float* x     = (const float*)d_in[0];
    const float* adj   = (const float*)d_in[1];
    const float* eimp  = (const float*)d_in[2];
    const float* w1    = (const float*)d_in[3];
    const float* b1    = (const float*)d_in[4];
    const float* rw1   = (const float*)d_in[5];
    const float* rb1   = (const float*)d_in[6];
    const float* rg1   = (const float*)d_in[7];
    const float* rbeta1= (const float*)d_in[8];
    const float* g1    = (const float*)d_in[9];
    const float* beta1 = (const float*)d_in[10];
    const float* w2    = (const float*)d_in[11];
    const float* b2    = (const float*)d_in[12];
    const float* rw2   = (const float*)d_in[13];
    const float* rb2   = (const float*)d_in[14];
    const float* rg2   = (const float*)d_in[15];
    const float* rbeta2= (const float*)d_in[16];
    const float* g2    = (const float*)d_in[17];
    const float* beta2 = (const float*)d_in[18];
    const float* cw1   = (const float*)d_in[19];
    /* cb1 = d_in[20]: cancels exactly through BN mean-subtraction */
    const float* cg1   = (const float*)d_in[21];
    const float* cbeta1= (const float*)d_in[22];
    const float* cw2   = (const float*)d_in[23];
    /* cb2 = d_in[24]: cancels exactly */
    const float* cg2   = (const float*)d_in[25];
    const float* cbeta2= (const float*)d_in[26];
    const float* ow    = (const float*)d_in[27];
    const float* ob    = (const float*)d_in[28];
    float* out = (float*)d_out;

    float *p_xc1, *p_res1, *p_xc2, *p_res2, *p_stats;
    __half *p_htH, *p_t1H, *p_t2H, *p_wt1H, *p_wt2H;
    cudaGetSymbolAddress((void**)&p_xc1,  g_xc1);
    cudaGetSymbolAddress((void**)&p_res1, g_res1);
    cudaGetSymbolAddress((void**)&p_xc2,  g_xc2);
    cudaGetSymbolAddress((void**)&p_res2, g_res2);
    cudaGetSymbolAddress((void**)&p_stats, g_stats);
    cudaGetSymbolAddress((void**)&p_htH,  g_htH);
    cudaGetSymbolAddress((void**)&p_t1H,  g_t1H);
    cudaGetSymbolAddress((void**)&p_t2H,  g_t2H);
    cudaGetSymbolAddress((void**)&p_wt1H, g_wt1H);
    cudaGetSymbolAddress((void**)&p_wt2H, g_wt2H);

    cudaFuncSetAttribute(conv_gemm_f16,
                         cudaFuncAttributeMaxDynamicSharedMemorySize, CST3 * STG3);
    cudaFuncSetAttribute(gcn2_gemm_tf32,
                         cudaFuncAttributeMaxDynamicSharedMemorySize, 3 * STG2);
    cudaFuncSetAttribute(out_gemm_f16,
                         cudaFuncAttributeMaxDynamicSharedMemorySize, 3 * STGOh);

    // -------- prep: merged zero/pack + weight transforms --------------------
    prep_all<<<1118, 256>>>(w2, rw2, b2, rb2, ow);
    wtrans_convH2<<<96*12, 256>>>(cw1, p_wt1H);
    wtrans_convH2<<<96*12, 256>>>(cw2, p_wt2H);

    // -------- GCN stage 1 --------
    gcn1_kernel<<<NBS, 256>>>(x, adj, eimp, w1, b1, rw1, rb1);
    stats_rows<<<1024, H1C>>>(p_xc1, p_res1, M1R, H1C, p_stats + ST1);
    bn_apply1<<<(M1R*H1C)/256, 256>>>(g1, beta1, rg1, rbeta1);

    // -------- GCN stage 2 (tf32 dual GEMM) --------
    gcn2_gemm_tf32<<<dim3(M1R/128, 4), 256, 3*STG2>>>();
    nodemix2<<<NBS, 256>>>(adj, eimp);
    stats_rows<<<1024, HHC>>>(p_xc2, p_res2, M1R, HHC, p_stats + ST2);
    bn_apply2_tohalf<<<M1R, 256>>>(g2, beta2, rg2, rbeta2);

    // -------- TCN conv 1 (fp16 mma, ci-tiled, 4-stage) --------
    conv_gemm_f16<<<dim3(TCC/128, LLEN/128, Bb), 256, CST3*STG3>>>(
        p_htH, p_wt1H, p_t1H, p_stats + STC1);
    conv_bnH<<<(Bb*LLEN*(TCC/2) + 255)/256, 256>>>(
        p_t1H, cg1, cbeta1, (const __half*)nullptr, p_stats + STC1);

    // -------- TCN conv 2 + residual --------
    conv_gemm_f16<<<dim3(TCC/128, LLEN/128, Bb), 256, CST3*STG3>>>(
        p_t1H, p_wt2H, p_t2H, p_stats + STC2);
    conv_bnH<<<(Bb*LLEN*(TCC/2) + 255)/256, 256>>>(
        p_t2H, cg2, cbeta2, p_htH, p_stats + STC2);

    // -------- output layer (fp16 mma) --------
    out_gemm_f16<<<dim3(HHC/128, LLEN/128, Bb), 256, 3*STGOh>>>(p_t2H, ob, out);

    (void)in_sizes; (void)n_in; (void)out_size;
}

// round 15
// speedup vs baseline: 1.3342x; 1.0573x over previous
#include <cuda_runtime.h>
#include <cuda_fp16.h>
#include <math.h>
#include <stdint.h>

#define Bb 32
#define Ss 512
#define NNODE 6
#define CIN 12
#define H1C 128
#define HHC 256
#define TCC 1536
#define LLEN 512
#define LROWS 544           /* 16 pad | 512 | 16 pad rows in [l][c] layout */
#define M1R (Bb*Ss*NNODE)   /* 98304 */
#define NBS (Bb*Ss)         /* 16384 */
#define RKK (5*TCC)         /* 7680  */
#define BNEPS 1e-5f

// stat regions (disjoint, zeroed once)
#define ST1 0
#define ST2 512
#define STC1 1536
#define STC2 4608
#define STTOT 7680

// ---------------- scratch (device globals; no runtime allocation) ----------
__device__ float  g_xc1 [M1R*H1C];
__device__ float  g_res1[M1R*H1C];
__device__ float  g_h1  [M1R*H1C];     // tf32-rounded at write
__device__ float  g_y2  [M1R*HHC];
__device__ float  g_res2[M1R*HHC];
__device__ float  g_xc2 [M1R*HHC];
__device__ __half g_htH [Bb*LROWS*TCC];  // [l][c] fp16, padded rows
__device__ __half g_t1H [Bb*LROWS*TCC];
__device__ __half g_t2H [Bb*LROWS*TCC];
__device__ __half g_wt1H[RKK*TCC];       // fragment-permuted fp16 tiles
__device__ __half g_wt2H[RKK*TCC];
__device__ float  g_wB  [H1C*512];       // packed (w2T | rw2T), tf32 bits
__device__ float  g_biasP[512];
__device__ __half g_owRH[TCC*HHC];       // fragment-permuted ow fp16 tiles
__device__ float  g_stats[STTOT];

// ---------------- helpers ----------------------------------------------------
__device__ __forceinline__ unsigned f2tf32(float f) {
    unsigned u; asm("cvt.rna.tf32.f32 %0, %1;" : "=r"(u) : "f"(f)); return u;
}
#define MMA_TF32(c, a, b) \
    asm volatile("mma.sync.aligned.m16n8k8.row.col.f32.tf32.tf32.f32 " \
        "{%0,%1,%2,%3}, {%4,%5,%6,%7}, {%8,%9}, {%0,%1,%2,%3};" \
        : "+f"((c)[0]), "+f"((c)[1]), "+f"((c)[2]), "+f"((c)[3]) \
        : "r"((a)[0]), "r"((a)[1]), "r"((a)[2]), "r"((a)[3]), \
          "r"((b)[0]), "r"((b)[1]))
#define MMA_F16(c, a, b) \
    asm volatile("mma.sync.aligned.m16n8k16.row.col.f32.f16.f16.f32 " \
        "{%0,%1,%2,%3}, {%4,%5,%6,%7}, {%8,%9}, {%0,%1,%2,%3};" \
        : "+f"((c)[0]), "+f"((c)[1]), "+f"((c)[2]), "+f"((c)[3]) \
        : "r"((a)[0]), "r"((a)[1]), "r"((a)[2]), "r"((a)[3]), \
          "r"((b)[0]), "r"((b)[1]))

__device__ __forceinline__ void cpasync16(uint32_t dst, const void* src) {
    asm volatile("cp.async.cg.shared.global [%0], [%1], 16;" :: "r"(dst), "l"(src));
}
__device__ __forceinline__ void cpa_commit() {
    asm volatile("cp.async.commit_group;" ::: "memory");
}
template<int N>
__device__ __forceinline__ void cpa_wait() {
    asm volatile("cp.async.wait_group %0;" :: "n"(N) : "memory");
}
__device__ __forceinline__ uint32_t s2u(const void* p) {
    return (uint32_t)__cvta_generic_to_shared(p);
}
__device__ __forceinline__ unsigned packh2(float a, float b) {
    __half2 h = __floats2half2_rn(a, b);
    return *(unsigned*)&h;
}

// ---------------- merged prep kernel ----------------------------------------
__global__ void prep_all(const float* __restrict__ w2, const float* __restrict__ rw2,
                         const float* __restrict__ b2, const float* __restrict__ rb2,
                         const float* __restrict__ ow) {
    int blk = blockIdx.x;
    int tid = threadIdx.x;
    if (blk < 30) {
        int i = blk * 256 + tid;
        if (i < STTOT) g_stats[i] = 0.f;
        return;
    }
    if (blk < 798) {
        int idx = (blk - 30) * 256 + tid;
        const int per = Bb * 32 * (TCC/8);
        if (idx >= per) return;
        int col8 = idx % (TCC/8);
        int rr   = (idx / (TCC/8)) % 32;
        int b    = idx / (32 * (TCC/8));
        int row  = rr < 16 ? rr : 512 + rr;
        size_t off = ((size_t)b * LROWS + row) * TCC + col8 * 8;
        uint4 z = make_uint4(0,0,0,0);
        *(uint4*)((char*)g_htH + off*2) = z;
        *(uint4*)((char*)g_t1H + off*2) = z;
        return;
    }
    if (blk < 926) {
        int idx = (blk - 798) * 256 + tid;
        if (idx >= H1C * HHC) return;
        int i = idx >> 8;
        int o = idx & 255;
        unsigned* wB = (unsigned*)g_wB;
        wB[i * 512 + o]       = f2tf32(w2[(size_t)o * H1C + i]);
        wB[i * 512 + 256 + o] = f2tf32(rw2[(size_t)o * H1C + i]);
        if (i == 0) { g_biasP[o] = b2[o]; g_biasP[256 + o] = rb2[o]; }
        return;
    }
    {
        int tile = blk - 926;                 // 0..191 : tk*2 + cb
        int tk = tile >> 1, cb = tile & 1;
        unsigned* dst = (unsigned*)g_owRH + (size_t)tile * 1024 + tid * 4;
#pragma unroll
        for (int u = 0; u < 4; u++) {
            int pos = tid * 4 + u;
            int r = pos & 3, lane = (pos >> 2) & 31, mi = pos >> 7;
            int kl = 2 * (lane & 3) + ((r >> 1) << 3);
            int ml = mi * 16 + (lane >> 2) + ((r & 1) << 3);
            int c = tk * 16 + kl;
            int o = cb * 128 + ml;
            float f0 = ow[(size_t)o * TCC + c];
            float f1 = ow[(size_t)o * TCC + c + 1];
            dst[u] = packh2(f0, f1);
        }
    }
}

// coalesced conv-weight transform -> fragment-permuted fp16 tiles
__global__ void wtrans_convH2(const float* __restrict__ cw, __half* __restrict__ wt) {
    __shared__ float sm[128 * 81];
    int blk = blockIdx.x;                 // cib*12 + cb ; cib in [0,96)
    int cib = blk / 12, cb = blk % 12;
    int ci0 = cib * 16;
    int tid = threadIdx.x;
    for (int i = tid; i < 128 * 80; i += 256) {
        int co = i / 80, j = i % 80;
        sm[co * 81 + j] = cw[((size_t)(cb * 128 + co) * TCC + ci0) * 5 + j];
    }
    __syncthreads();
#pragma unroll
    for (int k = 0; k < 5; k++) {
        int tile = (k * 96 + cib) * 12 + cb;
        unsigned* dst = (unsigned*)wt + (size_t)tile * 1024 + tid * 4;
#pragma unroll
        for (int u = 0; u < 4; u++) {
            int pos = tid * 4 + u;
            int r = pos & 3, lane = (pos >> 2) & 31, mi = pos >> 7;
            int kl = 2 * (lane & 3) + ((r >> 1) << 3);
            int ml = mi * 16 + (lane >> 2) + ((r & 1) << 3);
            float f0 = sm[ml * 81 + kl * 5 + k];
            float f1 = sm[ml * 81 + (kl + 1) * 5 + k];
            dst[u] = packh2(f0, f1);
        }
    }
}

// ======== GCN stage 1: register node-mix + fused BN1 stats ==================
// 1024 blocks x 16 (b,s) slices. Thread = (path, c): path 0 = residual branch
// (rw1/rb1 -> g_res1), path 1 = conv branch (w1/b1 -> node mix -> g_xc1).
// Weight row register-resident; node mix entirely in registers; per-thread
// stats accumulated over all 96 outputs then one atomicAdd per region.
#define G1BS 16
__global__ __launch_bounds__(256) void gcn1_fused(
        const float* __restrict__ x, const float* __restrict__ adj,
        const float* __restrict__ eimp,
        const float* __restrict__ w1, const float* __restrict__ b1,
        const float* __restrict__ rw1, const float* __restrict__ rb1) {
    __shared__ float xs[G1BS * NNODE * CIN];   // 1152 floats
    __shared__ float Asm[NNODE * NNODE];
    const int tid = threadIdx.x;
    const int blk = blockIdx.x;
    const int path = tid >> 7;        // 0: res, 1: xc
    const int c = tid & 127;

    // load x slab (coalesced) + A
    for (int i = tid; i < G1BS * NNODE * CIN; i += 256)
        xs[i] = x[(size_t)blk * (G1BS * NNODE * CIN) + i];
    if (tid < NNODE * NNODE) Asm[tid] = adj[tid] * eimp[tid];

    // register weight row + bias
    float wrow[CIN];
    const float* wsrc = path ? (w1 + c * CIN) : (rw1 + c * CIN);
#pragma unroll
    for (int i = 0; i < CIN; i++) wrow[i] = wsrc[i];
    const float bias = path ? b1[c] : rb1[c];
    __syncthreads();

    float ssum = 0.f, sqq = 0.f;
    for (int j = 0; j < G1BS; j++) {
        const float* xj = xs + j * (NNODE * CIN);
        float v[NNODE];
#pragma unroll
        for (int n = 0; n < NNODE; n++) {
            float acc = bias;
#pragma unroll
            for (int i = 0; i < CIN; i++) acc += wrow[i] * xj[n * CIN + i];
            v[n] = acc;
        }
        const size_t base = ((size_t)(blk * G1BS + j) * NNODE) * H1C + c;
        if (path) {
#pragma unroll
            for (int n = 0; n < NNODE; n++) {
                float m = 0.f;
#pragma unroll
                for (int q = 0; q < NNODE; q++) m += Asm[n * NNODE + q] * v[q];
                g_xc1[base + (size_t)n * H1C] = m;
                ssum += m; sqq += m * m;
            }
        } else {
#pragma unroll
            for (int n = 0; n < NNODE; n++) {
                g_res1[base + (size_t)n * H1C] = v[n];
                ssum += v[n]; sqq += v[n] * v[n];
            }
        }
    }
    float* st = g_stats + ST1 + (path ? 0 : 2 * H1C);
    atomicAdd(&st[c],        ssum);
    atomicAdd(&st[H1C + c],  sqq);
}

__global__ void stats_rows(const float* __restrict__ a, const float* __restrict__ b,
                           int Mrows, int C, float* __restrict__ base) {
    int c = threadIdx.x;
    int rows_per = Mrows / gridDim.x;
    int r0 = blockIdx.x * rows_per;
    int r1 = r0 + rows_per;
    float sa = 0.f, qa = 0.f, sb = 0.f, qb = 0.f;
    for (int r = r0; r < r1; r++) {
        float v = a[(size_t)r*C + c]; sa += v; qa += v*v;
        float u = b[(size_t)r*C + c]; sb += u; qb += u*u;
    }
    atomicAdd(&base[c],       sa);
    atomicAdd(&base[C + c],   qa);
    atomicAdd(&base[2*C + c], sb);
    atomicAdd(&base[3*C + c], qb);
}

__global__ void bn_apply1(const float* __restrict__ g1, const float* __restrict__ beta1,
                          const float* __restrict__ rg1, const float* __restrict__ rbeta1) {
    size_t idx = (size_t)blockIdx.x * blockDim.x + threadIdx.x;
    if (idx >= (size_t)M1R*H1C) return;
    int c = (int)(idx % H1C);
    const float* st = g_stats + ST1;
    const float invM = 1.f / (float)M1R;
    float m1 = st[c] * invM;
    float v1 = st[H1C + c] * invM - m1*m1;
    float m2 = st[2*H1C + c] * invM;
    float v2 = st[3*H1C + c] * invM - m2*m2;
    float a = (g_xc1[idx]  - m1) * rsqrtf(v1 + BNEPS) * g1[c]  + beta1[c];
    float r = (g_res1[idx] - m2) * rsqrtf(v2 + BNEPS) * rg1[c] + rbeta1[c];
    float o = a + r;
    o = o > 0.f ? o : 0.f;
    g_h1[idx] = __uint_as_float(f2tf32(o));
}

// ---------------- gcn2 dual GEMM (tf32 mma, unchanged) ----------------------
#define A2STR 20
#define B2STR 136
#define A2SZ (128*A2STR*4)
#define B2SZ (16*B2STR*4)
#define STG2 (A2SZ + B2SZ)

__global__ __launch_bounds__(256, 2) void gcn2_gemm_tf32() {
    extern __shared__ __align__(128) char dsm[];
    const int tid = threadIdx.x;
    const int bm = blockIdx.x * 128;
    const int by = blockIdx.y;
    const int bn = by * 128;
    const int lane = tid & 31, wid = tid >> 5;
    const int wm = (wid & 1) * 64, wn = (wid >> 1) * 32;
    const int g = lane >> 2, tg = lane & 3;
    const uint32_t smem_u = s2u(dsm);
    const float* A = g_h1;

    float acc[4][4][4];
#pragma unroll
    for (int mi = 0; mi < 4; mi++)
#pragma unroll
        for (int ni = 0; ni < 4; ni++)
#pragma unroll
            for (int r = 0; r < 4; r++) acc[mi][ni][r] = 0.f;

    const int NT = H1C / 16;   // 8

    auto load_stage = [&](int slot, int t) {
        const int kk0 = t * 16;
        const uint32_t sa = smem_u + slot * STG2;
        const uint32_t sb = sa + A2SZ;
#pragma unroll
        for (int i = 0; i < 2; i++) {
            int idx = tid + i * 256;
            int m = idx >> 2, kc = (idx & 3) * 4;
            cpasync16(sa + (m * A2STR + kc) * 4,
                      A + (size_t)(bm + m) * H1C + kk0 + kc);
        }
#pragma unroll
        for (int i = 0; i < 2; i++) {
            int idx = tid + i * 256;
            int row = idx >> 5, ch = idx & 31;
            cpasync16(sb + (row * B2STR + ch * 4) * 4,
                      g_wB + (size_t)(kk0 + row) * 512 + bn + ch * 4);
        }
    };
    load_stage(0, 0); cpa_commit();
    load_stage(1, 1); cpa_commit();

    for (int t = 0; t < NT; ++t) {
        cpa_wait<1>();
        __syncthreads();
        if (t + 2 < NT) load_stage((t + 2) % 3, t + 2);
        cpa_commit();
        const int cur = t % 3;
        const float* As = (const float*)(dsm + cur * STG2);
        const float* Bs = (const float*)(dsm + cur * STG2 + A2SZ);
#pragma unroll
        for (int ks = 0; ks < 16; ks += 8) {
            unsigned a[4][4], b[4][2];
#pragma unroll
            for (int mi = 0; mi < 4; mi++) {
                int m = wm + mi * 16 + g;
                a[mi][0] = __float_as_uint(As[(m    ) * A2STR + ks + tg]);
                a[mi][1] = __float_as_uint(As[(m + 8) * A2STR + ks + tg]);
                a[mi][2] = __float_as_uint(As[(m    ) * A2STR + ks + tg + 4]);
                a[mi][3] = __float_as_uint(As[(m + 8) * A2STR + ks + tg + 4]);
            }
#pragma unroll
            for (int ni = 0; ni < 4; ni++) {
                int c = wn + ni * 8 + g;
                b[ni][0] = __float_as_uint(Bs[(ks + tg    ) * B2STR + c]);
                b[ni][1] = __float_as_uint(Bs[(ks + tg + 4) * B2STR + c]);
            }
#pragma unroll
            for (int mi = 0; mi < 4; mi++)
#pragma unroll
                for (int ni = 0; ni < 4; ni++)
                    MMA_TF32(acc[mi][ni], a[mi], b[ni]);
        }
    }

    float* tgt = (by < 2) ? g_y2 : g_res2;
    const int nb = (by & 1) * 128;
#pragma unroll
    for (int mi = 0; mi < 4; mi++) {
        int m0 = bm + wm + mi * 16 + g;
#pragma unroll
        for (int ni = 0; ni < 4; ni++) {
            int n = nb + wn + ni * 8 + 2 * tg;
            int pb = bn + wn + ni * 8 + 2 * tg;
            float b0 = g_biasP[pb], b1 = g_biasP[pb + 1];
            *(float2*)(tgt + (size_t)m0 * HHC + n)
                = make_float2(acc[mi][ni][0] + b0, acc[mi][ni][1] + b1);
            *(float2*)(tgt + (size_t)(m0 + 8) * HHC + n)
                = make_float2(acc[mi][ni][2] + b0, acc[mi][ni][3] + b1);
        }
    }
}

// ---------------- node mix for stage 2 --------------------------------------
__global__ void nodemix2(const float* __restrict__ adj, const float* __restrict__ eimp) {
    __shared__ float ys[NNODE*HHC];
    __shared__ float Asm[NNODE*NNODE];
    int bs = blockIdx.x, tid = threadIdx.x;
    if (tid < NNODE*NNODE) Asm[tid] = adj[tid] * eimp[tid];
    for (int e = tid; e < NNODE*HHC; e += blockDim.x)
        ys[e] = g_y2[(size_t)bs*NNODE*HHC + e];
    __syncthreads();
    for (int e = tid; e < NNODE*HHC; e += blockDim.x) {
        int n = e / HHC, c = e % HHC;
        float acc = 0.f;
#pragma unroll
        for (int m = 0; m < NNODE; m++) acc += Asm[n*NNODE + m] * ys[m*HHC + c];
        g_xc2[(size_t)bs*NNODE*HHC + e] = acc;
    }
}

// ---------------- BN apply stage 2 -> [l][c] fp16 ----------------------------
__global__ void bn_apply2_tohalf(const float* __restrict__ g2, const float* __restrict__ beta2,
                                 const float* __restrict__ rg2, const float* __restrict__ rbeta2) {
    int row = blockIdx.x;        // (b*Ss + s)*6 + n
    int c = threadIdx.x;         // 0..255
    const float* st = g_stats + ST2;
    const float invM = 1.f / (float)M1R;
    float m1 = st[c] * invM;
    float v1 = st[HHC + c] * invM - m1*m1;
    float m2 = st[2*HHC + c] * invM;
    float v2 = st[3*HHC + c] * invM - m2*m2;
    float sc1 = rsqrtf(v1 + BNEPS) * g2[c];
    float sh1 = beta2[c] - m1*sc1;
    float sc2 = rsqrtf(v2 + BNEPS) * rg2[c];
    float sh2 = rbeta2[c] - m2*sc2;
    size_t ridx = (size_t)row * HHC + c;
    float o = g_xc2[ridx]*sc1 + sh1 + g_res2[ridx]*sc2 + sh2;
    o = o > 0.f ? o : 0.f;
    int n = row % NNODE;
    int bs = row / NNODE;
    int b = bs / Ss, s = bs % Ss;
    g_htH[((size_t)b * LROWS + 16 + s) * TCC + n * HHC + c] = __float2half(o);
}

// ======================= conv1d fp16 mma GEMM, ci-tiled, 4-stage =============
#define A5SZ 20480          /* 5 x 4096 weight tap tiles */
#define BROWB2 48           /* B smem row stride bytes */
#define STG3 26880          /* A5SZ + 132*48 = 26816, padded to 128 */
#define CST3 4

__global__ __launch_bounds__(256, 2) void conv_gemm_f16(
        const __half* __restrict__ X, const __half* __restrict__ Wt,
        __half* __restrict__ Y, float* __restrict__ statsB) {
    extern __shared__ __align__(128) char dsm[];
    const int tid = threadIdx.x;
    const int cb = blockIdx.x;
    const int bm = cb * 128;           // co
    const int bn = blockIdx.y * 128;   // l
    const __half* Xb = X + (size_t)blockIdx.z * LROWS * TCC;
    __half* Yb = Y + (size_t)blockIdx.z * LROWS * TCC;
    const int lane = tid & 31, wid = tid >> 5;
    const int wm = (wid & 1) * 64, wn = (wid >> 1) * 32;
    const int g = lane >> 2, tg = lane & 3;
    const int aoff = (wid & 1) * 4;
    const uint32_t smem_u = s2u(dsm);

    float acc[4][4][4];
#pragma unroll
    for (int mi = 0; mi < 4; mi++)
#pragma unroll
        for (int ni = 0; ni < 4; ni++)
#pragma unroll
            for (int r = 0; r < 4; r++) acc[mi][ni][r] = 0.f;

    const int NTC = TCC / 16;   // 96 ci-tiles

    auto load_stage = [&](int slot, int it) {
        const int ci0 = it * 16;
        const uint32_t sa = smem_u + slot * STG3;
        const uint32_t sb = sa + A5SZ;
#pragma unroll
        for (int k = 0; k < 5; k++)
            cpasync16(sa + k * 4096 + tid * 16,
                      Wt + ((size_t)(k * 96 + it) * 12 + cb) * 2048 + tid * 8);
        for (int i = tid; i < 264; i += 256) {
            int r = i >> 1, h = i & 1;
            cpasync16(sb + r * BROWB2 + h * 16,
                      Xb + (size_t)(14 + bn + r) * TCC + ci0 + h * 8);
        }
    };

    load_stage(0, 0); cpa_commit();
    load_stage(1, 1); cpa_commit();
    load_stage(2, 2); cpa_commit();

    for (int t = 0; t < NTC; ++t) {
        cpa_wait<2>();
        __syncthreads();
        if (t + 3 < NTC) load_stage((t + 3) % CST3, t + 3);
        cpa_commit();

        const char* base = dsm + (t % CST3) * STG3;
        const char* Bs = base + A5SZ;
#pragma unroll
        for (int k = 0; k < 5; k++) {
            const uint4* Af = (const uint4*)(base + k * 4096);
            unsigned a[4][4], b[4][2];
#pragma unroll
            for (int mi = 0; mi < 4; mi++) {
                uint4 v = Af[(aoff + mi) * 32 + lane];
                a[mi][0] = v.x; a[mi][1] = v.y; a[mi][2] = v.z; a[mi][3] = v.w;
            }
#pragma unroll
            for (int ni = 0; ni < 4; ni++) {
                int row = wn + ni * 8 + g + k;
                b[ni][0] = *(const unsigned*)(Bs + row * BROWB2 + tg * 4);
                b[ni][1] = *(const unsigned*)(Bs + row * BROWB2 + 16 + tg * 4);
            }
#pragma unroll
            for (int mi = 0; mi < 4; mi++)
#pragma unroll
                for (int ni = 0; ni < 4; ni++)
                    MMA_F16(acc[mi][ni], a[mi], b[ni]);
        }
    }

    // epilogue: store fp16 [l][c] + fused per-channel stats from fp32 accs
#pragma unroll
    for (int mi = 0; mi < 4; mi++) {
        int m0 = bm + wm + mi * 16 + g;
        float s0 = 0.f, q0 = 0.f, s1 = 0.f, q1 = 0.f;
#pragma unroll
        for (int ni = 0; ni < 4; ni++) {
            float v0 = acc[mi][ni][0], v1 = acc[mi][ni][1];
            float v2 = acc[mi][ni][2], v3 = acc[mi][ni][3];
            s0 += v0 + v1; q0 += v0*v0 + v1*v1;
            s1 += v2 + v3; q1 += v2*v2 + v3*v3;
            int l0 = bn + wn + ni * 8 + 2 * tg;
            size_t r0 = ((size_t)(16 + l0)) * TCC;
            size_t r1 = ((size_t)(17 + l0)) * TCC;
            Yb[r0 + m0]     = __float2half(v0);
            Yb[r1 + m0]     = __float2half(v1);
            Yb[r0 + m0 + 8] = __float2half(v2);
            Yb[r1 + m0 + 8] = __float2half(v3);
        }
        s0 += __shfl_xor_sync(0xffffffffu, s0, 1);
        s0 += __shfl_xor_sync(0xffffffffu, s0, 2);
        q0 += __shfl_xor_sync(0xffffffffu, q0, 1);
        q0 += __shfl_xor_sync(0xffffffffu, q0, 2);
        s1 += __shfl_xor_sync(0xffffffffu, s1, 1);
        s1 += __shfl_xor_sync(0xffffffffu, s1, 2);
        q1 += __shfl_xor_sync(0xffffffffu, q1, 1);
        q1 += __shfl_xor_sync(0xffffffffu, q1, 2);
        if (tg == 0) {
            atomicAdd(&statsB[m0],         s0);
            atomicAdd(&statsB[TCC + m0],   q0);
            atomicAdd(&statsB[m0 + 8],     s1);
            atomicAdd(&statsB[TCC + m0+8], q1);
        }
    }
}

// ---------------- conv BN apply in-place on fp16 [l][c] ----------------------
__global__ void conv_bnH(__half* __restrict__ T, const float* __restrict__ g,
                         const float* __restrict__ beta, const __half* __restrict__ resid,
                         const float* __restrict__ statsB) {
    size_t idx = (size_t)blockIdx.x * blockDim.x + threadIdx.x;
    const size_t total = (size_t)Bb * LLEN * (TCC/2);
    if (idx >= total) return;
    int c2  = (int)(idx % (TCC/2));
    int l   = (int)((idx / (TCC/2)) % LLEN);
    int b   = (int)(idx / ((size_t)(TCC/2) * LLEN));
    int c   = c2 * 2;
    size_t a = ((size_t)b * LROWS + 16 + l) * TCC + c;
    const float invM = 1.f / (float)(Bb * LLEN);
    float m0 = statsB[c] * invM;
    float va = statsB[TCC + c] * invM - m0*m0;
    float m1 = statsB[c+1] * invM;
    float vb = statsB[TCC + c+1] * invM - m1*m1;
    __half2 hv = *(__half2*)(T + a);
    float2 f = __half22float2(hv);
    float o0 = (f.x - m0) * rsqrtf(va + BNEPS) * g[c]   + beta[c];
    float o1 = (f.y - m1) * rsqrtf(vb + BNEPS) * g[c+1] + beta[c+1];
    o0 = o0 > 0.f ? o0 : 0.f;
    o1 = o1 > 0.f ? o1 : 0.f;
    if (resid) {
        float2 r = __half22float2(*(const __half2*)(resid + a));
        o0 += r.x; o1 += r.y;
    }
    *(__half2*)(T + a) = __floats2half2_rn(o0, o1);
}

// ======================= output GEMM (fp16 mma, permuted A) =================
#define ASZh 4096
#define BROWB 48
#define BSZh (128*BROWB)
#define STGOh (ASZh + BSZh)

__global__ __launch_bounds__(256, 2) void out_gemm_f16(
        const __half* __restrict__ T2, const float* __restrict__ OB,
        float* __restrict__ OUT) {
    extern __shared__ __align__(128) char dsm[];
    const int tid = threadIdx.x;
    const int cb = blockIdx.x;
    const int bm = cb * 128;           // o
    const int bn = blockIdx.y * 128;   // s
    const int b  = blockIdx.z;
    const __half* T2b = T2 + (size_t)b * LROWS * TCC;
    const int lane = tid & 31, wid = tid >> 5;
    const int wm = (wid & 1) * 64, wn = (wid >> 1) * 32;
    const int g = lane >> 2, tg = lane & 3;
    const int aoff = (wid & 1) * 4;
    const uint32_t smem_u = s2u(dsm);

    float acc[4][4][4];
#pragma unroll
    for (int mi = 0; mi < 4; mi++)
#pragma unroll
        for (int ni = 0; ni < 4; ni++)
#pragma unroll
            for (int r = 0; r < 4; r++) acc[mi][ni][r] = 0.f;

    const int NT = TCC / 16;   // 96
    const int brow = tid >> 1, bhalf = tid & 1;

    auto load_stage = [&](int slot, int t) {
        const uint32_t sa = smem_u + slot * STGOh;
        const uint32_t sb = sa + ASZh;
        cpasync16(sa + tid * 16, g_owRH + ((size_t)t * 2 + cb) * 2048 + tid * 8);
        const __half* src = T2b + (size_t)(16 + bn + brow) * TCC + t * 16 + bhalf * 8;
        cpasync16(sb + brow * BROWB + bhalf * 16, src);
    };
    load_stage(0, 0); cpa_commit();
    load_stage(1, 1); cpa_commit();

    for (int t = 0; t < NT; ++t) {
        cpa_wait<1>();
        __syncthreads();
        if (t + 2 < NT) load_stage((t + 2) % 3, t + 2);
        cpa_commit();
        const int cur = t % 3;
        const uint4* Af = (const uint4*)(dsm + cur * STGOh);
        const char* Bs = dsm + cur * STGOh + ASZh;

        unsigned a[4][4], b[4][2];
#pragma unroll
        for (int mi = 0; mi < 4; mi++) {
            uint4 v = Af[(aoff + mi) * 32 + lane];
            a[mi][0] = v.x; a[mi][1] = v.y; a[mi][2] = v.z; a[mi][3] = v.w;
        }
#pragma unroll
        for (int ni = 0; ni < 4; ni++) {
            int row = wn + ni * 8 + g;
            b[ni][0] = *(const unsigned*)(Bs + row * BROWB + tg * 4);
            b[ni][1] = *(const unsigned*)(Bs + row * BROWB + 16 + tg * 4);
        }
#pragma unroll
        for (int mi = 0; mi < 4; mi++)
#pragma unroll
            for (int ni = 0; ni < 4; ni++)
                MMA_F16(acc[mi][ni], a[mi], b[ni]);
    }

#pragma unroll
    for (int mi = 0; mi < 4; mi++) {
        int o0 = bm + wm + mi * 16 + g;
        float bo0 = OB[o0], bo1 = OB[o0 + 8];
#pragma unroll
        for (int ni = 0; ni < 4; ni++) {
            int sL = bn + wn + ni * 8 + 2 * tg;
            float v0 = acc[mi][ni][0] + bo0; v0 = v0 > 0.f ? v0 : 0.f;
            float v1 = acc[mi][ni][1] + bo0; v1 = v1 > 0.f ? v1 : 0.f;
            float v2 = acc[mi][ni][2] + bo1; v2 = v2 > 0.f ? v2 : 0.f;
            float v3 = acc[mi][ni][3] + bo1; v3 = v3 > 0.f ? v3 : 0.f;
            OUT[((size_t)b * Ss + sL    ) * HHC + o0    ] = v0;
            OUT[((size_t)b * Ss + sL + 1) * HHC + o0    ] = v1;
            OUT[((size_t)b * Ss + sL    ) * HHC + o0 + 8] = v2;
            OUT[((size_t)b * Ss + sL + 1) * HHC + o0 + 8] = v3;
        }
    }
}

// ---------------- launch ----------------------------------------------------
extern "C" void kernel_launch(void* const* d_in, const int* in_sizes, int n_in,
                              void* d_out, int out_size) {
    const float* x     = (const float*)d_in[0];
    const float* adj   = (const float*)d_in[1];
    const float* eimp  = (const float*)d_in[2];
    const float* w1    = (const float*)d_in[3];
    const float* b1    = (const float*)d_in[4];
    const float* rw1   = (const float*)d_in[5];
    const float* rb1   = (const float*)d_in[6];
    const float* rg1   = (const float*)d_in[7];
    const float* rbeta1= (const float*)d_in[8];
    const float* g1    = (const float*)d_in[9];
    const float* beta1 = (const float*)d_in[10];
    const float* w2    = (const float*)d_in[11];
    const float* b2    = (const float*)d_in[12];
    const float* rw2   = (const float*)d_in[13];
    const float* rb2   = (const float*)d_in[14];
    const float* rg2   = (const float*)d_in[15];
    const float* rbeta2= (const float*)d_in[16];
    const float* g2    = (const float*)d_in[17];
    const float* beta2 = (const float*)d_in[18];
    const float* cw1   = (const float*)d_in[19];
    /* cb1 = d_in[20]: cancels exactly through BN mean-subtraction */
    const float* cg1   = (const float*)d_in[21];
    const float* cbeta1= (const float*)d_in[22];
    const float* cw2   = (const float*)d_in[23];
    /* cb2 = d_in[24]: cancels exactly */
    const float* cg2   = (const float*)d_in[25];
    const float* cbeta2= (const float*)d_in[26];
    const float* ow    = (const float*)d_in[27];
    const float* ob    = (const float*)d_in[28];
    float* out = (float*)d_out;

    float *p_xc1, *p_res1, *p_xc2, *p_res2, *p_stats;
    __half *p_htH, *p_t1H, *p_t2H, *p_wt1H, *p_wt2H;
    cudaGetSymbolAddress((void**)&p_xc1,  g_xc1);
    cudaGetSymbolAddress((void**)&p_res1, g_res1);
    cudaGetSymbolAddress((void**)&p_xc2,  g_xc2);
    cudaGetSymbolAddress((void**)&p_res2, g_res2);
    cudaGetSymbolAddress((void**)&p_stats, g_stats);
    cudaGetSymbolAddress((void**)&p_htH,  g_htH);
    cudaGetSymbolAddress((void**)&p_t1H,  g_t1H);
    cudaGetSymbolAddress((void**)&p_t2H,  g_t2H);
    cudaGetSymbolAddress((void**)&p_wt1H, g_wt1H);
    cudaGetSymbolAddress((void**)&p_wt2H, g_wt2H);

    cudaFuncSetAttribute(conv_gemm_f16,
                         cudaFuncAttributeMaxDynamicSharedMemorySize, CST3 * STG3);
    cudaFuncSetAttribute(gcn2_gemm_tf32,
                         cudaFuncAttributeMaxDynamicSharedMemorySize, 3 * STG2);
    cudaFuncSetAttribute(out_gemm_f16,
                         cudaFuncAttributeMaxDynamicSharedMemorySize, 3 * STGOh);

    // -------- prep: merged zero/pack + weight transforms --------------------
    prep_all<<<1118, 256>>>(w2, rw2, b2, rb2, ow);
    wtrans_convH2<<<96*12, 256>>>(cw1, p_wt1H);
    wtrans_convH2<<<96*12, 256>>>(cw2, p_wt2H);

    // -------- GCN stage 1 (fused linear + register node-mix + stats) --------
    gcn1_fused<<<NBS/G1BS, 256>>>(x, adj, eimp, w1, b1, rw1, rb1);
    bn_apply1<<<(M1R*H1C)/256, 256>>>(g1, beta1, rg1, rbeta1);

    // -------- GCN stage 2 (tf32 dual GEMM) --------
    gcn2_gemm_tf32<<<dim3(M1R/128, 4), 256, 3*STG2>>>();
    nodemix2<<<NBS, 256>>>(adj, eimp);
    stats_rows<<<1024, HHC>>>(p_xc2, p_res2, M1R, HHC, p_stats + ST2);
    bn_apply2_tohalf<<<M1R, 256>>>(g2, beta2, rg2, rbeta2);

    // -------- TCN conv 1 (fp16 mma, ci-tiled, 4-stage) --------
    conv_gemm_f16<<<dim3(TCC/128, LLEN/128, Bb), 256, CST3*STG3>>>(
        p_htH, p_wt1H, p_t1H, p_stats + STC1);
    conv_bnH<<<(Bb*LLEN*(TCC/2) + 255)/256, 256>>>(
        p_t1H, cg1, cbeta1, (const __half*)nullptr, p_stats + STC1);

    // -------- TCN conv 2 + residual --------
    conv_gemm_f16<<<dim3(TCC/128, LLEN/128, Bb), 256, CST3*STG3>>>(
        p_t1H, p_wt2H, p_t2H, p_stats + STC2);
    conv_bnH<<<(Bb*LLEN*(TCC/2) + 255)/256, 256>>>(
        p_t2H, cg2, cbeta2, p_htH, p_stats + STC2);

    // -------- output layer (fp16 mma) --------
    out_gemm_f16<<<dim3(HHC/128, LLEN/128, Bb), 256, 3*STGOh>>>(p_t2H, ob, out);

    (void)in_sizes; (void)n_in; (void)out_size;
}